// round 1
// baseline (speedup 1.0000x reference)
#include <cuda_runtime.h>
#include <cstdint>
#include <cstddef>

// Problem constants
#define BB 2
#define NN 1024
#define DD 1024
#define HH 4
#define KDIM 512      // KD
#define VDIM 1024     // VD
#define DK 128
#define DV 256
#define MROWS (BB*NN) // 2048

// Scratch layout (floats)
// q:      [2048,512]   off 0
// k:      [2048,512]   off 1048576
// v:      [2048,1024]  off 2097152
// gaux:   [2048,1024]  off 4194304
// eg:     [2048,512]   off 6291456
// t16:    [2048,16]    off 7340032
// o:      [2048,1024]  off 7372800
// y:      [2048,1024]  off 9469952
#define OFF_Q   0
#define OFF_K   1048576
#define OFF_V   2097152
#define OFF_GA  4194304
#define OFF_EG  6291456
#define OFF_T16 7340032
#define OFF_O   7372800
#define OFF_Y   9469952
#define SCRATCH_TOTAL 11567104

__device__ float g_scratch[SCRATCH_TOTAL];

// ---------------------------------------------------------------------------
// Classic 128x128x8 SIMT sgemm, 8x8 register tiles, 256 threads.
// Requires M%128==0, N%128==0, K%8==0. C = A[MxK] @ B[KxN], all row-major.
// ---------------------------------------------------------------------------
__global__ __launch_bounds__(256) void sgemm128(
    int M, int N, int K,
    const float* __restrict__ A, const float* __restrict__ B, float* __restrict__ C)
{
    constexpr int BM = 128, BN = 128, BK = 8, TM = 8, TN = 8;
    __shared__ float As[BK][BM];
    __shared__ float Bs[BK][BN];

    const int tid  = threadIdx.x;
    const int trow = tid >> 4;       // 0..15
    const int tcol = tid & 15;       // 0..15

    const float* Ab = A + (size_t)blockIdx.y * BM * K;
    const float* Bb = B + (size_t)blockIdx.x * BN;
    float*       Cb = C + (size_t)blockIdx.y * BM * N + (size_t)blockIdx.x * BN;

    const int aRow = tid >> 1;          // 0..127
    const int aCol = (tid & 1) * 4;     // 0 or 4
    const int bRow = tid >> 5;          // 0..7
    const int bCol = (tid & 31) * 4;    // 0..124

    float acc[TM][TN];
#pragma unroll
    for (int i = 0; i < TM; i++)
#pragma unroll
        for (int j = 0; j < TN; j++) acc[i][j] = 0.f;

    for (int k0 = 0; k0 < K; k0 += BK) {
        float4 a4 = *reinterpret_cast<const float4*>(Ab + (size_t)aRow * K + aCol);
        As[aCol + 0][aRow] = a4.x;
        As[aCol + 1][aRow] = a4.y;
        As[aCol + 2][aRow] = a4.z;
        As[aCol + 3][aRow] = a4.w;
        *reinterpret_cast<float4*>(&Bs[bRow][bCol]) =
            *reinterpret_cast<const float4*>(Bb + (size_t)bRow * N + bCol);
        __syncthreads();

        Ab += BK;
        Bb += (size_t)BK * N;

#pragma unroll
        for (int kk = 0; kk < BK; kk++) {
            float ar[TM], br[TN];
            *reinterpret_cast<float4*>(ar)     = *reinterpret_cast<const float4*>(&As[kk][trow * TM]);
            *reinterpret_cast<float4*>(ar + 4) = *reinterpret_cast<const float4*>(&As[kk][trow * TM + 4]);
            *reinterpret_cast<float4*>(br)     = *reinterpret_cast<const float4*>(&Bs[kk][tcol * TN]);
            *reinterpret_cast<float4*>(br + 4) = *reinterpret_cast<const float4*>(&Bs[kk][tcol * TN + 4]);
#pragma unroll
            for (int i = 0; i < TM; i++)
#pragma unroll
                for (int j = 0; j < TN; j++)
                    acc[i][j] = fmaf(ar[i], br[j], acc[i][j]);
        }
        __syncthreads();
    }

#pragma unroll
    for (int i = 0; i < TM; i++) {
        float* crow = Cb + (size_t)(trow * TM + i) * N + tcol * TN;
        *reinterpret_cast<float4*>(crow)     = make_float4(acc[i][0], acc[i][1], acc[i][2], acc[i][3]);
        *reinterpret_cast<float4*>(crow + 4) = make_float4(acc[i][4], acc[i][5], acc[i][6], acc[i][7]);
    }
}

// ---------------------------------------------------------------------------
// Low-rank projection t16 = x @ Wgk1, [2048,1024]@[1024,16]. One block per row.
// ---------------------------------------------------------------------------
__global__ __launch_bounds__(128) void proj_lr_kernel(
    const float* __restrict__ x, const float* __restrict__ Wgk1, float* __restrict__ t16)
{
    __shared__ float sx[1024];
    __shared__ float part[8][16];
    const int row = blockIdx.x;
    const int tid = threadIdx.x;
    for (int i = tid; i < 1024; i += 128) sx[i] = x[(size_t)row * 1024 + i];
    __syncthreads();
    const int col = tid & 15;
    const int seg = tid >> 4;  // 0..7, 128 k each
    float p = 0.f;
#pragma unroll 8
    for (int j = 0; j < 128; j++) {
        int kidx = seg * 128 + j;
        p = fmaf(sx[kidx], Wgk1[(size_t)kidx * 16 + col], p);
    }
    part[seg][col] = p;
    __syncthreads();
    if (tid < 16) {
        float s = 0.f;
#pragma unroll
        for (int s8 = 0; s8 < 8; s8++) s += part[s8][tid];
        t16[(size_t)row * 16 + tid] = s;
    }
}

// ---------------------------------------------------------------------------
// Gate: z = t16 @ Wgk2 + bgk2; g = max(log_sigmoid(z)/16, -3); eg = exp(g).
// One block per row, 256 threads -> 2 cols each.
// ---------------------------------------------------------------------------
__global__ __launch_bounds__(256) void gate_eg_kernel(
    const float* __restrict__ t16, const float* __restrict__ Wgk2,
    const float* __restrict__ bgk2, float* __restrict__ eg)
{
    const int row = blockIdx.x;
    const int tid = threadIdx.x;
    __shared__ float st[16];
    if (tid < 16) st[tid] = t16[(size_t)row * 16 + tid];
    __syncthreads();
    for (int c = tid; c < KDIM; c += 256) {
        float z = bgk2[c];
#pragma unroll
        for (int r = 0; r < 16; r++)
            z = fmaf(st[r], Wgk2[(size_t)r * KDIM + c], z);
        // stable log-sigmoid
        float ls = (z >= 0.f) ? -log1pf(expf(-z)) : (z - log1pf(expf(z)));
        float g = fmaxf(ls * (1.f / 16.f), -3.f);
        eg[(size_t)row * KDIM + c] = expf(g);
    }
}

// ---------------------------------------------------------------------------
// GLA scan. Grid: 64 CTAs = (b,h) x 8 v-splits of 32 columns. 128 threads.
// Thread (kg = tid&15, vg = tid>>4) owns S[k = kg+16*j][v = vg*4+i], j<8, i<4.
// Sequential over t: S = S*exp(g_t) + k_t v_t^T ; o_t = q_t^T S.
// q/k/eg/v staged via smem with 1-step register prefetch.
// ---------------------------------------------------------------------------
__global__ __launch_bounds__(128) void gla_scan_kernel(
    const float* __restrict__ q, const float* __restrict__ k,
    const float* __restrict__ v, const float* __restrict__ eg,
    float* __restrict__ o)
{
    const int cta = blockIdx.x;
    const int vs = cta & 7;
    const int bh = cta >> 3;
    const int h = bh & 3;
    const int b = bh >> 2;

    const int tid = threadIdx.x;
    const int kg = tid & 15;
    const int vg = tid >> 4;

    __shared__ float sq[128], sk[128], se[128], sv[32];

    float S[8][4];
#pragma unroll
    for (int j = 0; j < 8; j++)
#pragma unroll
        for (int i = 0; i < 4; i++) S[j][i] = 0.f;

    const size_t qoff = ((size_t)b * NN) * KDIM + (size_t)h * DK;
    const float* qb = q + qoff;
    const float* kb = k + qoff;
    const float* ebp = eg + qoff;
    const size_t voff = ((size_t)b * NN) * VDIM + (size_t)h * DV + (size_t)vs * 32;
    const float* vb = v + voff;
    float* ob = o + voff;

    // prefetch step 0
    float rq = qb[tid];
    float rk = kb[tid];
    float re = ebp[tid];
    float rv = (tid < 32) ? vb[tid] : 0.f;

    for (int t = 0; t < NN; t++) {
        sq[tid] = rq;
        sk[tid] = rk;
        se[tid] = re;
        if (tid < 32) sv[tid] = rv;
        __syncthreads();

        if (t + 1 < NN) {
            const size_t r = (size_t)(t + 1) * KDIM;
            rq = qb[r + tid];
            rk = kb[r + tid];
            re = ebp[r + tid];
            if (tid < 32) rv = vb[(size_t)(t + 1) * VDIM + tid];
        }

        const float v0 = sv[vg * 4 + 0];
        const float v1 = sv[vg * 4 + 1];
        const float v2 = sv[vg * 4 + 2];
        const float v3 = sv[vg * 4 + 3];

        float a0 = 0.f, a1 = 0.f, a2 = 0.f, a3 = 0.f;
#pragma unroll
        for (int j = 0; j < 8; j++) {
            const int kk = kg + 16 * j;
            const float e = se[kk];
            const float kv = sk[kk];
            const float qv = sq[kk];
            S[j][0] = fmaf(kv, v0, S[j][0] * e); a0 = fmaf(qv, S[j][0], a0);
            S[j][1] = fmaf(kv, v1, S[j][1] * e); a1 = fmaf(qv, S[j][1], a1);
            S[j][2] = fmaf(kv, v2, S[j][2] * e); a2 = fmaf(qv, S[j][2], a2);
            S[j][3] = fmaf(kv, v3, S[j][3] * e); a3 = fmaf(qv, S[j][3], a3);
        }

        // reduce over the 16 kg lanes (within warp)
#pragma unroll
        for (int off = 1; off < 16; off <<= 1) {
            a0 += __shfl_xor_sync(0xffffffffu, a0, off);
            a1 += __shfl_xor_sync(0xffffffffu, a1, off);
            a2 += __shfl_xor_sync(0xffffffffu, a2, off);
            a3 += __shfl_xor_sync(0xffffffffu, a3, off);
        }
        if (kg == 0) {
            *reinterpret_cast<float4*>(ob + (size_t)t * VDIM + vg * 4) =
                make_float4(a0, a1, a2, a3);
        }
        __syncthreads();
    }
}

// ---------------------------------------------------------------------------
// RMSNorm (per head, DV=256) + rms_w + SiLU(gaux) gating. One block per row.
// Thread tid handles 4 consecutive cols; head = tid/64 (64 threads = 2 warps).
// ---------------------------------------------------------------------------
__global__ __launch_bounds__(256) void norm_gate_kernel(
    const float* __restrict__ o, const float* __restrict__ gaux,
    const float* __restrict__ rms_w, float* __restrict__ y)
{
    const int row = blockIdx.x;
    const int tid = threadIdx.x;
    const size_t base = (size_t)row * VDIM + tid * 4;

    const float4 ov = *reinterpret_cast<const float4*>(o + base);
    float ss = ov.x * ov.x + ov.y * ov.y + ov.z * ov.z + ov.w * ov.w;
#pragma unroll
    for (int off = 16; off; off >>= 1)
        ss += __shfl_xor_sync(0xffffffffu, ss, off);

    __shared__ float ws[8];
    const int warp = tid >> 5, lane = tid & 31;
    if (lane == 0) ws[warp] = ss;
    __syncthreads();

    const int hw = (tid >> 6) << 1;  // first warp index of this head
    const float tot = ws[hw] + ws[hw + 1];
    const float scale = rsqrtf(tot * (1.f / 256.f) + 1e-5f);

    const float4 gv = *reinterpret_cast<const float4*>(gaux + base);
    const int dv = (tid * 4) & 255;
    const float w0 = rms_w[dv + 0], w1 = rms_w[dv + 1], w2 = rms_w[dv + 2], w3 = rms_w[dv + 3];

    float4 r;
    r.x = ov.x * scale * w0 * (gv.x / (1.f + expf(-gv.x)));
    r.y = ov.y * scale * w1 * (gv.y / (1.f + expf(-gv.y)));
    r.z = ov.z * scale * w2 * (gv.z / (1.f + expf(-gv.z)));
    r.w = ov.w * scale * w3 * (gv.w / (1.f + expf(-gv.w)));
    *reinterpret_cast<float4*>(y + base) = r;
}

// ---------------------------------------------------------------------------
extern "C" void kernel_launch(void* const* d_in, const int* in_sizes, int n_in,
                              void* d_out, int out_size)
{
    const float* x    = (const float*)d_in[0];
    const float* Wq   = (const float*)d_in[1];
    const float* Wk   = (const float*)d_in[2];
    const float* Wv   = (const float*)d_in[3];
    const float* Wg   = (const float*)d_in[4];
    const float* Wgk1 = (const float*)d_in[5];
    const float* Wgk2 = (const float*)d_in[6];
    const float* bgk2 = (const float*)d_in[7];
    const float* Wout = (const float*)d_in[8];
    const float* rmsw = (const float*)d_in[9];
    float* out = (float*)d_out;

    float* scratch = nullptr;
    cudaGetSymbolAddress((void**)&scratch, g_scratch);
    float* q   = scratch + OFF_Q;
    float* k   = scratch + OFF_K;
    float* v   = scratch + OFF_V;
    float* ga  = scratch + OFF_GA;
    float* eg  = scratch + OFF_EG;
    float* t16 = scratch + OFF_T16;
    float* o   = scratch + OFF_O;
    float* y   = scratch + OFF_Y;

    // projections
    sgemm128<<<dim3(KDIM / 128, MROWS / 128), 256>>>(MROWS, KDIM, DD, x, Wq, q);
    sgemm128<<<dim3(KDIM / 128, MROWS / 128), 256>>>(MROWS, KDIM, DD, x, Wk, k);
    sgemm128<<<dim3(VDIM / 128, MROWS / 128), 256>>>(MROWS, VDIM, DD, x, Wv, v);
    sgemm128<<<dim3(VDIM / 128, MROWS / 128), 256>>>(MROWS, VDIM, DD, x, Wg, ga);

    // gates
    proj_lr_kernel<<<MROWS, 128>>>(x, Wgk1, t16);
    gate_eg_kernel<<<MROWS, 256>>>(t16, Wgk2, bgk2, eg);

    // recurrent scan
    gla_scan_kernel<<<BB * HH * 8, 128>>>(q, k, v, eg, o);

    // rmsnorm + silu gate
    norm_gate_kernel<<<MROWS, 256>>>(o, ga, rmsw, y);

    // output projection
    sgemm128<<<dim3(DD / 128, MROWS / 128), 256>>>(MROWS, DD, VDIM, y, Wout, out);
}

// round 2
// speedup vs baseline: 1.5212x; 1.5212x over previous
#include <cuda_runtime.h>
#include <cstdint>
#include <cstddef>

// Problem constants
#define BB 2
#define NN 1024
#define DD 1024
#define HH 4
#define KDIM 512      // KD
#define VDIM 1024     // VD
#define DK 128
#define DV 256
#define MROWS (BB*NN) // 2048

// Scratch layout (floats)
#define OFF_Q   0
#define OFF_K   1048576
#define OFF_V   2097152
#define OFF_GA  4194304
#define OFF_EG  6291456
#define OFF_T16 7340032
#define OFF_O   7372800
#define OFF_Y   9469952
#define SCRATCH_TOTAL 11567104

__device__ float g_scratch[SCRATCH_TOTAL];

// ---------------------------------------------------------------------------
// Double-buffered SIMT GEMM body. C = A[MxK] @ B[KxN] row-major.
// THREADS = (BM/TM)*(BN/TN). Per-thread A load = 4 floats (float4);
// per-thread B load = BK*BN/THREADS floats (4 or 2).
// ---------------------------------------------------------------------------
template<int BM, int BN, int BK, int TM, int TN>
__device__ __forceinline__ void gemm_body(
    int N, int K,
    const float* __restrict__ A, const float* __restrict__ B, float* __restrict__ C,
    int bx, int by)
{
    constexpr int THREADS = (BM / TM) * (BN / TN);
    constexpr int BLD = (BK * BN) / THREADS;   // B floats per thread (4 or 2)
    static_assert((BM * BK) / THREADS == 4, "A load must be float4");
    static_assert(BLD == 4 || BLD == 2, "B load must be float4/float2");

    __shared__ float As[2][BK][BM];
    __shared__ float Bs[2][BK][BN];

    const int tid  = threadIdx.x;
    const int trow = tid / (BN / TN);
    const int tcol = tid % (BN / TN);

    const float* Ab = A + (size_t)by * BM * K;
    const float* Bb = B + (size_t)bx * BN;
    float*       Cb = C + (size_t)by * BM * N + (size_t)bx * BN;

    // A-load mapping: BK/4 threads per row
    constexpr int APT = BK / 4;                 // threads per A row (2 for BK=8)
    const int aRow = tid / APT;
    const int aCol = (tid % APT) * 4;
    // B-load mapping
    const int bThreadsPerRow = BN / BLD;
    const int bRow = tid / bThreadsPerRow;
    const int bCol = (tid % bThreadsPerRow) * BLD;

    float acc[TM][TN];
#pragma unroll
    for (int i = 0; i < TM; i++)
#pragma unroll
        for (int j = 0; j < TN; j++) acc[i][j] = 0.f;

    // ---- load tile 0 ----
    float4 a4 = *reinterpret_cast<const float4*>(Ab + (size_t)aRow * K + aCol);
    float4 b4;
    float2 b2;
    if constexpr (BLD == 4)
        b4 = *reinterpret_cast<const float4*>(Bb + (size_t)bRow * N + bCol);
    else
        b2 = *reinterpret_cast<const float2*>(Bb + (size_t)bRow * N + bCol);

    As[0][aCol + 0][aRow] = a4.x;
    As[0][aCol + 1][aRow] = a4.y;
    As[0][aCol + 2][aRow] = a4.z;
    As[0][aCol + 3][aRow] = a4.w;
    if constexpr (BLD == 4)
        *reinterpret_cast<float4*>(&Bs[0][bRow][bCol]) = b4;
    else
        *reinterpret_cast<float2*>(&Bs[0][bRow][bCol]) = b2;
    __syncthreads();

    int buf = 0;
    for (int k0 = BK; k0 < K; k0 += BK) {
        // prefetch next tile into registers
        const float* An = Ab + k0;
        const float* Bn = Bb + (size_t)k0 * N;
        a4 = *reinterpret_cast<const float4*>(An + (size_t)aRow * K + aCol);
        if constexpr (BLD == 4)
            b4 = *reinterpret_cast<const float4*>(Bn + (size_t)bRow * N + bCol);
        else
            b2 = *reinterpret_cast<const float2*>(Bn + (size_t)bRow * N + bCol);

        // compute current tile
#pragma unroll
        for (int kk = 0; kk < BK; kk++) {
            float ar[TM], br[TN];
#pragma unroll
            for (int i = 0; i < TM; i += 4)
                *reinterpret_cast<float4*>(ar + i) =
                    *reinterpret_cast<const float4*>(&As[buf][kk][trow * TM + i]);
#pragma unroll
            for (int j = 0; j < TN; j += 4) {
                if constexpr (TN >= 4)
                    *reinterpret_cast<float4*>(br + j) =
                        *reinterpret_cast<const float4*>(&Bs[buf][kk][tcol * TN + j]);
            }
#pragma unroll
            for (int i = 0; i < TM; i++)
#pragma unroll
                for (int j = 0; j < TN; j++)
                    acc[i][j] = fmaf(ar[i], br[j], acc[i][j]);
        }

        // store prefetched tile into the other buffer
        const int nb = buf ^ 1;
        As[nb][aCol + 0][aRow] = a4.x;
        As[nb][aCol + 1][aRow] = a4.y;
        As[nb][aCol + 2][aRow] = a4.z;
        As[nb][aCol + 3][aRow] = a4.w;
        if constexpr (BLD == 4)
            *reinterpret_cast<float4*>(&Bs[nb][bRow][bCol]) = b4;
        else
            *reinterpret_cast<float2*>(&Bs[nb][bRow][bCol]) = b2;
        __syncthreads();
        buf = nb;
    }

    // last tile
#pragma unroll
    for (int kk = 0; kk < BK; kk++) {
        float ar[TM], br[TN];
#pragma unroll
        for (int i = 0; i < TM; i += 4)
            *reinterpret_cast<float4*>(ar + i) =
                *reinterpret_cast<const float4*>(&As[buf][kk][trow * TM + i]);
#pragma unroll
        for (int j = 0; j < TN; j += 4) {
            if constexpr (TN >= 4)
                *reinterpret_cast<float4*>(br + j) =
                    *reinterpret_cast<const float4*>(&Bs[buf][kk][tcol * TN + j]);
        }
#pragma unroll
        for (int i = 0; i < TM; i++)
#pragma unroll
            for (int j = 0; j < TN; j++)
                acc[i][j] = fmaf(ar[i], br[j], acc[i][j]);
    }

    // epilogue
#pragma unroll
    for (int i = 0; i < TM; i++) {
        float* crow = Cb + (size_t)(trow * TM + i) * N + tcol * TN;
#pragma unroll
        for (int j = 0; j < TN; j += 4)
            *reinterpret_cast<float4*>(crow + j) =
                make_float4(acc[i][j], acc[i][j + 1], acc[i][j + 2], acc[i][j + 3]);
    }
}

// ---------------------------------------------------------------------------
// Fused projection GEMM: z selects {q,k,v,g}. Grid (8,16,4).
// q,k have N=512 (bx<4), v,g have N=1024.
// ---------------------------------------------------------------------------
__global__ __launch_bounds__(256) void proj_gemm_kernel(
    const float* __restrict__ x,
    const float* __restrict__ Bq, const float* __restrict__ Bk,
    const float* __restrict__ Bv, const float* __restrict__ Bg,
    float* __restrict__ Cq, float* __restrict__ Ck,
    float* __restrict__ Cv, float* __restrict__ Cg)
{
    const int z = blockIdx.z;
    const int N = (z < 2) ? KDIM : VDIM;
    if ((int)blockIdx.x * 128 >= N) return;
    const float* B = (z == 0) ? Bq : (z == 1) ? Bk : (z == 2) ? Bv : Bg;
    float*       C = (z == 0) ? Cq : (z == 1) ? Ck : (z == 2) ? Cv : Cg;
    gemm_body<128, 128, 8, 8, 8>(N, DD, x, B, C, blockIdx.x, blockIdx.y);
}

// Output projection: 128x64 tiles -> 256 CTAs.
__global__ __launch_bounds__(256) void out_gemm_kernel(
    const float* __restrict__ A, const float* __restrict__ B, float* __restrict__ C)
{
    gemm_body<128, 64, 8, 8, 4>(DD, VDIM, A, B, C, blockIdx.x, blockIdx.y);
}

// ---------------------------------------------------------------------------
// Low-rank projection t16 = x @ Wgk1, [2048,1024]@[1024,16]. One block per row.
// ---------------------------------------------------------------------------
__global__ __launch_bounds__(128) void proj_lr_kernel(
    const float* __restrict__ x, const float* __restrict__ Wgk1, float* __restrict__ t16)
{
    __shared__ float sx[1024];
    __shared__ float part[8][16];
    const int row = blockIdx.x;
    const int tid = threadIdx.x;
    for (int i = tid; i < 1024; i += 128) sx[i] = x[(size_t)row * 1024 + i];
    __syncthreads();
    const int col = tid & 15;
    const int seg = tid >> 4;
    float p = 0.f;
#pragma unroll 8
    for (int j = 0; j < 128; j++) {
        int kidx = seg * 128 + j;
        p = fmaf(sx[kidx], Wgk1[(size_t)kidx * 16 + col], p);
    }
    part[seg][col] = p;
    __syncthreads();
    if (tid < 16) {
        float s = 0.f;
#pragma unroll
        for (int s8 = 0; s8 < 8; s8++) s += part[s8][tid];
        t16[(size_t)row * 16 + tid] = s;
    }
}

// ---------------------------------------------------------------------------
// Gate: z = t16 @ Wgk2 + bgk2; g = max(log_sigmoid(z)/16, -3); eg = exp(g).
// ---------------------------------------------------------------------------
__global__ __launch_bounds__(256) void gate_eg_kernel(
    const float* __restrict__ t16, const float* __restrict__ Wgk2,
    const float* __restrict__ bgk2, float* __restrict__ eg)
{
    const int row = blockIdx.x;
    const int tid = threadIdx.x;
    __shared__ float st[16];
    if (tid < 16) st[tid] = t16[(size_t)row * 16 + tid];
    __syncthreads();
    for (int c = tid; c < KDIM; c += 256) {
        float z = bgk2[c];
#pragma unroll
        for (int r = 0; r < 16; r++)
            z = fmaf(st[r], Wgk2[(size_t)r * KDIM + c], z);
        float ls = (z >= 0.f) ? -log1pf(expf(-z)) : (z - log1pf(expf(z)));
        float g = fmaxf(ls * (1.f / 16.f), -3.f);
        eg[(size_t)row * KDIM + c] = expf(g);
    }
}

// ---------------------------------------------------------------------------
// GLA scan. Grid: 64 CTAs = (b,h) x 8 v-splits of 32 columns. 128 threads.
// ---------------------------------------------------------------------------
__global__ __launch_bounds__(128) void gla_scan_kernel(
    const float* __restrict__ q, const float* __restrict__ k,
    const float* __restrict__ v, const float* __restrict__ eg,
    float* __restrict__ o)
{
    const int cta = blockIdx.x;
    const int vs = cta & 7;
    const int bh = cta >> 3;
    const int h = bh & 3;
    const int b = bh >> 2;

    const int tid = threadIdx.x;
    const int kg = tid & 15;
    const int vg = tid >> 4;

    __shared__ float sq[128], sk[128], se[128], sv[32];

    float S[8][4];
#pragma unroll
    for (int j = 0; j < 8; j++)
#pragma unroll
        for (int i = 0; i < 4; i++) S[j][i] = 0.f;

    const size_t qoff = ((size_t)b * NN) * KDIM + (size_t)h * DK;
    const float* qb = q + qoff;
    const float* kb = k + qoff;
    const float* ebp = eg + qoff;
    const size_t voff = ((size_t)b * NN) * VDIM + (size_t)h * DV + (size_t)vs * 32;
    const float* vb = v + voff;
    float* ob = o + voff;

    float rq = qb[tid];
    float rk = kb[tid];
    float re = ebp[tid];
    float rv = (tid < 32) ? vb[tid] : 0.f;

    for (int t = 0; t < NN; t++) {
        sq[tid] = rq;
        sk[tid] = rk;
        se[tid] = re;
        if (tid < 32) sv[tid] = rv;
        __syncthreads();

        if (t + 1 < NN) {
            const size_t r = (size_t)(t + 1) * KDIM;
            rq = qb[r + tid];
            rk = kb[r + tid];
            re = ebp[r + tid];
            if (tid < 32) rv = vb[(size_t)(t + 1) * VDIM + tid];
        }

        const float v0 = sv[vg * 4 + 0];
        const float v1 = sv[vg * 4 + 1];
        const float v2 = sv[vg * 4 + 2];
        const float v3 = sv[vg * 4 + 3];

        float a0 = 0.f, a1 = 0.f, a2 = 0.f, a3 = 0.f;
#pragma unroll
        for (int j = 0; j < 8; j++) {
            const int kk = kg + 16 * j;
            const float e = se[kk];
            const float kv = sk[kk];
            const float qv = sq[kk];
            S[j][0] = fmaf(kv, v0, S[j][0] * e); a0 = fmaf(qv, S[j][0], a0);
            S[j][1] = fmaf(kv, v1, S[j][1] * e); a1 = fmaf(qv, S[j][1], a1);
            S[j][2] = fmaf(kv, v2, S[j][2] * e); a2 = fmaf(qv, S[j][2], a2);
            S[j][3] = fmaf(kv, v3, S[j][3] * e); a3 = fmaf(qv, S[j][3], a3);
        }

#pragma unroll
        for (int off = 1; off < 16; off <<= 1) {
            a0 += __shfl_xor_sync(0xffffffffu, a0, off);
            a1 += __shfl_xor_sync(0xffffffffu, a1, off);
            a2 += __shfl_xor_sync(0xffffffffu, a2, off);
            a3 += __shfl_xor_sync(0xffffffffu, a3, off);
        }
        if (kg == 0) {
            *reinterpret_cast<float4*>(ob + (size_t)t * VDIM + vg * 4) =
                make_float4(a0, a1, a2, a3);
        }
        __syncthreads();
    }
}

// ---------------------------------------------------------------------------
// RMSNorm (per head, DV=256) + rms_w + SiLU(gaux) gating. One block per row.
// ---------------------------------------------------------------------------
__global__ __launch_bounds__(256) void norm_gate_kernel(
    const float* __restrict__ o, const float* __restrict__ gaux,
    const float* __restrict__ rms_w, float* __restrict__ y)
{
    const int row = blockIdx.x;
    const int tid = threadIdx.x;
    const size_t base = (size_t)row * VDIM + tid * 4;

    const float4 ov = *reinterpret_cast<const float4*>(o + base);
    float ss = ov.x * ov.x + ov.y * ov.y + ov.z * ov.z + ov.w * ov.w;
#pragma unroll
    for (int off = 16; off; off >>= 1)
        ss += __shfl_xor_sync(0xffffffffu, ss, off);

    __shared__ float ws[8];
    const int warp = tid >> 5, lane = tid & 31;
    if (lane == 0) ws[warp] = ss;
    __syncthreads();

    const int hw = (tid >> 6) << 1;
    const float tot = ws[hw] + ws[hw + 1];
    const float scale = rsqrtf(tot * (1.f / 256.f) + 1e-5f);

    const float4 gv = *reinterpret_cast<const float4*>(gaux + base);
    const int dv = (tid * 4) & 255;
    const float w0 = rms_w[dv + 0], w1 = rms_w[dv + 1], w2 = rms_w[dv + 2], w3 = rms_w[dv + 3];

    float4 r;
    r.x = ov.x * scale * w0 * (gv.x / (1.f + expf(-gv.x)));
    r.y = ov.y * scale * w1 * (gv.y / (1.f + expf(-gv.y)));
    r.z = ov.z * scale * w2 * (gv.z / (1.f + expf(-gv.z)));
    r.w = ov.w * scale * w3 * (gv.w / (1.f + expf(-gv.w)));
    *reinterpret_cast<float4*>(y + base) = r;
}

// ---------------------------------------------------------------------------
extern "C" void kernel_launch(void* const* d_in, const int* in_sizes, int n_in,
                              void* d_out, int out_size)
{
    const float* x    = (const float*)d_in[0];
    const float* Wq   = (const float*)d_in[1];
    const float* Wk   = (const float*)d_in[2];
    const float* Wv   = (const float*)d_in[3];
    const float* Wg   = (const float*)d_in[4];
    const float* Wgk1 = (const float*)d_in[5];
    const float* Wgk2 = (const float*)d_in[6];
    const float* bgk2 = (const float*)d_in[7];
    const float* Wout = (const float*)d_in[8];
    const float* rmsw = (const float*)d_in[9];
    float* out = (float*)d_out;

    float* scratch = nullptr;
    cudaGetSymbolAddress((void**)&scratch, g_scratch);
    float* q   = scratch + OFF_Q;
    float* k   = scratch + OFF_K;
    float* v   = scratch + OFF_V;
    float* ga  = scratch + OFF_GA;
    float* eg  = scratch + OFF_EG;
    float* t16 = scratch + OFF_T16;
    float* o   = scratch + OFF_O;
    float* y   = scratch + OFF_Y;

    // fused projections (q,k,v,g) in one launch
    proj_gemm_kernel<<<dim3(VDIM / 128, MROWS / 128, 4), 256>>>(
        x, Wq, Wk, Wv, Wg, q, k, v, ga);

    // gates
    proj_lr_kernel<<<MROWS, 128>>>(x, Wgk1, t16);
    gate_eg_kernel<<<MROWS, 256>>>(t16, Wgk2, bgk2, eg);

    // recurrent scan
    gla_scan_kernel<<<BB * HH * 8, 128>>>(q, k, v, eg, o);

    // rmsnorm + silu gate
    norm_gate_kernel<<<MROWS, 256>>>(o, ga, rmsw, y);

    // output projection (128x64 tiles for occupancy)
    out_gemm_kernel<<<dim3(VDIM / 64, MROWS / 128), 256>>>(y, Wout, out);
}

// round 3
// speedup vs baseline: 1.8257x; 1.2001x over previous
#include <cuda_runtime.h>
#include <cstdint>
#include <cstddef>

// Problem constants
#define BB 2
#define NN 1024
#define DD 1024
#define HH 4
#define KDIM 512
#define VDIM 1024
#define DK 128
#define DV 256
#define MROWS (BB*NN)
#define CHUNK 64
#define NCHUNK (NN/CHUNK)          // 16
#define TOTCHUNK (BB*HH*NCHUNK)    // 128

// Scratch layout (floats)
#define OFF_Q   0
#define OFF_K   1048576
#define OFF_V   2097152
#define OFF_GA  4194304
#define OFF_G   6291456
#define OFF_T16 7340032
#define OFF_O   7372800
#define OFF_Y   9469952
#define OFF_QH  11567104
#define OFF_KH  12615680
#define OFF_U   13664256
#define OFF_D   17858560
#define SCRATCH_TOTAL 17874944

__device__ float g_scratch[SCRATCH_TOTAL];

// ---------------------------------------------------------------------------
// Double-buffered SIMT GEMM body (unchanged from round 2).
// ---------------------------------------------------------------------------
template<int BM, int BN, int BK, int TM, int TN>
__device__ __forceinline__ void gemm_body(
    int N, int K,
    const float* __restrict__ A, const float* __restrict__ B, float* __restrict__ C,
    int bx, int by)
{
    constexpr int THREADS = (BM / TM) * (BN / TN);
    constexpr int BLD = (BK * BN) / THREADS;
    static_assert((BM * BK) / THREADS == 4, "A load must be float4");
    static_assert(BLD == 4 || BLD == 2, "B load must be float4/float2");

    __shared__ float As[2][BK][BM];
    __shared__ float Bs[2][BK][BN];

    const int tid  = threadIdx.x;
    const int trow = tid / (BN / TN);
    const int tcol = tid % (BN / TN);

    const float* Ab = A + (size_t)by * BM * K;
    const float* Bb = B + (size_t)bx * BN;
    float*       Cb = C + (size_t)by * BM * N + (size_t)bx * BN;

    constexpr int APT = BK / 4;
    const int aRow = tid / APT;
    const int aCol = (tid % APT) * 4;
    const int bThreadsPerRow = BN / BLD;
    const int bRow = tid / bThreadsPerRow;
    const int bCol = (tid % bThreadsPerRow) * BLD;

    float acc[TM][TN];
#pragma unroll
    for (int i = 0; i < TM; i++)
#pragma unroll
        for (int j = 0; j < TN; j++) acc[i][j] = 0.f;

    float4 a4 = *reinterpret_cast<const float4*>(Ab + (size_t)aRow * K + aCol);
    float4 b4;
    float2 b2;
    if constexpr (BLD == 4)
        b4 = *reinterpret_cast<const float4*>(Bb + (size_t)bRow * N + bCol);
    else
        b2 = *reinterpret_cast<const float2*>(Bb + (size_t)bRow * N + bCol);

    As[0][aCol + 0][aRow] = a4.x;
    As[0][aCol + 1][aRow] = a4.y;
    As[0][aCol + 2][aRow] = a4.z;
    As[0][aCol + 3][aRow] = a4.w;
    if constexpr (BLD == 4)
        *reinterpret_cast<float4*>(&Bs[0][bRow][bCol]) = b4;
    else
        *reinterpret_cast<float2*>(&Bs[0][bRow][bCol]) = b2;
    __syncthreads();

    int buf = 0;
    for (int k0 = BK; k0 < K; k0 += BK) {
        const float* An = Ab + k0;
        const float* Bn = Bb + (size_t)k0 * N;
        a4 = *reinterpret_cast<const float4*>(An + (size_t)aRow * K + aCol);
        if constexpr (BLD == 4)
            b4 = *reinterpret_cast<const float4*>(Bn + (size_t)bRow * N + bCol);
        else
            b2 = *reinterpret_cast<const float2*>(Bn + (size_t)bRow * N + bCol);

#pragma unroll
        for (int kk = 0; kk < BK; kk++) {
            float ar[TM], br[TN];
#pragma unroll
            for (int i = 0; i < TM; i += 4)
                *reinterpret_cast<float4*>(ar + i) =
                    *reinterpret_cast<const float4*>(&As[buf][kk][trow * TM + i]);
#pragma unroll
            for (int j = 0; j < TN; j += 4)
                *reinterpret_cast<float4*>(br + j) =
                    *reinterpret_cast<const float4*>(&Bs[buf][kk][tcol * TN + j]);
#pragma unroll
            for (int i = 0; i < TM; i++)
#pragma unroll
                for (int j = 0; j < TN; j++)
                    acc[i][j] = fmaf(ar[i], br[j], acc[i][j]);
        }

        const int nb = buf ^ 1;
        As[nb][aCol + 0][aRow] = a4.x;
        As[nb][aCol + 1][aRow] = a4.y;
        As[nb][aCol + 2][aRow] = a4.z;
        As[nb][aCol + 3][aRow] = a4.w;
        if constexpr (BLD == 4)
            *reinterpret_cast<float4*>(&Bs[nb][bRow][bCol]) = b4;
        else
            *reinterpret_cast<float2*>(&Bs[nb][bRow][bCol]) = b2;
        __syncthreads();
        buf = nb;
    }

#pragma unroll
    for (int kk = 0; kk < BK; kk++) {
        float ar[TM], br[TN];
#pragma unroll
        for (int i = 0; i < TM; i += 4)
            *reinterpret_cast<float4*>(ar + i) =
                *reinterpret_cast<const float4*>(&As[buf][kk][trow * TM + i]);
#pragma unroll
        for (int j = 0; j < TN; j += 4)
            *reinterpret_cast<float4*>(br + j) =
                *reinterpret_cast<const float4*>(&Bs[buf][kk][tcol * TN + j]);
#pragma unroll
        for (int i = 0; i < TM; i++)
#pragma unroll
            for (int j = 0; j < TN; j++)
                acc[i][j] = fmaf(ar[i], br[j], acc[i][j]);
    }

#pragma unroll
    for (int i = 0; i < TM; i++) {
        float* crow = Cb + (size_t)(trow * TM + i) * N + tcol * TN;
#pragma unroll
        for (int j = 0; j < TN; j += 4)
            *reinterpret_cast<float4*>(crow + j) =
                make_float4(acc[i][j], acc[i][j + 1], acc[i][j + 2], acc[i][j + 3]);
    }
}

__global__ __launch_bounds__(256) void proj_gemm_kernel(
    const float* __restrict__ x,
    const float* __restrict__ Bq, const float* __restrict__ Bk,
    const float* __restrict__ Bv, const float* __restrict__ Bg,
    float* __restrict__ Cq, float* __restrict__ Ck,
    float* __restrict__ Cv, float* __restrict__ Cg)
{
    const int z = blockIdx.z;
    const int N = (z < 2) ? KDIM : VDIM;
    if ((int)blockIdx.x * 128 >= N) return;
    const float* B = (z == 0) ? Bq : (z == 1) ? Bk : (z == 2) ? Bv : Bg;
    float*       C = (z == 0) ? Cq : (z == 1) ? Ck : (z == 2) ? Cv : Cg;
    gemm_body<128, 128, 8, 8, 8>(N, DD, x, B, C, blockIdx.x, blockIdx.y);
}

__global__ __launch_bounds__(256) void out_gemm_kernel(
    const float* __restrict__ A, const float* __restrict__ B, float* __restrict__ C)
{
    gemm_body<128, 64, 8, 8, 4>(DD, VDIM, A, B, C, blockIdx.x, blockIdx.y);
}

// ---------------------------------------------------------------------------
// Low-rank projection t16 = x @ Wgk1
// ---------------------------------------------------------------------------
__global__ __launch_bounds__(128) void proj_lr_kernel(
    const float* __restrict__ x, const float* __restrict__ Wgk1, float* __restrict__ t16)
{
    __shared__ float sx[1024];
    __shared__ float part[8][16];
    const int row = blockIdx.x;
    const int tid = threadIdx.x;
    for (int i = tid; i < 1024; i += 128) sx[i] = x[(size_t)row * 1024 + i];
    __syncthreads();
    const int col = tid & 15;
    const int seg = tid >> 4;
    float p = 0.f;
#pragma unroll 8
    for (int j = 0; j < 128; j++) {
        int kidx = seg * 128 + j;
        p = fmaf(sx[kidx], Wgk1[(size_t)kidx * 16 + col], p);
    }
    part[seg][col] = p;
    __syncthreads();
    if (tid < 16) {
        float s = 0.f;
#pragma unroll
        for (int s8 = 0; s8 < 8; s8++) s += part[s8][tid];
        t16[(size_t)row * 16 + tid] = s;
    }
}

// ---------------------------------------------------------------------------
// Gate: g = max(log_sigmoid(t16@Wgk2 + b)/16, -3)   (LOG decay, not exp)
// ---------------------------------------------------------------------------
__global__ __launch_bounds__(256) void gate_g_kernel(
    const float* __restrict__ t16, const float* __restrict__ Wgk2,
    const float* __restrict__ bgk2, float* __restrict__ gout)
{
    const int row = blockIdx.x;
    const int tid = threadIdx.x;
    __shared__ float st[16];
    if (tid < 16) st[tid] = t16[(size_t)row * 16 + tid];
    __syncthreads();
    for (int c = tid; c < KDIM; c += 256) {
        float z = bgk2[c];
#pragma unroll
        for (int r = 0; r < 16; r++)
            z = fmaf(st[r], Wgk2[(size_t)r * KDIM + c], z);
        float ls = (z >= 0.f) ? -log1pf(expf(-z)) : (z - log1pf(expf(z)));
        gout[(size_t)row * KDIM + c] = fmaxf(ls * (1.f / 16.f), -3.f);
    }
}

// ---------------------------------------------------------------------------
// Chunk prep: per (b,h,chunk,d): a_t = cumsum g; qh = q*exp(a), kh = k*exp(-a),
// D = exp(a_C). Grid 128 CTAs x 128 threads.
// ---------------------------------------------------------------------------
__global__ __launch_bounds__(128) void chunk_prep_kernel(
    const float* __restrict__ q, const float* __restrict__ k,
    const float* __restrict__ g, float* __restrict__ qh,
    float* __restrict__ kh, float* __restrict__ D)
{
    const int cta = blockIdx.x;
    const int bh = cta >> 4, c = cta & 15;
    const int b = bh >> 2, h = bh & 3;
    const int d = threadIdx.x;
    const size_t base = ((size_t)(b * NN + c * CHUNK)) * KDIM + h * DK + d;
    float a = 0.f;
#pragma unroll 4
    for (int t = 0; t < CHUNK; t++) {
        const size_t idx = base + (size_t)t * KDIM;
        a += g[idx];
        const float e = expf(a);
        qh[idx] = q[idx] * e;
        kh[idx] = k[idx] / e;
    }
    D[cta * DK + d] = expf(a);
}

// ---------------------------------------------------------------------------
// Intra-chunk: O = tril(Qhat Khat^T) @ V. Grid 128 CTAs x 256 threads.
// ---------------------------------------------------------------------------
__global__ __launch_bounds__(256) void intra_kernel(
    const float* __restrict__ qh, const float* __restrict__ kh,
    const float* __restrict__ v, float* __restrict__ o)
{
    __shared__ float sm[64 * 65 + 64 * 36];
    float* sQ = sm;            // [32][64] (stage 1)
    float* sK = sm + 2048;     // [32][64]
    float* sA = sm;            // [64][65] (stage 2, overlays sQ/sK)
    float* sV = sm + 4160;     // [64][36]

    const int cta = blockIdx.x;
    const int bh = cta >> 4, c = cta & 15;
    const int b = bh >> 2, h = bh & 3;
    const int tid = threadIdx.x;
    const size_t rbase = ((size_t)(b * NN + c * CHUNK)) * KDIM + h * DK;
    const size_t vbase = ((size_t)(b * NN + c * CHUNK)) * VDIM + h * DV;

    const int ty = tid >> 4, tx = tid & 15;
    const int lt = tid & 63, lg = tid >> 6;

    float acc[4][4];
#pragma unroll
    for (int i = 0; i < 4; i++)
#pragma unroll
        for (int j = 0; j < 4; j++) acc[i][j] = 0.f;

    for (int k0 = 0; k0 < DK; k0 += 32) {
        const float* qp = qh + rbase + (size_t)lt * KDIM + k0 + lg * 8;
        const float* kp = kh + rbase + (size_t)lt * KDIM + k0 + lg * 8;
        float4 q0 = *reinterpret_cast<const float4*>(qp);
        float4 q1 = *reinterpret_cast<const float4*>(qp + 4);
        float4 kk0 = *reinterpret_cast<const float4*>(kp);
        float4 kk1 = *reinterpret_cast<const float4*>(kp + 4);
        sQ[(lg * 8 + 0) * 64 + lt] = q0.x; sQ[(lg * 8 + 1) * 64 + lt] = q0.y;
        sQ[(lg * 8 + 2) * 64 + lt] = q0.z; sQ[(lg * 8 + 3) * 64 + lt] = q0.w;
        sQ[(lg * 8 + 4) * 64 + lt] = q1.x; sQ[(lg * 8 + 5) * 64 + lt] = q1.y;
        sQ[(lg * 8 + 6) * 64 + lt] = q1.z; sQ[(lg * 8 + 7) * 64 + lt] = q1.w;
        sK[(lg * 8 + 0) * 64 + lt] = kk0.x; sK[(lg * 8 + 1) * 64 + lt] = kk0.y;
        sK[(lg * 8 + 2) * 64 + lt] = kk0.z; sK[(lg * 8 + 3) * 64 + lt] = kk0.w;
        sK[(lg * 8 + 4) * 64 + lt] = kk1.x; sK[(lg * 8 + 5) * 64 + lt] = kk1.y;
        sK[(lg * 8 + 6) * 64 + lt] = kk1.z; sK[(lg * 8 + 7) * 64 + lt] = kk1.w;
        __syncthreads();
#pragma unroll
        for (int dd = 0; dd < 32; dd++) {
            float4 a4 = *reinterpret_cast<const float4*>(&sQ[dd * 64 + ty * 4]);
            float4 b4 = *reinterpret_cast<const float4*>(&sK[dd * 64 + tx * 4]);
            const float ar[4] = {a4.x, a4.y, a4.z, a4.w};
            const float br[4] = {b4.x, b4.y, b4.z, b4.w};
#pragma unroll
            for (int i = 0; i < 4; i++)
#pragma unroll
                for (int j = 0; j < 4; j++)
                    acc[i][j] = fmaf(ar[i], br[j], acc[i][j]);
        }
        __syncthreads();
    }

    // masked A into smem (causal, diagonal inclusive)
#pragma unroll
    for (int i = 0; i < 4; i++)
#pragma unroll
        for (int j = 0; j < 4; j++) {
            const int t = ty * 4 + i, s = tx * 4 + j;
            sA[t * 65 + s] = (s <= t) ? acc[i][j] : 0.f;
        }
    __syncthreads();

    // stage 2: O = A @ V, v-tiles of 32
    const int t2 = tid >> 2, vq = tid & 3;
    for (int vt = 0; vt < 8; vt++) {
        const float* vp = v + vbase + (size_t)t2 * VDIM + vt * 32 + vq * 8;
        float4 v0 = *reinterpret_cast<const float4*>(vp);
        float4 v1 = *reinterpret_cast<const float4*>(vp + 4);
        *reinterpret_cast<float4*>(&sV[t2 * 36 + vq * 8]) = v0;
        *reinterpret_cast<float4*>(&sV[t2 * 36 + vq * 8 + 4]) = v1;
        __syncthreads();
        float o0[8];
#pragma unroll
        for (int j = 0; j < 8; j++) o0[j] = 0.f;
#pragma unroll 8
        for (int s = 0; s < 64; s++) {
            const float a = sA[t2 * 65 + s];
            float4 x0 = *reinterpret_cast<const float4*>(&sV[s * 36 + vq * 8]);
            float4 x1 = *reinterpret_cast<const float4*>(&sV[s * 36 + vq * 8 + 4]);
            o0[0] = fmaf(a, x0.x, o0[0]); o0[1] = fmaf(a, x0.y, o0[1]);
            o0[2] = fmaf(a, x0.z, o0[2]); o0[3] = fmaf(a, x0.w, o0[3]);
            o0[4] = fmaf(a, x1.x, o0[4]); o0[5] = fmaf(a, x1.y, o0[5]);
            o0[6] = fmaf(a, x1.z, o0[6]); o0[7] = fmaf(a, x1.w, o0[7]);
        }
        float* op = o + vbase + (size_t)t2 * VDIM + vt * 32 + vq * 8;
        *reinterpret_cast<float4*>(op)     = make_float4(o0[0], o0[1], o0[2], o0[3]);
        *reinterpret_cast<float4*>(op + 4) = make_float4(o0[4], o0[5], o0[6], o0[7]);
        __syncthreads();
    }
}

// ---------------------------------------------------------------------------
// Per-chunk state contribution: U = (Khat * D)^T @ V  [128 x 256], K=64.
// Grid (2 n-splits, 128 chunks) x 256 threads, 8x8 register tiles.
// ---------------------------------------------------------------------------
__global__ __launch_bounds__(256) void u_gemm_kernel(
    const float* __restrict__ kh, const float* __restrict__ v,
    const float* __restrict__ D, float* __restrict__ U)
{
    __shared__ float As[8][128];
    __shared__ float Bs[8][128];
    __shared__ float sD[128];

    const int bx = blockIdx.x, by = blockIdx.y;
    const int bh = by >> 4, c = by & 15;
    const int b = bh >> 2, h = bh & 3;
    const int tid = threadIdx.x;
    if (tid < 128) sD[tid] = D[by * DK + tid];

    const size_t kbase = ((size_t)(b * NN + c * CHUNK)) * KDIM + h * DK;
    const size_t vbase = ((size_t)(b * NN + c * CHUNK)) * VDIM + h * DV + bx * 128;
    const int trow = tid >> 4, tcol = tid & 15;
    const int ls = tid >> 5, lc = (tid & 31) * 4;

    float acc[8][8];
#pragma unroll
    for (int i = 0; i < 8; i++)
#pragma unroll
        for (int j = 0; j < 8; j++) acc[i][j] = 0.f;
    __syncthreads();

    for (int s0 = 0; s0 < CHUNK; s0 += 8) {
        float4 a4 = *reinterpret_cast<const float4*>(kh + kbase + (size_t)(s0 + ls) * KDIM + lc);
        float4 b4 = *reinterpret_cast<const float4*>(v + vbase + (size_t)(s0 + ls) * VDIM + lc);
        a4.x *= sD[lc]; a4.y *= sD[lc + 1]; a4.z *= sD[lc + 2]; a4.w *= sD[lc + 3];
        *reinterpret_cast<float4*>(&As[ls][lc]) = a4;
        *reinterpret_cast<float4*>(&Bs[ls][lc]) = b4;
        __syncthreads();
#pragma unroll
        for (int kk = 0; kk < 8; kk++) {
            float ar[8], br[8];
            *reinterpret_cast<float4*>(ar)     = *reinterpret_cast<const float4*>(&As[kk][trow * 8]);
            *reinterpret_cast<float4*>(ar + 4) = *reinterpret_cast<const float4*>(&As[kk][trow * 8 + 4]);
            *reinterpret_cast<float4*>(br)     = *reinterpret_cast<const float4*>(&Bs[kk][tcol * 8]);
            *reinterpret_cast<float4*>(br + 4) = *reinterpret_cast<const float4*>(&Bs[kk][tcol * 8 + 4]);
#pragma unroll
            for (int i = 0; i < 8; i++)
#pragma unroll
                for (int j = 0; j < 8; j++)
                    acc[i][j] = fmaf(ar[i], br[j], acc[i][j]);
        }
        __syncthreads();
    }

    float* Ub = U + ((size_t)by * DK) * DV + bx * 128;
#pragma unroll
    for (int i = 0; i < 8; i++) {
        float* urow = Ub + (size_t)(trow * 8 + i) * DV + tcol * 8;
        *reinterpret_cast<float4*>(urow)     = make_float4(acc[i][0], acc[i][1], acc[i][2], acc[i][3]);
        *reinterpret_cast<float4*>(urow + 4) = make_float4(acc[i][4], acc[i][5], acc[i][6], acc[i][7]);
    }
}

// ---------------------------------------------------------------------------
// Sequential inter-chunk pass: per (b,h,vtile): S in smem [128][64];
// for each chunk: O += Qhat @ S; S = diag(D)S + U. Grid 32 CTAs x 256 thr.
// ---------------------------------------------------------------------------
__global__ __launch_bounds__(256) void inter_kernel(
    const float* __restrict__ qh, const float* __restrict__ U,
    const float* __restrict__ D, float* __restrict__ o)
{
    __shared__ float sS[128 * 68];
    __shared__ float sQ[32 * 64];

    const int bh = blockIdx.x >> 2, vt = blockIdx.x & 3;
    const int b = bh >> 2, h = bh & 3;
    const int tid = threadIdx.x;
    const int ty = tid >> 4, tx = tid & 15;
    const int lt = tid & 63, lg = tid >> 6;

    for (int i = tid; i < 128 * 68; i += 256) sS[i] = 0.f;
    __syncthreads();

    for (int c = 0; c < NCHUNK; c++) {
        const size_t rbase = ((size_t)(b * NN + c * CHUNK)) * KDIM + h * DK;
        if (c > 0) {
            float acc[4][4];
#pragma unroll
            for (int i = 0; i < 4; i++)
#pragma unroll
                for (int j = 0; j < 4; j++) acc[i][j] = 0.f;

            for (int d0 = 0; d0 < DK; d0 += 32) {
                const float* qp = qh + rbase + (size_t)lt * KDIM + d0 + lg * 8;
                float4 q0 = *reinterpret_cast<const float4*>(qp);
                float4 q1 = *reinterpret_cast<const float4*>(qp + 4);
                sQ[(lg * 8 + 0) * 64 + lt] = q0.x; sQ[(lg * 8 + 1) * 64 + lt] = q0.y;
                sQ[(lg * 8 + 2) * 64 + lt] = q0.z; sQ[(lg * 8 + 3) * 64 + lt] = q0.w;
                sQ[(lg * 8 + 4) * 64 + lt] = q1.x; sQ[(lg * 8 + 5) * 64 + lt] = q1.y;
                sQ[(lg * 8 + 6) * 64 + lt] = q1.z; sQ[(lg * 8 + 7) * 64 + lt] = q1.w;
                __syncthreads();
#pragma unroll
                for (int dd = 0; dd < 32; dd++) {
                    float4 a4 = *reinterpret_cast<const float4*>(&sQ[dd * 64 + ty * 4]);
                    float4 b4 = *reinterpret_cast<const float4*>(&sS[(d0 + dd) * 68 + tx * 4]);
                    const float ar[4] = {a4.x, a4.y, a4.z, a4.w};
                    const float br[4] = {b4.x, b4.y, b4.z, b4.w};
#pragma unroll
                    for (int i = 0; i < 4; i++)
#pragma unroll
                        for (int j = 0; j < 4; j++)
                            acc[i][j] = fmaf(ar[i], br[j], acc[i][j]);
                }
                __syncthreads();
            }

            const size_t obase = ((size_t)(b * NN + c * CHUNK)) * VDIM + h * DV + vt * 64;
#pragma unroll
            for (int i = 0; i < 4; i++) {
                float* op = o + obase + (size_t)(ty * 4 + i) * VDIM + tx * 4;
                float4 cur = *reinterpret_cast<const float4*>(op);
                cur.x += acc[i][0]; cur.y += acc[i][1];
                cur.z += acc[i][2]; cur.w += acc[i][3];
                *reinterpret_cast<float4*>(op) = cur;
            }
        }

        // state update: S = diag(D_c) S + U_c  (uses S AFTER all phase-1 reads)
        const float* Uc = U + ((size_t)(bh * NCHUNK + c) * DK) * DV + vt * 64;
        const float* Dc = D + (bh * NCHUNK + c) * DK;
        for (int idx = tid; idx < DK * 64; idx += 256) {
            const int d = idx >> 6, vv = idx & 63;
            sS[d * 68 + vv] = sS[d * 68 + vv] * Dc[d] + Uc[(size_t)d * DV + vv];
        }
        __syncthreads();
    }
}

// ---------------------------------------------------------------------------
// RMSNorm + SiLU gating
// ---------------------------------------------------------------------------
__global__ __launch_bounds__(256) void norm_gate_kernel(
    const float* __restrict__ o, const float* __restrict__ gaux,
    const float* __restrict__ rms_w, float* __restrict__ y)
{
    const int row = blockIdx.x;
    const int tid = threadIdx.x;
    const size_t base = (size_t)row * VDIM + tid * 4;

    const float4 ov = *reinterpret_cast<const float4*>(o + base);
    float ss = ov.x * ov.x + ov.y * ov.y + ov.z * ov.z + ov.w * ov.w;
#pragma unroll
    for (int off = 16; off; off >>= 1)
        ss += __shfl_xor_sync(0xffffffffu, ss, off);

    __shared__ float ws[8];
    const int warp = tid >> 5, lane = tid & 31;
    if (lane == 0) ws[warp] = ss;
    __syncthreads();

    const int hw = (tid >> 6) << 1;
    const float tot = ws[hw] + ws[hw + 1];
    const float scale = rsqrtf(tot * (1.f / 256.f) + 1e-5f);

    const float4 gv = *reinterpret_cast<const float4*>(gaux + base);
    const int dv = (tid * 4) & 255;
    const float w0 = rms_w[dv + 0], w1 = rms_w[dv + 1], w2 = rms_w[dv + 2], w3 = rms_w[dv + 3];

    float4 r;
    r.x = ov.x * scale * w0 * (gv.x / (1.f + expf(-gv.x)));
    r.y = ov.y * scale * w1 * (gv.y / (1.f + expf(-gv.y)));
    r.z = ov.z * scale * w2 * (gv.z / (1.f + expf(-gv.z)));
    r.w = ov.w * scale * w3 * (gv.w / (1.f + expf(-gv.w)));
    *reinterpret_cast<float4*>(y + base) = r;
}

// ---------------------------------------------------------------------------
extern "C" void kernel_launch(void* const* d_in, const int* in_sizes, int n_in,
                              void* d_out, int out_size)
{
    const float* x    = (const float*)d_in[0];
    const float* Wq   = (const float*)d_in[1];
    const float* Wk   = (const float*)d_in[2];
    const float* Wv   = (const float*)d_in[3];
    const float* Wg   = (const float*)d_in[4];
    const float* Wgk1 = (const float*)d_in[5];
    const float* Wgk2 = (const float*)d_in[6];
    const float* bgk2 = (const float*)d_in[7];
    const float* Wout = (const float*)d_in[8];
    const float* rmsw = (const float*)d_in[9];
    float* out = (float*)d_out;

    float* scratch = nullptr;
    cudaGetSymbolAddress((void**)&scratch, g_scratch);
    float* q    = scratch + OFF_Q;
    float* k    = scratch + OFF_K;
    float* v    = scratch + OFF_V;
    float* ga   = scratch + OFF_GA;
    float* gbuf = scratch + OFF_G;
    float* t16  = scratch + OFF_T16;
    float* o    = scratch + OFF_O;
    float* y    = scratch + OFF_Y;
    float* qhb  = scratch + OFF_QH;
    float* khb  = scratch + OFF_KH;
    float* Ub   = scratch + OFF_U;
    float* Db   = scratch + OFF_D;

    proj_gemm_kernel<<<dim3(VDIM / 128, MROWS / 128, 4), 256>>>(
        x, Wq, Wk, Wv, Wg, q, k, v, ga);

    proj_lr_kernel<<<MROWS, 128>>>(x, Wgk1, t16);
    gate_g_kernel<<<MROWS, 256>>>(t16, Wgk2, bgk2, gbuf);

    chunk_prep_kernel<<<TOTCHUNK, 128>>>(q, k, gbuf, qhb, khb, Db);
    intra_kernel<<<TOTCHUNK, 256>>>(qhb, khb, v, o);
    u_gemm_kernel<<<dim3(2, TOTCHUNK), 256>>>(khb, v, Db, Ub);
    inter_kernel<<<BB * HH * 4, 256>>>(qhb, Ub, Db, o);

    norm_gate_kernel<<<MROWS, 256>>>(o, ga, rmsw, y);
    out_gemm_kernel<<<dim3(VDIM / 64, MROWS / 128), 256>>>(y, Wout, out);
}

// round 4
// speedup vs baseline: 2.3408x; 1.2821x over previous
#include <cuda_runtime.h>
#include <cstdint>
#include <cstddef>

// Problem constants
#define BB 2
#define NN 1024
#define DD 1024
#define HH 4
#define KDIM 512
#define VDIM 1024
#define DK 128
#define DV 256
#define MROWS (BB*NN)
#define CHUNK 64
#define NCHUNK (NN/CHUNK)          // 16
#define TOTCHUNK (BB*HH*NCHUNK)    // 128

// Scratch layout (floats)
#define OFF_Q   0
#define OFF_K   1048576
#define OFF_V   2097152
#define OFF_GA  4194304
#define OFF_T16 6291456
#define OFF_O   6324224
#define OFF_Y   8421376
#define OFF_QH  10518528
#define OFF_KH  11567104
#define OFF_U   12615680
#define OFF_D   16809984
#define OFF_S   16826368
#define SCRATCH_TOTAL 21020672

__device__ float g_scratch[SCRATCH_TOTAL];

// ---------------------------------------------------------------------------
// Double-buffered SIMT GEMM body.
// ---------------------------------------------------------------------------
template<int BM, int BN, int BK, int TM, int TN>
__device__ __forceinline__ void gemm_body(
    int N, int K,
    const float* __restrict__ A, const float* __restrict__ B, float* __restrict__ C,
    int bx, int by)
{
    constexpr int THREADS = (BM / TM) * (BN / TN);
    constexpr int BLD = (BK * BN) / THREADS;
    static_assert((BM * BK) / THREADS == 4, "A load must be float4");
    static_assert(BLD == 4 || BLD == 2, "B load must be float4/float2");

    __shared__ float As[2][BK][BM];
    __shared__ float Bs[2][BK][BN];

    const int tid  = threadIdx.x;
    const int trow = tid / (BN / TN);
    const int tcol = tid % (BN / TN);

    const float* Ab = A + (size_t)by * BM * K;
    const float* Bb = B + (size_t)bx * BN;
    float*       Cb = C + (size_t)by * BM * N + (size_t)bx * BN;

    constexpr int APT = BK / 4;
    const int aRow = tid / APT;
    const int aCol = (tid % APT) * 4;
    const int bThreadsPerRow = BN / BLD;
    const int bRow = tid / bThreadsPerRow;
    const int bCol = (tid % bThreadsPerRow) * BLD;

    float acc[TM][TN];
#pragma unroll
    for (int i = 0; i < TM; i++)
#pragma unroll
        for (int j = 0; j < TN; j++) acc[i][j] = 0.f;

    float4 a4 = *reinterpret_cast<const float4*>(Ab + (size_t)aRow * K + aCol);
    float4 b4;
    float2 b2;
    if constexpr (BLD == 4)
        b4 = *reinterpret_cast<const float4*>(Bb + (size_t)bRow * N + bCol);
    else
        b2 = *reinterpret_cast<const float2*>(Bb + (size_t)bRow * N + bCol);

    As[0][aCol + 0][aRow] = a4.x;
    As[0][aCol + 1][aRow] = a4.y;
    As[0][aCol + 2][aRow] = a4.z;
    As[0][aCol + 3][aRow] = a4.w;
    if constexpr (BLD == 4)
        *reinterpret_cast<float4*>(&Bs[0][bRow][bCol]) = b4;
    else
        *reinterpret_cast<float2*>(&Bs[0][bRow][bCol]) = b2;
    __syncthreads();

    int buf = 0;
    for (int k0 = BK; k0 < K; k0 += BK) {
        const float* An = Ab + k0;
        const float* Bn = Bb + (size_t)k0 * N;
        a4 = *reinterpret_cast<const float4*>(An + (size_t)aRow * K + aCol);
        if constexpr (BLD == 4)
            b4 = *reinterpret_cast<const float4*>(Bn + (size_t)bRow * N + bCol);
        else
            b2 = *reinterpret_cast<const float2*>(Bn + (size_t)bRow * N + bCol);

#pragma unroll
        for (int kk = 0; kk < BK; kk++) {
            float ar[TM], br[TN];
#pragma unroll
            for (int i = 0; i < TM; i += 4)
                *reinterpret_cast<float4*>(ar + i) =
                    *reinterpret_cast<const float4*>(&As[buf][kk][trow * TM + i]);
#pragma unroll
            for (int j = 0; j < TN; j += 4)
                *reinterpret_cast<float4*>(br + j) =
                    *reinterpret_cast<const float4*>(&Bs[buf][kk][tcol * TN + j]);
#pragma unroll
            for (int i = 0; i < TM; i++)
#pragma unroll
                for (int j = 0; j < TN; j++)
                    acc[i][j] = fmaf(ar[i], br[j], acc[i][j]);
        }

        const int nb = buf ^ 1;
        As[nb][aCol + 0][aRow] = a4.x;
        As[nb][aCol + 1][aRow] = a4.y;
        As[nb][aCol + 2][aRow] = a4.z;
        As[nb][aCol + 3][aRow] = a4.w;
        if constexpr (BLD == 4)
            *reinterpret_cast<float4*>(&Bs[nb][bRow][bCol]) = b4;
        else
            *reinterpret_cast<float2*>(&Bs[nb][bRow][bCol]) = b2;
        __syncthreads();
        buf = nb;
    }

#pragma unroll
    for (int kk = 0; kk < BK; kk++) {
        float ar[TM], br[TN];
#pragma unroll
        for (int i = 0; i < TM; i += 4)
            *reinterpret_cast<float4*>(ar + i) =
                *reinterpret_cast<const float4*>(&As[buf][kk][trow * TM + i]);
#pragma unroll
        for (int j = 0; j < TN; j += 4)
            *reinterpret_cast<float4*>(br + j) =
                *reinterpret_cast<const float4*>(&Bs[buf][kk][tcol * TN + j]);
#pragma unroll
        for (int i = 0; i < TM; i++)
#pragma unroll
            for (int j = 0; j < TN; j++)
                acc[i][j] = fmaf(ar[i], br[j], acc[i][j]);
    }

#pragma unroll
    for (int i = 0; i < TM; i++) {
        float* crow = Cb + (size_t)(trow * TM + i) * N + tcol * TN;
#pragma unroll
        for (int j = 0; j < TN; j += 4)
            *reinterpret_cast<float4*>(crow + j) =
                make_float4(acc[i][j], acc[i][j + 1], acc[i][j + 2], acc[i][j + 3]);
    }
}

__global__ __launch_bounds__(256) void proj_gemm_kernel(
    const float* __restrict__ x,
    const float* __restrict__ Bq, const float* __restrict__ Bk,
    const float* __restrict__ Bv, const float* __restrict__ Bg,
    float* __restrict__ Cq, float* __restrict__ Ck,
    float* __restrict__ Cv, float* __restrict__ Cg)
{
    const int z = blockIdx.z;
    const int N = (z < 2) ? KDIM : VDIM;
    if ((int)blockIdx.x * 128 >= N) return;
    const float* B = (z == 0) ? Bq : (z == 1) ? Bk : (z == 2) ? Bv : Bg;
    float*       C = (z == 0) ? Cq : (z == 1) ? Ck : (z == 2) ? Cv : Cg;
    gemm_body<128, 128, 8, 8, 8>(N, DD, x, B, C, blockIdx.x, blockIdx.y);
}

__global__ __launch_bounds__(256) void out_gemm_kernel(
    const float* __restrict__ A, const float* __restrict__ B, float* __restrict__ C)
{
    gemm_body<128, 64, 8, 8, 4>(DD, VDIM, A, B, C, blockIdx.x, blockIdx.y);
}

// ---------------------------------------------------------------------------
// Low-rank projection t16 = x @ Wgk1
// ---------------------------------------------------------------------------
__global__ __launch_bounds__(128) void proj_lr_kernel(
    const float* __restrict__ x, const float* __restrict__ Wgk1, float* __restrict__ t16)
{
    __shared__ float sx[1024];
    __shared__ float part[8][16];
    const int row = blockIdx.x;
    const int tid = threadIdx.x;
    for (int i = tid; i < 1024; i += 128) sx[i] = x[(size_t)row * 1024 + i];
    __syncthreads();
    const int col = tid & 15;
    const int seg = tid >> 4;
    float p = 0.f;
#pragma unroll 8
    for (int j = 0; j < 128; j++) {
        int kidx = seg * 128 + j;
        p = fmaf(sx[kidx], Wgk1[(size_t)kidx * 16 + col], p);
    }
    part[seg][col] = p;
    __syncthreads();
    if (tid < 16) {
        float s = 0.f;
#pragma unroll
        for (int s8 = 0; s8 < 8; s8++) s += part[s8][tid];
        t16[(size_t)row * 16 + tid] = s;
    }
}

// ---------------------------------------------------------------------------
// Fused gate + chunk prep. Grid (16 chunks, 8 bh), 256 threads.
// Computes g = max(logsig(t16@Wgk2+b)/16,-3) into smem, cumsum over t,
// then qh = q*exp(a), kh = k/exp(a), D = exp(a_63).
// ---------------------------------------------------------------------------
__global__ __launch_bounds__(256) void gate_prep_kernel(
    const float* __restrict__ q, const float* __restrict__ k,
    const float* __restrict__ t16, const float* __restrict__ Wgk2,
    const float* __restrict__ bgk2,
    float* __restrict__ qh, float* __restrict__ kh, float* __restrict__ D)
{
    __shared__ float st[64][16];
    __shared__ float sg[64 * 128];

    const int c = blockIdx.x, bh = blockIdx.y;
    const int b = bh >> 2, h = bh & 3;
    const int tid = threadIdx.x;

    // load t16 rows for this chunk (coalesced)
    {
        const float* tp = t16 + (size_t)(b * NN + c * CHUNK) * 16;
        for (int i = tid; i < 1024; i += 256)
            (&st[0][0])[i] = tp[i];
    }
    __syncthreads();

    // g into smem
    for (int i = tid; i < CHUNK * DK; i += 256) {
        const int t = i >> 7, d = i & 127;
        float z = bgk2[h * DK + d];
#pragma unroll
        for (int r = 0; r < 16; r++)
            z = fmaf(st[t][r], Wgk2[(size_t)r * KDIM + h * DK + d], z);
        float ls = (z >= 0.f) ? -log1pf(expf(-z)) : (z - log1pf(expf(z)));
        sg[i] = fmaxf(ls * 0.0625f, -3.f);
    }
    __syncthreads();

    // cumsum over t (serial per d, in smem)
    if (tid < 128) {
#pragma unroll 4
        for (int t = 1; t < CHUNK; t++)
            sg[t * 128 + tid] += sg[(t - 1) * 128 + tid];
    }
    __syncthreads();

    // qh/kh (t-parallel, coalesced over d)
    const size_t gbase = ((size_t)(b * NN + c * CHUNK)) * KDIM + h * DK;
    for (int i = tid; i < CHUNK * DK; i += 256) {
        const int t = i >> 7, d = i & 127;
        const size_t idx = gbase + (size_t)t * KDIM + d;
        const float e = __expf(sg[i]);
        qh[idx] = q[idx] * e;
        kh[idx] = __fdividef(k[idx], e);
    }
    if (tid < 128)
        D[(bh * NCHUNK + c) * DK + tid] = __expf(sg[63 * 128 + tid]);
}

// ---------------------------------------------------------------------------
// Intra-chunk: O = tril(Qhat Khat^T) @ V. Grid 128 CTAs x 256 threads.
// ---------------------------------------------------------------------------
__global__ __launch_bounds__(256) void intra_kernel(
    const float* __restrict__ qh, const float* __restrict__ kh,
    const float* __restrict__ v, float* __restrict__ o)
{
    __shared__ float sm[4160 + 64 * 132];
    float* sQ = sm;            // [32][64] (stage 1)
    float* sK = sm + 2048;     // [32][64]
    float* sA = sm;            // [64][65] (stage 2, overlays)
    float* sV = sm + 4160;     // [64][132]

    const int cta = blockIdx.x;
    const int bh = cta >> 4, c = cta & 15;
    const int b = bh >> 2, h = bh & 3;
    const int tid = threadIdx.x;
    const size_t rbase = ((size_t)(b * NN + c * CHUNK)) * KDIM + h * DK;
    const size_t vbase = ((size_t)(b * NN + c * CHUNK)) * VDIM + h * DV;

    const int ty = tid >> 4, tx = tid & 15;
    const int lt = tid & 63, lg = tid >> 6;

    float acc[4][4];
#pragma unroll
    for (int i = 0; i < 4; i++)
#pragma unroll
        for (int j = 0; j < 4; j++) acc[i][j] = 0.f;

    for (int k0 = 0; k0 < DK; k0 += 32) {
        const float* qp = qh + rbase + (size_t)lt * KDIM + k0 + lg * 8;
        const float* kp = kh + rbase + (size_t)lt * KDIM + k0 + lg * 8;
        float4 q0 = *reinterpret_cast<const float4*>(qp);
        float4 q1 = *reinterpret_cast<const float4*>(qp + 4);
        float4 kk0 = *reinterpret_cast<const float4*>(kp);
        float4 kk1 = *reinterpret_cast<const float4*>(kp + 4);
        sQ[(lg * 8 + 0) * 64 + lt] = q0.x; sQ[(lg * 8 + 1) * 64 + lt] = q0.y;
        sQ[(lg * 8 + 2) * 64 + lt] = q0.z; sQ[(lg * 8 + 3) * 64 + lt] = q0.w;
        sQ[(lg * 8 + 4) * 64 + lt] = q1.x; sQ[(lg * 8 + 5) * 64 + lt] = q1.y;
        sQ[(lg * 8 + 6) * 64 + lt] = q1.z; sQ[(lg * 8 + 7) * 64 + lt] = q1.w;
        sK[(lg * 8 + 0) * 64 + lt] = kk0.x; sK[(lg * 8 + 1) * 64 + lt] = kk0.y;
        sK[(lg * 8 + 2) * 64 + lt] = kk0.z; sK[(lg * 8 + 3) * 64 + lt] = kk0.w;
        sK[(lg * 8 + 4) * 64 + lt] = kk1.x; sK[(lg * 8 + 5) * 64 + lt] = kk1.y;
        sK[(lg * 8 + 6) * 64 + lt] = kk1.z; sK[(lg * 8 + 7) * 64 + lt] = kk1.w;
        __syncthreads();
#pragma unroll
        for (int dd = 0; dd < 32; dd++) {
            float4 a4 = *reinterpret_cast<const float4*>(&sQ[dd * 64 + ty * 4]);
            float4 b4 = *reinterpret_cast<const float4*>(&sK[dd * 64 + tx * 4]);
            const float ar[4] = {a4.x, a4.y, a4.z, a4.w};
            const float br[4] = {b4.x, b4.y, b4.z, b4.w};
#pragma unroll
            for (int i = 0; i < 4; i++)
#pragma unroll
                for (int j = 0; j < 4; j++)
                    acc[i][j] = fmaf(ar[i], br[j], acc[i][j]);
        }
        __syncthreads();
    }

    // masked A into smem (causal, diagonal inclusive)
#pragma unroll
    for (int i = 0; i < 4; i++)
#pragma unroll
        for (int j = 0; j < 4; j++) {
            const int t = ty * 4 + i, s = tx * 4 + j;
            sA[t * 65 + s] = (s <= t) ? acc[i][j] : 0.f;
        }
    __syncthreads();

    // stage 2: O = A @ V — two 128-col halves, 4x8 thread tiles
    const int t2r = tid >> 4;   // 0..15 -> rows t2r*4..+3
    const int t2c = tid & 15;   // cols t2c*8
#pragma unroll
    for (int half = 0; half < 2; half++) {
        for (int i = tid; i < 2048; i += 256) {
            const int s = i >> 5, c4 = (i & 31) * 4;
            *reinterpret_cast<float4*>(&sV[s * 132 + c4]) =
                *reinterpret_cast<const float4*>(v + vbase + (size_t)s * VDIM + half * 128 + c4);
        }
        __syncthreads();

        float a2[4][8];
#pragma unroll
        for (int i = 0; i < 4; i++)
#pragma unroll
            for (int j = 0; j < 8; j++) a2[i][j] = 0.f;

#pragma unroll 4
        for (int s = 0; s < CHUNK; s++) {
            float ar[4];
#pragma unroll
            for (int i = 0; i < 4; i++) ar[i] = sA[(t2r * 4 + i) * 65 + s];
            float4 b0 = *reinterpret_cast<const float4*>(&sV[s * 132 + t2c * 8]);
            float4 b1 = *reinterpret_cast<const float4*>(&sV[s * 132 + t2c * 8 + 4]);
            const float br[8] = {b0.x, b0.y, b0.z, b0.w, b1.x, b1.y, b1.z, b1.w};
#pragma unroll
            for (int i = 0; i < 4; i++)
#pragma unroll
                for (int j = 0; j < 8; j++)
                    a2[i][j] = fmaf(ar[i], br[j], a2[i][j]);
        }

#pragma unroll
        for (int i = 0; i < 4; i++) {
            float* op = o + vbase + (size_t)(t2r * 4 + i) * VDIM + half * 128 + t2c * 8;
            *reinterpret_cast<float4*>(op) =
                make_float4(a2[i][0], a2[i][1], a2[i][2], a2[i][3]);
            *reinterpret_cast<float4*>(op + 4) =
                make_float4(a2[i][4], a2[i][5], a2[i][6], a2[i][7]);
        }
        __syncthreads();
    }
}

// ---------------------------------------------------------------------------
// Per-chunk state contribution: U = (Khat * D)^T @ V  [128 x 256], K=64.
// ---------------------------------------------------------------------------
__global__ __launch_bounds__(256) void u_gemm_kernel(
    const float* __restrict__ kh, const float* __restrict__ v,
    const float* __restrict__ D, float* __restrict__ U)
{
    __shared__ float As[8][128];
    __shared__ float Bs[8][128];
    __shared__ float sD[128];

    const int bx = blockIdx.x, by = blockIdx.y;
    const int bh = by >> 4, c = by & 15;
    const int b = bh >> 2, h = bh & 3;
    const int tid = threadIdx.x;
    if (tid < 128) sD[tid] = D[by * DK + tid];

    const size_t kbase = ((size_t)(b * NN + c * CHUNK)) * KDIM + h * DK;
    const size_t vbase = ((size_t)(b * NN + c * CHUNK)) * VDIM + h * DV + bx * 128;
    const int trow = tid >> 4, tcol = tid & 15;
    const int ls = tid >> 5, lc = (tid & 31) * 4;

    float acc[8][8];
#pragma unroll
    for (int i = 0; i < 8; i++)
#pragma unroll
        for (int j = 0; j < 8; j++) acc[i][j] = 0.f;
    __syncthreads();

    for (int s0 = 0; s0 < CHUNK; s0 += 8) {
        float4 a4 = *reinterpret_cast<const float4*>(kh + kbase + (size_t)(s0 + ls) * KDIM + lc);
        float4 b4 = *reinterpret_cast<const float4*>(v + vbase + (size_t)(s0 + ls) * VDIM + lc);
        a4.x *= sD[lc]; a4.y *= sD[lc + 1]; a4.z *= sD[lc + 2]; a4.w *= sD[lc + 3];
        *reinterpret_cast<float4*>(&As[ls][lc]) = a4;
        *reinterpret_cast<float4*>(&Bs[ls][lc]) = b4;
        __syncthreads();
#pragma unroll
        for (int kk = 0; kk < 8; kk++) {
            float ar[8], br[8];
            *reinterpret_cast<float4*>(ar)     = *reinterpret_cast<const float4*>(&As[kk][trow * 8]);
            *reinterpret_cast<float4*>(ar + 4) = *reinterpret_cast<const float4*>(&As[kk][trow * 8 + 4]);
            *reinterpret_cast<float4*>(br)     = *reinterpret_cast<const float4*>(&Bs[kk][tcol * 8]);
            *reinterpret_cast<float4*>(br + 4) = *reinterpret_cast<const float4*>(&Bs[kk][tcol * 8 + 4]);
#pragma unroll
            for (int i = 0; i < 8; i++)
#pragma unroll
                for (int j = 0; j < 8; j++)
                    acc[i][j] = fmaf(ar[i], br[j], acc[i][j]);
        }
        __syncthreads();
    }

    float* Ub = U + ((size_t)by * DK) * DV + bx * 128;
#pragma unroll
    for (int i = 0; i < 8; i++) {
        float* urow = Ub + (size_t)(trow * 8 + i) * DV + tcol * 8;
        *reinterpret_cast<float4*>(urow)     = make_float4(acc[i][0], acc[i][1], acc[i][2], acc[i][3]);
        *reinterpret_cast<float4*>(urow + 4) = make_float4(acc[i][4], acc[i][5], acc[i][6], acc[i][7]);
    }
}

// ---------------------------------------------------------------------------
// Elementwise chunk-state scan: Sstart[c] = D_{c-1}*Sstart[c-1] + U_{c-1}.
// Grid (32, 8 bh) x 256 threads; each thread one (d, 4v) lane over 16 chunks.
// ---------------------------------------------------------------------------
__global__ __launch_bounds__(256) void state_scan_kernel(
    const float* __restrict__ U, const float* __restrict__ D, float* __restrict__ S)
{
    const int bh = blockIdx.y;
    const int e = blockIdx.x * 256 + threadIdx.x;   // 0..8191
    const int d = e >> 6;
    const int vq = (e & 63) * 4;

    float4 s = make_float4(0.f, 0.f, 0.f, 0.f);
#pragma unroll
    for (int c = 0; c < NCHUNK; c++) {
        const size_t base = ((size_t)((bh * NCHUNK + c) * DK) + d) * DV + vq;
        if (c > 0)
            *reinterpret_cast<float4*>(S + base) = s;
        const float dc = D[(bh * NCHUNK + c) * DK + d];
        const float4 u = *reinterpret_cast<const float4*>(U + base);
        s.x = fmaf(s.x, dc, u.x);
        s.y = fmaf(s.y, dc, u.y);
        s.z = fmaf(s.z, dc, u.z);
        s.w = fmaf(s.w, dc, u.w);
    }
}

// ---------------------------------------------------------------------------
// Inter-chunk output: O_c += Qhat_c @ Sstart_c. Batched GEMM,
// grid (2 vhalf, 8*15 chunk-instances) x 256 threads, 4x8 tiles, BK=16.
// ---------------------------------------------------------------------------
__global__ __launch_bounds__(256) void inter2_kernel(
    const float* __restrict__ qh, const float* __restrict__ S, float* __restrict__ o)
{
    __shared__ float sQ[16 * 68];
    __shared__ float sS[16 * 132];

    const int vhalf = blockIdx.x;
    const int j = blockIdx.y;
    const int bh = j / 15;
    const int c = j % 15 + 1;
    const int b = bh >> 2, h = bh & 3;
    const int tid = threadIdx.x;

    const size_t qbase = ((size_t)(b * NN + c * CHUNK)) * KDIM + h * DK;
    const size_t Sbase = ((size_t)((bh * NCHUNK + c) * DK)) * DV + vhalf * 128;
    const size_t obase = ((size_t)(b * NN + c * CHUNK)) * VDIM + h * DV + vhalf * 128;

    const int trow = tid >> 4, tcol = tid & 15;
    const int qt = tid >> 2;            // 0..63
    const int qk = (tid & 3) * 4;       // 0,4,8,12
    const int sr = tid >> 5;            // 0..7
    const int sc = (tid & 31) * 4;

    float acc[4][8];
#pragma unroll
    for (int i = 0; i < 4; i++)
#pragma unroll
        for (int j2 = 0; j2 < 8; j2++) acc[i][j2] = 0.f;

    for (int k0 = 0; k0 < DK; k0 += 16) {
        // Q tile (transposed into sQ[k][t])
        float4 qv = *reinterpret_cast<const float4*>(qh + qbase + (size_t)qt * KDIM + k0 + qk);
        sQ[(qk + 0) * 68 + qt] = qv.x;
        sQ[(qk + 1) * 68 + qt] = qv.y;
        sQ[(qk + 2) * 68 + qt] = qv.z;
        sQ[(qk + 3) * 68 + qt] = qv.w;
        // S tile (direct)
        *reinterpret_cast<float4*>(&sS[sr * 132 + sc]) =
            *reinterpret_cast<const float4*>(S + Sbase + (size_t)(k0 + sr) * DV + sc);
        *reinterpret_cast<float4*>(&sS[(sr + 8) * 132 + sc]) =
            *reinterpret_cast<const float4*>(S + Sbase + (size_t)(k0 + sr + 8) * DV + sc);
        __syncthreads();

#pragma unroll
        for (int kk = 0; kk < 16; kk++) {
            float4 a4 = *reinterpret_cast<const float4*>(&sQ[kk * 68 + trow * 4]);
            float4 b0 = *reinterpret_cast<const float4*>(&sS[kk * 132 + tcol * 8]);
            float4 b1 = *reinterpret_cast<const float4*>(&sS[kk * 132 + tcol * 8 + 4]);
            const float ar[4] = {a4.x, a4.y, a4.z, a4.w};
            const float br[8] = {b0.x, b0.y, b0.z, b0.w, b1.x, b1.y, b1.z, b1.w};
#pragma unroll
            for (int i = 0; i < 4; i++)
#pragma unroll
                for (int j2 = 0; j2 < 8; j2++)
                    acc[i][j2] = fmaf(ar[i], br[j2], acc[i][j2]);
        }
        __syncthreads();
    }

#pragma unroll
    for (int i = 0; i < 4; i++) {
        float* op = o + obase + (size_t)(trow * 4 + i) * VDIM + tcol * 8;
        float4 c0 = *reinterpret_cast<const float4*>(op);
        float4 c1 = *reinterpret_cast<const float4*>(op + 4);
        c0.x += acc[i][0]; c0.y += acc[i][1]; c0.z += acc[i][2]; c0.w += acc[i][3];
        c1.x += acc[i][4]; c1.y += acc[i][5]; c1.z += acc[i][6]; c1.w += acc[i][7];
        *reinterpret_cast<float4*>(op)     = c0;
        *reinterpret_cast<float4*>(op + 4) = c1;
    }
}

// ---------------------------------------------------------------------------
// RMSNorm + SiLU gating
// ---------------------------------------------------------------------------
__global__ __launch_bounds__(256) void norm_gate_kernel(
    const float* __restrict__ o, const float* __restrict__ gaux,
    const float* __restrict__ rms_w, float* __restrict__ y)
{
    const int row = blockIdx.x;
    const int tid = threadIdx.x;
    const size_t base = (size_t)row * VDIM + tid * 4;

    const float4 ov = *reinterpret_cast<const float4*>(o + base);
    float ss = ov.x * ov.x + ov.y * ov.y + ov.z * ov.z + ov.w * ov.w;
#pragma unroll
    for (int off = 16; off; off >>= 1)
        ss += __shfl_xor_sync(0xffffffffu, ss, off);

    __shared__ float ws[8];
    const int warp = tid >> 5, lane = tid & 31;
    if (lane == 0) ws[warp] = ss;
    __syncthreads();

    const int hw = (tid >> 6) << 1;
    const float tot = ws[hw] + ws[hw + 1];
    const float scale = rsqrtf(tot * (1.f / 256.f) + 1e-5f);

    const float4 gv = *reinterpret_cast<const float4*>(gaux + base);
    const int dv = (tid * 4) & 255;
    const float w0 = rms_w[dv + 0], w1 = rms_w[dv + 1], w2 = rms_w[dv + 2], w3 = rms_w[dv + 3];

    float4 r;
    r.x = ov.x * scale * w0 * (gv.x / (1.f + expf(-gv.x)));
    r.y = ov.y * scale * w1 * (gv.y / (1.f + expf(-gv.y)));
    r.z = ov.z * scale * w2 * (gv.z / (1.f + expf(-gv.z)));
    r.w = ov.w * scale * w3 * (gv.w / (1.f + expf(-gv.w)));
    *reinterpret_cast<float4*>(y + base) = r;
}

// ---------------------------------------------------------------------------
extern "C" void kernel_launch(void* const* d_in, const int* in_sizes, int n_in,
                              void* d_out, int out_size)
{
    const float* x    = (const float*)d_in[0];
    const float* Wq   = (const float*)d_in[1];
    const float* Wk   = (const float*)d_in[2];
    const float* Wv   = (const float*)d_in[3];
    const float* Wg   = (const float*)d_in[4];
    const float* Wgk1 = (const float*)d_in[5];
    const float* Wgk2 = (const float*)d_in[6];
    const float* bgk2 = (const float*)d_in[7];
    const float* Wout = (const float*)d_in[8];
    const float* rmsw = (const float*)d_in[9];
    float* out = (float*)d_out;

    float* scratch = nullptr;
    cudaGetSymbolAddress((void**)&scratch, g_scratch);
    float* q    = scratch + OFF_Q;
    float* k    = scratch + OFF_K;
    float* v    = scratch + OFF_V;
    float* ga   = scratch + OFF_GA;
    float* t16  = scratch + OFF_T16;
    float* o    = scratch + OFF_O;
    float* y    = scratch + OFF_Y;
    float* qhb  = scratch + OFF_QH;
    float* khb  = scratch + OFF_KH;
    float* Ub   = scratch + OFF_U;
    float* Db   = scratch + OFF_D;
    float* Sb   = scratch + OFF_S;

    proj_gemm_kernel<<<dim3(VDIM / 128, MROWS / 128, 4), 256>>>(
        x, Wq, Wk, Wv, Wg, q, k, v, ga);

    proj_lr_kernel<<<MROWS, 128>>>(x, Wgk1, t16);
    gate_prep_kernel<<<dim3(NCHUNK, BB * HH), 256>>>(
        q, k, t16, Wgk2, bgk2, qhb, khb, Db);

    intra_kernel<<<TOTCHUNK, 256>>>(qhb, khb, v, o);
    u_gemm_kernel<<<dim3(2, TOTCHUNK), 256>>>(khb, v, Db, Ub);
    state_scan_kernel<<<dim3(32, BB * HH), 256>>>(Ub, Db, Sb);
    inter2_kernel<<<dim3(2, BB * HH * (NCHUNK - 1)), 256>>>(qhb, Sb, o);

    norm_gate_kernel<<<MROWS, 256>>>(o, ga, rmsw, y);
    out_gemm_kernel<<<dim3(VDIM / 64, MROWS / 128), 256>>>(y, Wout, out);
}

// round 5
// speedup vs baseline: 2.7697x; 1.1832x over previous
#include <cuda_runtime.h>
#include <cstdint>
#include <cstddef>

// Problem constants
#define BB 2
#define NN 1024
#define DD 1024
#define HH 4
#define KDIM 512
#define VDIM 1024
#define DK 128
#define DV 256
#define MROWS (BB*NN)
#define CHUNK 64
#define NCHUNK (NN/CHUNK)          // 16
#define TOTCHUNK (BB*HH*NCHUNK)    // 128

// Scratch layout (floats)
#define OFF_Q   0
#define OFF_K   1048576
#define OFF_V   2097152
#define OFF_GA  4194304
#define OFF_T16 6291456
#define OFF_O   6324224
#define OFF_Y   8421376
#define OFF_QH  10518528
#define OFF_KH  11567104
#define OFF_U   12615680
#define OFF_D   16809984
#define OFF_S   16826368
#define SCRATCH_TOTAL 21020672

__device__ float g_scratch[SCRATCH_TOTAL];

// ---------------------------------------------------------------------------
// TF32 helpers
// ---------------------------------------------------------------------------
__device__ __forceinline__ uint32_t f2tf32(float x) {
    uint32_t r;
    asm("cvt.rna.tf32.f32 %0, %1;" : "=r"(r) : "f"(x));
    return r;
}

__device__ __forceinline__ void mma_tf32(
    float* c, uint32_t a0, uint32_t a1, uint32_t a2, uint32_t a3,
    uint32_t b0, uint32_t b1)
{
    asm volatile(
        "mma.sync.aligned.m16n8k8.row.col.f32.tf32.tf32.f32 "
        "{%0,%1,%2,%3}, {%4,%5,%6,%7}, {%8,%9}, {%0,%1,%2,%3};"
        : "+f"(c[0]), "+f"(c[1]), "+f"(c[2]), "+f"(c[3])
        : "r"(a0), "r"(a1), "r"(a2), "r"(a3), "r"(b0), "r"(b1));
}

// ---------------------------------------------------------------------------
// TF32 tensor-core GEMM body: C = A[MxK] @ B[KxN], row-major, 128x128x16
// tiles, 256 threads = 8 warps (2M x 4N), each warp 64x32 via m16n8k8.
// Requires K%16==0.
// ---------------------------------------------------------------------------
__device__ __forceinline__ void tf32_gemm_body(
    int N, int K,
    const float* __restrict__ A, const float* __restrict__ B, float* __restrict__ C,
    int bx, int by)
{
    constexpr int BM = 128, BN = 128, BK = 16, LDA = 132;
    __shared__ uint32_t As[2][BK][LDA];
    __shared__ uint32_t Bs[2][BK][LDA];

    const int tid = threadIdx.x;
    const int lane = tid & 31, wid = tid >> 5;
    const int warpM = wid >> 2, warpN = wid & 3;
    const int lg = lane >> 2, lt = lane & 3;

    const float* Ab = A + (size_t)by * BM * K;
    const float* Bb = B + (size_t)bx * BN;

    const int ar = tid >> 2, ac = (tid & 3) * 4;   // A: rows ar, ar+64; cols ac..ac+3
    const int br = tid >> 5, bc = (tid & 31) * 4;  // B: rows br, br+8; cols bc..bc+3

    float acc[4][4][4];
#pragma unroll
    for (int mt = 0; mt < 4; mt++)
#pragma unroll
        for (int nt = 0; nt < 4; nt++)
#pragma unroll
            for (int i = 0; i < 4; i++) acc[mt][nt][i] = 0.f;

    float4 a40, a41, b40, b41;
    // ---- load tile 0 ----
    a40 = *reinterpret_cast<const float4*>(Ab + (size_t)ar * K + ac);
    a41 = *reinterpret_cast<const float4*>(Ab + (size_t)(ar + 64) * K + ac);
    b40 = *reinterpret_cast<const float4*>(Bb + (size_t)br * N + bc);
    b41 = *reinterpret_cast<const float4*>(Bb + (size_t)(br + 8) * N + bc);

    {
        As[0][ac + 0][ar] = f2tf32(a40.x); As[0][ac + 1][ar] = f2tf32(a40.y);
        As[0][ac + 2][ar] = f2tf32(a40.z); As[0][ac + 3][ar] = f2tf32(a40.w);
        As[0][ac + 0][ar + 64] = f2tf32(a41.x); As[0][ac + 1][ar + 64] = f2tf32(a41.y);
        As[0][ac + 2][ar + 64] = f2tf32(a41.z); As[0][ac + 3][ar + 64] = f2tf32(a41.w);
        uint4 u0 = make_uint4(f2tf32(b40.x), f2tf32(b40.y), f2tf32(b40.z), f2tf32(b40.w));
        uint4 u1 = make_uint4(f2tf32(b41.x), f2tf32(b41.y), f2tf32(b41.z), f2tf32(b41.w));
        *reinterpret_cast<uint4*>(&Bs[0][br][bc]) = u0;
        *reinterpret_cast<uint4*>(&Bs[0][br + 8][bc]) = u1;
    }
    __syncthreads();

    int buf = 0;
    for (int k0 = BK; k0 < K; k0 += BK) {
        // prefetch next tile
        a40 = *reinterpret_cast<const float4*>(Ab + (size_t)ar * K + k0 + ac);
        a41 = *reinterpret_cast<const float4*>(Ab + (size_t)(ar + 64) * K + k0 + ac);
        b40 = *reinterpret_cast<const float4*>(Bb + (size_t)(k0 + br) * N + bc);
        b41 = *reinterpret_cast<const float4*>(Bb + (size_t)(k0 + br + 8) * N + bc);

        // compute current tile
#pragma unroll
        for (int ks = 0; ks < 2; ks++) {
            const int kk = ks * 8;
            uint32_t bf[4][2];
#pragma unroll
            for (int nt = 0; nt < 4; nt++) {
                const int n0 = warpN * 32 + nt * 8 + lg;
                bf[nt][0] = Bs[buf][kk + lt][n0];
                bf[nt][1] = Bs[buf][kk + lt + 4][n0];
            }
#pragma unroll
            for (int mt = 0; mt < 4; mt++) {
                const int m0 = warpM * 64 + mt * 16 + lg;
                const uint32_t A0 = As[buf][kk + lt][m0];
                const uint32_t A1 = As[buf][kk + lt][m0 + 8];
                const uint32_t A2 = As[buf][kk + lt + 4][m0];
                const uint32_t A3 = As[buf][kk + lt + 4][m0 + 8];
#pragma unroll
                for (int nt = 0; nt < 4; nt++)
                    mma_tf32(acc[mt][nt], A0, A1, A2, A3, bf[nt][0], bf[nt][1]);
            }
        }

        // store prefetched tile
        const int nb = buf ^ 1;
        As[nb][ac + 0][ar] = f2tf32(a40.x); As[nb][ac + 1][ar] = f2tf32(a40.y);
        As[nb][ac + 2][ar] = f2tf32(a40.z); As[nb][ac + 3][ar] = f2tf32(a40.w);
        As[nb][ac + 0][ar + 64] = f2tf32(a41.x); As[nb][ac + 1][ar + 64] = f2tf32(a41.y);
        As[nb][ac + 2][ar + 64] = f2tf32(a41.z); As[nb][ac + 3][ar + 64] = f2tf32(a41.w);
        uint4 u0 = make_uint4(f2tf32(b40.x), f2tf32(b40.y), f2tf32(b40.z), f2tf32(b40.w));
        uint4 u1 = make_uint4(f2tf32(b41.x), f2tf32(b41.y), f2tf32(b41.z), f2tf32(b41.w));
        *reinterpret_cast<uint4*>(&Bs[nb][br][bc]) = u0;
        *reinterpret_cast<uint4*>(&Bs[nb][br + 8][bc]) = u1;
        __syncthreads();
        buf = nb;
    }

    // last tile
#pragma unroll
    for (int ks = 0; ks < 2; ks++) {
        const int kk = ks * 8;
        uint32_t bf[4][2];
#pragma unroll
        for (int nt = 0; nt < 4; nt++) {
            const int n0 = warpN * 32 + nt * 8 + lg;
            bf[nt][0] = Bs[buf][kk + lt][n0];
            bf[nt][1] = Bs[buf][kk + lt + 4][n0];
        }
#pragma unroll
        for (int mt = 0; mt < 4; mt++) {
            const int m0 = warpM * 64 + mt * 16 + lg;
            const uint32_t A0 = As[buf][kk + lt][m0];
            const uint32_t A1 = As[buf][kk + lt][m0 + 8];
            const uint32_t A2 = As[buf][kk + lt + 4][m0];
            const uint32_t A3 = As[buf][kk + lt + 4][m0 + 8];
#pragma unroll
            for (int nt = 0; nt < 4; nt++)
                mma_tf32(acc[mt][nt], A0, A1, A2, A3, bf[nt][0], bf[nt][1]);
        }
    }

    // epilogue: float2 stores
    float* Cb = C + (size_t)by * BM * N + (size_t)bx * BN;
#pragma unroll
    for (int mt = 0; mt < 4; mt++) {
        const int r = warpM * 64 + mt * 16 + lg;
#pragma unroll
        for (int nt = 0; nt < 4; nt++) {
            const int c = warpN * 32 + nt * 8 + 2 * lt;
            *reinterpret_cast<float2*>(Cb + (size_t)r * N + c) =
                make_float2(acc[mt][nt][0], acc[mt][nt][1]);
            *reinterpret_cast<float2*>(Cb + (size_t)(r + 8) * N + c) =
                make_float2(acc[mt][nt][2], acc[mt][nt][3]);
        }
    }
}

__global__ __launch_bounds__(256) void proj_gemm_kernel(
    const float* __restrict__ x,
    const float* __restrict__ Bq, const float* __restrict__ Bk,
    const float* __restrict__ Bv, const float* __restrict__ Bg,
    float* __restrict__ Cq, float* __restrict__ Ck,
    float* __restrict__ Cv, float* __restrict__ Cg)
{
    const int z = blockIdx.z;
    const int N = (z < 2) ? KDIM : VDIM;
    if ((int)blockIdx.x * 128 >= N) return;
    const float* B = (z == 0) ? Bq : (z == 1) ? Bk : (z == 2) ? Bv : Bg;
    float*       C = (z == 0) ? Cq : (z == 1) ? Ck : (z == 2) ? Cv : Cg;
    tf32_gemm_body(N, DD, x, B, C, blockIdx.x, blockIdx.y);
}

__global__ __launch_bounds__(256) void out_gemm_kernel(
    const float* __restrict__ A, const float* __restrict__ B, float* __restrict__ C)
{
    tf32_gemm_body(DD, VDIM, A, B, C, blockIdx.x, blockIdx.y);
}

// ---------------------------------------------------------------------------
// Low-rank projection t16 = x @ Wgk1
// ---------------------------------------------------------------------------
__global__ __launch_bounds__(128) void proj_lr_kernel(
    const float* __restrict__ x, const float* __restrict__ Wgk1, float* __restrict__ t16)
{
    __shared__ float sx[1024];
    __shared__ float part[8][16];
    const int row = blockIdx.x;
    const int tid = threadIdx.x;
    for (int i = tid; i < 1024; i += 128) sx[i] = x[(size_t)row * 1024 + i];
    __syncthreads();
    const int col = tid & 15;
    const int seg = tid >> 4;
    float p = 0.f;
#pragma unroll 8
    for (int j = 0; j < 128; j++) {
        int kidx = seg * 128 + j;
        p = fmaf(sx[kidx], Wgk1[(size_t)kidx * 16 + col], p);
    }
    part[seg][col] = p;
    __syncthreads();
    if (tid < 16) {
        float s = 0.f;
#pragma unroll
        for (int s8 = 0; s8 < 8; s8++) s += part[s8][tid];
        t16[(size_t)row * 16 + tid] = s;
    }
}

// ---------------------------------------------------------------------------
// Fused gate + chunk prep.
// ---------------------------------------------------------------------------
__global__ __launch_bounds__(256) void gate_prep_kernel(
    const float* __restrict__ q, const float* __restrict__ k,
    const float* __restrict__ t16, const float* __restrict__ Wgk2,
    const float* __restrict__ bgk2,
    float* __restrict__ qh, float* __restrict__ kh, float* __restrict__ D)
{
    __shared__ float st[64][16];
    __shared__ float sg[64 * 128];

    const int c = blockIdx.x, bh = blockIdx.y;
    const int b = bh >> 2, h = bh & 3;
    const int tid = threadIdx.x;

    {
        const float* tp = t16 + (size_t)(b * NN + c * CHUNK) * 16;
        for (int i = tid; i < 1024; i += 256)
            (&st[0][0])[i] = tp[i];
    }
    __syncthreads();

    for (int i = tid; i < CHUNK * DK; i += 256) {
        const int t = i >> 7, d = i & 127;
        float z = bgk2[h * DK + d];
#pragma unroll
        for (int r = 0; r < 16; r++)
            z = fmaf(st[t][r], Wgk2[(size_t)r * KDIM + h * DK + d], z);
        float ls = (z >= 0.f) ? -log1pf(expf(-z)) : (z - log1pf(expf(z)));
        sg[i] = fmaxf(ls * 0.0625f, -3.f);
    }
    __syncthreads();

    if (tid < 128) {
#pragma unroll 4
        for (int t = 1; t < CHUNK; t++)
            sg[t * 128 + tid] += sg[(t - 1) * 128 + tid];
    }
    __syncthreads();

    const size_t gbase = ((size_t)(b * NN + c * CHUNK)) * KDIM + h * DK;
    for (int i = tid; i < CHUNK * DK; i += 256) {
        const int t = i >> 7, d = i & 127;
        const size_t idx = gbase + (size_t)t * KDIM + d;
        const float e = __expf(sg[i]);
        qh[idx] = q[idx] * e;
        kh[idx] = __fdividef(k[idx], e);
    }
    if (tid < 128)
        D[(bh * NCHUNK + c) * DK + tid] = __expf(sg[63 * 128 + tid]);
}

// ---------------------------------------------------------------------------
// Intra-chunk: O = tril(Qhat Khat^T) @ V. Grid 128 CTAs x 256 threads.
// ---------------------------------------------------------------------------
__global__ __launch_bounds__(256) void intra_kernel(
    const float* __restrict__ qh, const float* __restrict__ kh,
    const float* __restrict__ v, float* __restrict__ o)
{
    __shared__ float sm[4160 + 64 * 132];
    float* sQ = sm;
    float* sK = sm + 2048;
    float* sA = sm;
    float* sV = sm + 4160;

    const int cta = blockIdx.x;
    const int bh = cta >> 4, c = cta & 15;
    const int b = bh >> 2, h = bh & 3;
    const int tid = threadIdx.x;
    const size_t rbase = ((size_t)(b * NN + c * CHUNK)) * KDIM + h * DK;
    const size_t vbase = ((size_t)(b * NN + c * CHUNK)) * VDIM + h * DV;

    const int ty = tid >> 4, tx = tid & 15;
    const int lt = tid & 63, lg = tid >> 6;

    float acc[4][4];
#pragma unroll
    for (int i = 0; i < 4; i++)
#pragma unroll
        for (int j = 0; j < 4; j++) acc[i][j] = 0.f;

    for (int k0 = 0; k0 < DK; k0 += 32) {
        const float* qp = qh + rbase + (size_t)lt * KDIM + k0 + lg * 8;
        const float* kp = kh + rbase + (size_t)lt * KDIM + k0 + lg * 8;
        float4 q0 = *reinterpret_cast<const float4*>(qp);
        float4 q1 = *reinterpret_cast<const float4*>(qp + 4);
        float4 kk0 = *reinterpret_cast<const float4*>(kp);
        float4 kk1 = *reinterpret_cast<const float4*>(kp + 4);
        sQ[(lg * 8 + 0) * 64 + lt] = q0.x; sQ[(lg * 8 + 1) * 64 + lt] = q0.y;
        sQ[(lg * 8 + 2) * 64 + lt] = q0.z; sQ[(lg * 8 + 3) * 64 + lt] = q0.w;
        sQ[(lg * 8 + 4) * 64 + lt] = q1.x; sQ[(lg * 8 + 5) * 64 + lt] = q1.y;
        sQ[(lg * 8 + 6) * 64 + lt] = q1.z; sQ[(lg * 8 + 7) * 64 + lt] = q1.w;
        sK[(lg * 8 + 0) * 64 + lt] = kk0.x; sK[(lg * 8 + 1) * 64 + lt] = kk0.y;
        sK[(lg * 8 + 2) * 64 + lt] = kk0.z; sK[(lg * 8 + 3) * 64 + lt] = kk0.w;
        sK[(lg * 8 + 4) * 64 + lt] = kk1.x; sK[(lg * 8 + 5) * 64 + lt] = kk1.y;
        sK[(lg * 8 + 6) * 64 + lt] = kk1.z; sK[(lg * 8 + 7) * 64 + lt] = kk1.w;
        __syncthreads();
#pragma unroll
        for (int dd = 0; dd < 32; dd++) {
            float4 a4 = *reinterpret_cast<const float4*>(&sQ[dd * 64 + ty * 4]);
            float4 b4 = *reinterpret_cast<const float4*>(&sK[dd * 64 + tx * 4]);
            const float ar[4] = {a4.x, a4.y, a4.z, a4.w};
            const float br[4] = {b4.x, b4.y, b4.z, b4.w};
#pragma unroll
            for (int i = 0; i < 4; i++)
#pragma unroll
                for (int j = 0; j < 4; j++)
                    acc[i][j] = fmaf(ar[i], br[j], acc[i][j]);
        }
        __syncthreads();
    }

#pragma unroll
    for (int i = 0; i < 4; i++)
#pragma unroll
        for (int j = 0; j < 4; j++) {
            const int t = ty * 4 + i, s = tx * 4 + j;
            sA[t * 65 + s] = (s <= t) ? acc[i][j] : 0.f;
        }
    __syncthreads();

    const int t2r = tid >> 4;
    const int t2c = tid & 15;
#pragma unroll
    for (int half = 0; half < 2; half++) {
        for (int i = tid; i < 2048; i += 256) {
            const int s = i >> 5, c4 = (i & 31) * 4;
            *reinterpret_cast<float4*>(&sV[s * 132 + c4]) =
                *reinterpret_cast<const float4*>(v + vbase + (size_t)s * VDIM + half * 128 + c4);
        }
        __syncthreads();

        float a2[4][8];
#pragma unroll
        for (int i = 0; i < 4; i++)
#pragma unroll
            for (int j = 0; j < 8; j++) a2[i][j] = 0.f;

#pragma unroll 4
        for (int s = 0; s < CHUNK; s++) {
            float ar[4];
#pragma unroll
            for (int i = 0; i < 4; i++) ar[i] = sA[(t2r * 4 + i) * 65 + s];
            float4 b0 = *reinterpret_cast<const float4*>(&sV[s * 132 + t2c * 8]);
            float4 b1 = *reinterpret_cast<const float4*>(&sV[s * 132 + t2c * 8 + 4]);
            const float br[8] = {b0.x, b0.y, b0.z, b0.w, b1.x, b1.y, b1.z, b1.w};
#pragma unroll
            for (int i = 0; i < 4; i++)
#pragma unroll
                for (int j = 0; j < 8; j++)
                    a2[i][j] = fmaf(ar[i], br[j], a2[i][j]);
        }

#pragma unroll
        for (int i = 0; i < 4; i++) {
            float* op = o + vbase + (size_t)(t2r * 4 + i) * VDIM + half * 128 + t2c * 8;
            *reinterpret_cast<float4*>(op) =
                make_float4(a2[i][0], a2[i][1], a2[i][2], a2[i][3]);
            *reinterpret_cast<float4*>(op + 4) =
                make_float4(a2[i][4], a2[i][5], a2[i][6], a2[i][7]);
        }
        __syncthreads();
    }
}

// ---------------------------------------------------------------------------
// Per-chunk state contribution: U = (Khat * D)^T @ V
// ---------------------------------------------------------------------------
__global__ __launch_bounds__(256) void u_gemm_kernel(
    const float* __restrict__ kh, const float* __restrict__ v,
    const float* __restrict__ D, float* __restrict__ U)
{
    __shared__ float As[8][128];
    __shared__ float Bs[8][128];
    __shared__ float sD[128];

    const int bx = blockIdx.x, by = blockIdx.y;
    const int bh = by >> 4, c = by & 15;
    const int b = bh >> 2, h = bh & 3;
    const int tid = threadIdx.x;
    if (tid < 128) sD[tid] = D[by * DK + tid];

    const size_t kbase = ((size_t)(b * NN + c * CHUNK)) * KDIM + h * DK;
    const size_t vbase = ((size_t)(b * NN + c * CHUNK)) * VDIM + h * DV + bx * 128;
    const int trow = tid >> 4, tcol = tid & 15;
    const int ls = tid >> 5, lc = (tid & 31) * 4;

    float acc[8][8];
#pragma unroll
    for (int i = 0; i < 8; i++)
#pragma unroll
        for (int j = 0; j < 8; j++) acc[i][j] = 0.f;
    __syncthreads();

    for (int s0 = 0; s0 < CHUNK; s0 += 8) {
        float4 a4 = *reinterpret_cast<const float4*>(kh + kbase + (size_t)(s0 + ls) * KDIM + lc);
        float4 b4 = *reinterpret_cast<const float4*>(v + vbase + (size_t)(s0 + ls) * VDIM + lc);
        a4.x *= sD[lc]; a4.y *= sD[lc + 1]; a4.z *= sD[lc + 2]; a4.w *= sD[lc + 3];
        *reinterpret_cast<float4*>(&As[ls][lc]) = a4;
        *reinterpret_cast<float4*>(&Bs[ls][lc]) = b4;
        __syncthreads();
#pragma unroll
        for (int kk = 0; kk < 8; kk++) {
            float ar[8], br[8];
            *reinterpret_cast<float4*>(ar)     = *reinterpret_cast<const float4*>(&As[kk][trow * 8]);
            *reinterpret_cast<float4*>(ar + 4) = *reinterpret_cast<const float4*>(&As[kk][trow * 8 + 4]);
            *reinterpret_cast<float4*>(br)     = *reinterpret_cast<const float4*>(&Bs[kk][tcol * 8]);
            *reinterpret_cast<float4*>(br + 4) = *reinterpret_cast<const float4*>(&Bs[kk][tcol * 8 + 4]);
#pragma unroll
            for (int i = 0; i < 8; i++)
#pragma unroll
                for (int j = 0; j < 8; j++)
                    acc[i][j] = fmaf(ar[i], br[j], acc[i][j]);
        }
        __syncthreads();
    }

    float* Ub = U + ((size_t)by * DK) * DV + bx * 128;
#pragma unroll
    for (int i = 0; i < 8; i++) {
        float* urow = Ub + (size_t)(trow * 8 + i) * DV + tcol * 8;
        *reinterpret_cast<float4*>(urow)     = make_float4(acc[i][0], acc[i][1], acc[i][2], acc[i][3]);
        *reinterpret_cast<float4*>(urow + 4) = make_float4(acc[i][4], acc[i][5], acc[i][6], acc[i][7]);
    }
}

// ---------------------------------------------------------------------------
// Elementwise chunk-state scan
// ---------------------------------------------------------------------------
__global__ __launch_bounds__(256) void state_scan_kernel(
    const float* __restrict__ U, const float* __restrict__ D, float* __restrict__ S)
{
    const int bh = blockIdx.y;
    const int e = blockIdx.x * 256 + threadIdx.x;
    const int d = e >> 6;
    const int vq = (e & 63) * 4;

    float4 s = make_float4(0.f, 0.f, 0.f, 0.f);
#pragma unroll
    for (int c = 0; c < NCHUNK; c++) {
        const size_t base = ((size_t)((bh * NCHUNK + c) * DK) + d) * DV + vq;
        if (c > 0)
            *reinterpret_cast<float4*>(S + base) = s;
        const float dc = D[(bh * NCHUNK + c) * DK + d];
        const float4 u = *reinterpret_cast<const float4*>(U + base);
        s.x = fmaf(s.x, dc, u.x);
        s.y = fmaf(s.y, dc, u.y);
        s.z = fmaf(s.z, dc, u.z);
        s.w = fmaf(s.w, dc, u.w);
    }
}

// ---------------------------------------------------------------------------
// Inter-chunk output: O_c += Qhat_c @ Sstart_c
// ---------------------------------------------------------------------------
__global__ __launch_bounds__(256) void inter2_kernel(
    const float* __restrict__ qh, const float* __restrict__ S, float* __restrict__ o)
{
    __shared__ float sQ[16 * 68];
    __shared__ float sS[16 * 132];

    const int vhalf = blockIdx.x;
    const int j = blockIdx.y;
    const int bh = j / 15;
    const int c = j % 15 + 1;
    const int b = bh >> 2, h = bh & 3;
    const int tid = threadIdx.x;

    const size_t qbase = ((size_t)(b * NN + c * CHUNK)) * KDIM + h * DK;
    const size_t Sbase = ((size_t)((bh * NCHUNK + c) * DK)) * DV + vhalf * 128;
    const size_t obase = ((size_t)(b * NN + c * CHUNK)) * VDIM + h * DV + vhalf * 128;

    const int trow = tid >> 4, tcol = tid & 15;
    const int qt = tid >> 2;
    const int qk = (tid & 3) * 4;
    const int sr = tid >> 5;
    const int sc = (tid & 31) * 4;

    float acc[4][8];
#pragma unroll
    for (int i = 0; i < 4; i++)
#pragma unroll
        for (int j2 = 0; j2 < 8; j2++) acc[i][j2] = 0.f;

    for (int k0 = 0; k0 < DK; k0 += 16) {
        float4 qv = *reinterpret_cast<const float4*>(qh + qbase + (size_t)qt * KDIM + k0 + qk);
        sQ[(qk + 0) * 68 + qt] = qv.x;
        sQ[(qk + 1) * 68 + qt] = qv.y;
        sQ[(qk + 2) * 68 + qt] = qv.z;
        sQ[(qk + 3) * 68 + qt] = qv.w;
        *reinterpret_cast<float4*>(&sS[sr * 132 + sc]) =
            *reinterpret_cast<const float4*>(S + Sbase + (size_t)(k0 + sr) * DV + sc);
        *reinterpret_cast<float4*>(&sS[(sr + 8) * 132 + sc]) =
            *reinterpret_cast<const float4*>(S + Sbase + (size_t)(k0 + sr + 8) * DV + sc);
        __syncthreads();

#pragma unroll
        for (int kk = 0; kk < 16; kk++) {
            float4 a4 = *reinterpret_cast<const float4*>(&sQ[kk * 68 + trow * 4]);
            float4 b0 = *reinterpret_cast<const float4*>(&sS[kk * 132 + tcol * 8]);
            float4 b1 = *reinterpret_cast<const float4*>(&sS[kk * 132 + tcol * 8 + 4]);
            const float ar[4] = {a4.x, a4.y, a4.z, a4.w};
            const float br[8] = {b0.x, b0.y, b0.z, b0.w, b1.x, b1.y, b1.z, b1.w};
#pragma unroll
            for (int i = 0; i < 4; i++)
#pragma unroll
                for (int j2 = 0; j2 < 8; j2++)
                    acc[i][j2] = fmaf(ar[i], br[j2], acc[i][j2]);
        }
        __syncthreads();
    }

#pragma unroll
    for (int i = 0; i < 4; i++) {
        float* op = o + obase + (size_t)(trow * 4 + i) * VDIM + tcol * 8;
        float4 c0 = *reinterpret_cast<const float4*>(op);
        float4 c1 = *reinterpret_cast<const float4*>(op + 4);
        c0.x += acc[i][0]; c0.y += acc[i][1]; c0.z += acc[i][2]; c0.w += acc[i][3];
        c1.x += acc[i][4]; c1.y += acc[i][5]; c1.z += acc[i][6]; c1.w += acc[i][7];
        *reinterpret_cast<float4*>(op)     = c0;
        *reinterpret_cast<float4*>(op + 4) = c1;
    }
}

// ---------------------------------------------------------------------------
// RMSNorm + SiLU gating
// ---------------------------------------------------------------------------
__global__ __launch_bounds__(256) void norm_gate_kernel(
    const float* __restrict__ o, const float* __restrict__ gaux,
    const float* __restrict__ rms_w, float* __restrict__ y)
{
    const int row = blockIdx.x;
    const int tid = threadIdx.x;
    const size_t base = (size_t)row * VDIM + tid * 4;

    const float4 ov = *reinterpret_cast<const float4*>(o + base);
    float ss = ov.x * ov.x + ov.y * ov.y + ov.z * ov.z + ov.w * ov.w;
#pragma unroll
    for (int off = 16; off; off >>= 1)
        ss += __shfl_xor_sync(0xffffffffu, ss, off);

    __shared__ float ws[8];
    const int warp = tid >> 5, lane = tid & 31;
    if (lane == 0) ws[warp] = ss;
    __syncthreads();

    const int hw = (tid >> 6) << 1;
    const float tot = ws[hw] + ws[hw + 1];
    const float scale = rsqrtf(tot * (1.f / 256.f) + 1e-5f);

    const float4 gv = *reinterpret_cast<const float4*>(gaux + base);
    const int dv = (tid * 4) & 255;
    const float w0 = rms_w[dv + 0], w1 = rms_w[dv + 1], w2 = rms_w[dv + 2], w3 = rms_w[dv + 3];

    float4 r;
    r.x = ov.x * scale * w0 * (gv.x / (1.f + expf(-gv.x)));
    r.y = ov.y * scale * w1 * (gv.y / (1.f + expf(-gv.y)));
    r.z = ov.z * scale * w2 * (gv.z / (1.f + expf(-gv.z)));
    r.w = ov.w * scale * w3 * (gv.w / (1.f + expf(-gv.w)));
    *reinterpret_cast<float4*>(y + base) = r;
}

// ---------------------------------------------------------------------------
extern "C" void kernel_launch(void* const* d_in, const int* in_sizes, int n_in,
                              void* d_out, int out_size)
{
    const float* x    = (const float*)d_in[0];
    const float* Wq   = (const float*)d_in[1];
    const float* Wk   = (const float*)d_in[2];
    const float* Wv   = (const float*)d_in[3];
    const float* Wg   = (const float*)d_in[4];
    const float* Wgk1 = (const float*)d_in[5];
    const float* Wgk2 = (const float*)d_in[6];
    const float* bgk2 = (const float*)d_in[7];
    const float* Wout = (const float*)d_in[8];
    const float* rmsw = (const float*)d_in[9];
    float* out = (float*)d_out;

    float* scratch = nullptr;
    cudaGetSymbolAddress((void**)&scratch, g_scratch);
    float* q    = scratch + OFF_Q;
    float* k    = scratch + OFF_K;
    float* v    = scratch + OFF_V;
    float* ga   = scratch + OFF_GA;
    float* t16  = scratch + OFF_T16;
    float* o    = scratch + OFF_O;
    float* y    = scratch + OFF_Y;
    float* qhb  = scratch + OFF_QH;
    float* khb  = scratch + OFF_KH;
    float* Ub   = scratch + OFF_U;
    float* Db   = scratch + OFF_D;
    float* Sb   = scratch + OFF_S;

    proj_gemm_kernel<<<dim3(VDIM / 128, MROWS / 128, 4), 256>>>(
        x, Wq, Wk, Wv, Wg, q, k, v, ga);

    proj_lr_kernel<<<MROWS, 128>>>(x, Wgk1, t16);
    gate_prep_kernel<<<dim3(NCHUNK, BB * HH), 256>>>(
        q, k, t16, Wgk2, bgk2, qhb, khb, Db);

    intra_kernel<<<TOTCHUNK, 256>>>(qhb, khb, v, o);
    u_gemm_kernel<<<dim3(2, TOTCHUNK), 256>>>(khb, v, Db, Ub);
    state_scan_kernel<<<dim3(32, BB * HH), 256>>>(Ub, Db, Sb);
    inter2_kernel<<<dim3(2, BB * HH * (NCHUNK - 1)), 256>>>(qhb, Sb, o);

    norm_gate_kernel<<<MROWS, 256>>>(o, ga, rmsw, y);
    out_gemm_kernel<<<dim3(VDIM / 128, MROWS / 128), 256>>>(y, Wout, out);
}

// round 6
// speedup vs baseline: 4.2362x; 1.5295x over previous
#include <cuda_runtime.h>
#include <cstdint>
#include <cstddef>

// Problem constants
#define BB 2
#define NN 1024
#define DD 1024
#define HH 4
#define KDIM 512
#define VDIM 1024
#define DK 128
#define DV 256
#define MROWS (BB*NN)
#define CHUNK 64
#define NCHUNK (NN/CHUNK)          // 16
#define TOTCHUNK (BB*HH*NCHUNK)    // 128

// Scratch layout (floats)
#define OFF_AG  0
#define OFF_V   2097152
#define OFF_GA  4194304
#define OFF_T16 6291456
#define OFF_O   6324224
#define OFF_Y   8421376
#define OFF_QH  10518528
#define OFF_KH  11567104
#define OFF_U   12615680
#define OFF_D   16809984
#define OFF_S   16826368
#define SCRATCH_TOTAL 21020672

__device__ float g_scratch[SCRATCH_TOTAL];

// ---------------------------------------------------------------------------
// TF32 helpers
// ---------------------------------------------------------------------------
__device__ __forceinline__ uint32_t f2tf32(float x) {
    uint32_t r;
    asm("cvt.rna.tf32.f32 %0, %1;" : "=r"(r) : "f"(x));
    return r;
}

__device__ __forceinline__ void mma_tf32(
    float* c, uint32_t a0, uint32_t a1, uint32_t a2, uint32_t a3,
    uint32_t b0, uint32_t b1)
{
    asm volatile(
        "mma.sync.aligned.m16n8k8.row.col.f32.tf32.tf32.f32 "
        "{%0,%1,%2,%3}, {%4,%5,%6,%7}, {%8,%9}, {%0,%1,%2,%3};"
        : "+f"(c[0]), "+f"(c[1]), "+f"(c[2]), "+f"(c[3])
        : "r"(a0), "r"(a1), "r"(a2), "r"(a3), "r"(b0), "r"(b1));
}

// ---------------------------------------------------------------------------
// TF32 tensor-core GEMM body: C = A[MxK] @ B[KxN], 128x128x16 tiles,
// 256 threads = 8 warps (2M x 4N). Optional gate: C *= exp(sgn * gA[r][c]).
// ---------------------------------------------------------------------------
__device__ __forceinline__ void tf32_gemm_body(
    int N, int K,
    const float* __restrict__ A, const float* __restrict__ B, float* __restrict__ C,
    int bx, int by, const float* __restrict__ gA, float sgn)
{
    constexpr int BM = 128, BN = 128, BK = 16, LDA = 132;
    __shared__ uint32_t As[2][BK][LDA];
    __shared__ uint32_t Bs[2][BK][LDA];

    const int tid = threadIdx.x;
    const int lane = tid & 31, wid = tid >> 5;
    const int warpM = wid >> 2, warpN = wid & 3;
    const int lg = lane >> 2, lt = lane & 3;

    const float* Ab = A + (size_t)by * BM * K;
    const float* Bb = B + (size_t)bx * BN;

    const int ar = tid >> 2, ac = (tid & 3) * 4;
    const int br = tid >> 5, bc = (tid & 31) * 4;

    float acc[4][4][4];
#pragma unroll
    for (int mt = 0; mt < 4; mt++)
#pragma unroll
        for (int nt = 0; nt < 4; nt++)
#pragma unroll
            for (int i = 0; i < 4; i++) acc[mt][nt][i] = 0.f;

    float4 a40, a41, b40, b41;
    a40 = *reinterpret_cast<const float4*>(Ab + (size_t)ar * K + ac);
    a41 = *reinterpret_cast<const float4*>(Ab + (size_t)(ar + 64) * K + ac);
    b40 = *reinterpret_cast<const float4*>(Bb + (size_t)br * N + bc);
    b41 = *reinterpret_cast<const float4*>(Bb + (size_t)(br + 8) * N + bc);

    {
        As[0][ac + 0][ar] = f2tf32(a40.x); As[0][ac + 1][ar] = f2tf32(a40.y);
        As[0][ac + 2][ar] = f2tf32(a40.z); As[0][ac + 3][ar] = f2tf32(a40.w);
        As[0][ac + 0][ar + 64] = f2tf32(a41.x); As[0][ac + 1][ar + 64] = f2tf32(a41.y);
        As[0][ac + 2][ar + 64] = f2tf32(a41.z); As[0][ac + 3][ar + 64] = f2tf32(a41.w);
        uint4 u0 = make_uint4(f2tf32(b40.x), f2tf32(b40.y), f2tf32(b40.z), f2tf32(b40.w));
        uint4 u1 = make_uint4(f2tf32(b41.x), f2tf32(b41.y), f2tf32(b41.z), f2tf32(b41.w));
        *reinterpret_cast<uint4*>(&Bs[0][br][bc]) = u0;
        *reinterpret_cast<uint4*>(&Bs[0][br + 8][bc]) = u1;
    }
    __syncthreads();

    int buf = 0;
    for (int k0 = BK; k0 < K; k0 += BK) {
        a40 = *reinterpret_cast<const float4*>(Ab + (size_t)ar * K + k0 + ac);
        a41 = *reinterpret_cast<const float4*>(Ab + (size_t)(ar + 64) * K + k0 + ac);
        b40 = *reinterpret_cast<const float4*>(Bb + (size_t)(k0 + br) * N + bc);
        b41 = *reinterpret_cast<const float4*>(Bb + (size_t)(k0 + br + 8) * N + bc);

#pragma unroll
        for (int ks = 0; ks < 2; ks++) {
            const int kk = ks * 8;
            uint32_t bf[4][2];
#pragma unroll
            for (int nt = 0; nt < 4; nt++) {
                const int n0 = warpN * 32 + nt * 8 + lg;
                bf[nt][0] = Bs[buf][kk + lt][n0];
                bf[nt][1] = Bs[buf][kk + lt + 4][n0];
            }
#pragma unroll
            for (int mt = 0; mt < 4; mt++) {
                const int m0 = warpM * 64 + mt * 16 + lg;
                const uint32_t A0 = As[buf][kk + lt][m0];
                const uint32_t A1 = As[buf][kk + lt][m0 + 8];
                const uint32_t A2 = As[buf][kk + lt + 4][m0];
                const uint32_t A3 = As[buf][kk + lt + 4][m0 + 8];
#pragma unroll
                for (int nt = 0; nt < 4; nt++)
                    mma_tf32(acc[mt][nt], A0, A1, A2, A3, bf[nt][0], bf[nt][1]);
            }
        }

        const int nb = buf ^ 1;
        As[nb][ac + 0][ar] = f2tf32(a40.x); As[nb][ac + 1][ar] = f2tf32(a40.y);
        As[nb][ac + 2][ar] = f2tf32(a40.z); As[nb][ac + 3][ar] = f2tf32(a40.w);
        As[nb][ac + 0][ar + 64] = f2tf32(a41.x); As[nb][ac + 1][ar + 64] = f2tf32(a41.y);
        As[nb][ac + 2][ar + 64] = f2tf32(a41.z); As[nb][ac + 3][ar + 64] = f2tf32(a41.w);
        uint4 u0 = make_uint4(f2tf32(b40.x), f2tf32(b40.y), f2tf32(b40.z), f2tf32(b40.w));
        uint4 u1 = make_uint4(f2tf32(b41.x), f2tf32(b41.y), f2tf32(b41.z), f2tf32(b41.w));
        *reinterpret_cast<uint4*>(&Bs[nb][br][bc]) = u0;
        *reinterpret_cast<uint4*>(&Bs[nb][br + 8][bc]) = u1;
        __syncthreads();
        buf = nb;
    }

#pragma unroll
    for (int ks = 0; ks < 2; ks++) {
        const int kk = ks * 8;
        uint32_t bf[4][2];
#pragma unroll
        for (int nt = 0; nt < 4; nt++) {
            const int n0 = warpN * 32 + nt * 8 + lg;
            bf[nt][0] = Bs[buf][kk + lt][n0];
            bf[nt][1] = Bs[buf][kk + lt + 4][n0];
        }
#pragma unroll
        for (int mt = 0; mt < 4; mt++) {
            const int m0 = warpM * 64 + mt * 16 + lg;
            const uint32_t A0 = As[buf][kk + lt][m0];
            const uint32_t A1 = As[buf][kk + lt][m0 + 8];
            const uint32_t A2 = As[buf][kk + lt + 4][m0];
            const uint32_t A3 = As[buf][kk + lt + 4][m0 + 8];
#pragma unroll
            for (int nt = 0; nt < 4; nt++)
                mma_tf32(acc[mt][nt], A0, A1, A2, A3, bf[nt][0], bf[nt][1]);
        }
    }

    float* Cb = C + (size_t)by * BM * N + (size_t)bx * BN;
    if (gA) {
        const float* gb = gA + (size_t)by * BM * N + (size_t)bx * BN;
#pragma unroll
        for (int mt = 0; mt < 4; mt++) {
            const int r = warpM * 64 + mt * 16 + lg;
#pragma unroll
            for (int nt = 0; nt < 4; nt++) {
                const int c = warpN * 32 + nt * 8 + 2 * lt;
                float2 e0 = *reinterpret_cast<const float2*>(gb + (size_t)r * N + c);
                float2 e1 = *reinterpret_cast<const float2*>(gb + (size_t)(r + 8) * N + c);
                *reinterpret_cast<float2*>(Cb + (size_t)r * N + c) =
                    make_float2(acc[mt][nt][0] * __expf(sgn * e0.x),
                                acc[mt][nt][1] * __expf(sgn * e0.y));
                *reinterpret_cast<float2*>(Cb + (size_t)(r + 8) * N + c) =
                    make_float2(acc[mt][nt][2] * __expf(sgn * e1.x),
                                acc[mt][nt][3] * __expf(sgn * e1.y));
            }
        }
    } else {
#pragma unroll
        for (int mt = 0; mt < 4; mt++) {
            const int r = warpM * 64 + mt * 16 + lg;
#pragma unroll
            for (int nt = 0; nt < 4; nt++) {
                const int c = warpN * 32 + nt * 8 + 2 * lt;
                *reinterpret_cast<float2*>(Cb + (size_t)r * N + c) =
                    make_float2(acc[mt][nt][0], acc[mt][nt][1]);
                *reinterpret_cast<float2*>(Cb + (size_t)(r + 8) * N + c) =
                    make_float2(acc[mt][nt][2], acc[mt][nt][3]);
            }
        }
    }
}

// Fused projections: z=0 -> qh (gate e^{+A}), z=1 -> kh (gate e^{-A}),
// z=2 -> v, z=3 -> gaux.
__global__ __launch_bounds__(256) void proj_gemm_kernel(
    const float* __restrict__ x,
    const float* __restrict__ Bq, const float* __restrict__ Bk,
    const float* __restrict__ Bv, const float* __restrict__ Bg,
    float* __restrict__ Cq, float* __restrict__ Ck,
    float* __restrict__ Cv, float* __restrict__ Cg,
    const float* __restrict__ Ag)
{
    const int z = blockIdx.z;
    const int N = (z < 2) ? KDIM : VDIM;
    if ((int)blockIdx.x * 128 >= N) return;
    const float* B = (z == 0) ? Bq : (z == 1) ? Bk : (z == 2) ? Bv : Bg;
    float*       C = (z == 0) ? Cq : (z == 1) ? Ck : (z == 2) ? Cv : Cg;
    const float* gA = (z < 2) ? Ag : nullptr;
    const float sgn = (z == 0) ? 1.f : -1.f;
    tf32_gemm_body(N, DD, x, B, C, blockIdx.x, blockIdx.y, gA, sgn);
}

__global__ __launch_bounds__(256) void out_gemm_kernel(
    const float* __restrict__ A, const float* __restrict__ B, float* __restrict__ C)
{
    tf32_gemm_body(DD, VDIM, A, B, C, blockIdx.x, blockIdx.y, nullptr, 0.f);
}

// ---------------------------------------------------------------------------
// Low-rank projection t16 = x @ Wgk1
// ---------------------------------------------------------------------------
__global__ __launch_bounds__(128) void proj_lr_kernel(
    const float* __restrict__ x, const float* __restrict__ Wgk1, float* __restrict__ t16)
{
    __shared__ float sx[1024];
    __shared__ float part[8][16];
    const int row = blockIdx.x;
    const int tid = threadIdx.x;
    for (int i = tid; i < 1024; i += 128) sx[i] = x[(size_t)row * 1024 + i];
    __syncthreads();
    const int col = tid & 15;
    const int seg = tid >> 4;
    float p = 0.f;
#pragma unroll 8
    for (int j = 0; j < 128; j++) {
        int kidx = seg * 128 + j;
        p = fmaf(sx[kidx], Wgk1[(size_t)kidx * 16 + col], p);
    }
    part[seg][col] = p;
    __syncthreads();
    if (tid < 16) {
        float s = 0.f;
#pragma unroll
        for (int s8 = 0; s8 < 8; s8++) s += part[s8][tid];
        t16[(size_t)row * 16 + tid] = s;
    }
}

// ---------------------------------------------------------------------------
// Gate cumsum: A = cumsum_t(max(logsig(t16@Wgk2+b)/16,-3)) per chunk;
// D = exp(A at t=63). Grid (16 chunks, 8 bh) x 256 threads.
// ---------------------------------------------------------------------------
__global__ __launch_bounds__(256) void gate_cum_kernel(
    const float* __restrict__ t16, const float* __restrict__ Wgk2,
    const float* __restrict__ bgk2,
    float* __restrict__ Ag, float* __restrict__ D)
{
    __shared__ float st[64][16];
    __shared__ float sg[64 * 128];

    const int c = blockIdx.x, bh = blockIdx.y;
    const int b = bh >> 2, h = bh & 3;
    const int tid = threadIdx.x;

    {
        const float* tp = t16 + (size_t)(b * NN + c * CHUNK) * 16;
        for (int i = tid; i < 1024; i += 256)
            (&st[0][0])[i] = tp[i];
    }
    __syncthreads();

    for (int i = tid; i < CHUNK * DK; i += 256) {
        const int t = i >> 7, d = i & 127;
        float z = bgk2[h * DK + d];
#pragma unroll
        for (int r = 0; r < 16; r++)
            z = fmaf(st[t][r], Wgk2[(size_t)r * KDIM + h * DK + d], z);
        float ls = (z >= 0.f) ? -log1pf(expf(-z)) : (z - log1pf(expf(z)));
        sg[i] = fmaxf(ls * 0.0625f, -3.f);
    }
    __syncthreads();

    // two-level cumsum: thread pairs per d (halves of 32), then offset fix
    {
        const int d = tid & 127, hl = tid >> 7;  // hl=0: t 0..31, hl=1: t 32..63
        const int t0 = hl * 32;
#pragma unroll 4
        for (int t = t0 + 1; t < t0 + 32; t++)
            sg[t * 128 + d] += sg[(t - 1) * 128 + d];
    }
    __syncthreads();
    {
        const int d = tid & 127, hl = tid >> 7;
        if (hl == 1) {
            const float off = sg[31 * 128 + d];
#pragma unroll 4
            for (int t = 32; t < 64; t++)
                sg[t * 128 + d] += off;
        }
    }
    __syncthreads();

    const size_t gbase = ((size_t)(b * NN + c * CHUNK)) * KDIM + h * DK;
    for (int i = tid; i < CHUNK * DK; i += 256) {
        const int t = i >> 7, d = i & 127;
        Ag[gbase + (size_t)t * KDIM + d] = sg[i];
    }
    if (tid < 128)
        D[(bh * NCHUNK + c) * DK + tid] = __expf(sg[63 * 128 + tid]);
}

// ---------------------------------------------------------------------------
// Intra-chunk: O = tril(Qhat Khat^T) @ V.
// Grid 256 CTAs = (chunk-instance, vhalf) x 256 threads.
// ---------------------------------------------------------------------------
__global__ __launch_bounds__(256) void intra_kernel(
    const float* __restrict__ qh, const float* __restrict__ kh,
    const float* __restrict__ v, float* __restrict__ o)
{
    __shared__ float sm[4160 + 64 * 132];
    float* sQ = sm;
    float* sK = sm + 2048;
    float* sA = sm;
    float* sV = sm + 4160;

    const int vhalf = blockIdx.x & 1;
    const int cta = blockIdx.x >> 1;
    const int bh = cta >> 4, c = cta & 15;
    const int b = bh >> 2, h = bh & 3;
    const int tid = threadIdx.x;
    const size_t rbase = ((size_t)(b * NN + c * CHUNK)) * KDIM + h * DK;
    const size_t vbase = ((size_t)(b * NN + c * CHUNK)) * VDIM + h * DV;

    const int ty = tid >> 4, tx = tid & 15;
    const int lt = tid & 63, lg = tid >> 6;

    float acc[4][4];
#pragma unroll
    for (int i = 0; i < 4; i++)
#pragma unroll
        for (int j = 0; j < 4; j++) acc[i][j] = 0.f;

    for (int k0 = 0; k0 < DK; k0 += 32) {
        const float* qp = qh + rbase + (size_t)lt * KDIM + k0 + lg * 8;
        const float* kp = kh + rbase + (size_t)lt * KDIM + k0 + lg * 8;
        float4 q0 = *reinterpret_cast<const float4*>(qp);
        float4 q1 = *reinterpret_cast<const float4*>(qp + 4);
        float4 kk0 = *reinterpret_cast<const float4*>(kp);
        float4 kk1 = *reinterpret_cast<const float4*>(kp + 4);
        sQ[(lg * 8 + 0) * 64 + lt] = q0.x; sQ[(lg * 8 + 1) * 64 + lt] = q0.y;
        sQ[(lg * 8 + 2) * 64 + lt] = q0.z; sQ[(lg * 8 + 3) * 64 + lt] = q0.w;
        sQ[(lg * 8 + 4) * 64 + lt] = q1.x; sQ[(lg * 8 + 5) * 64 + lt] = q1.y;
        sQ[(lg * 8 + 6) * 64 + lt] = q1.z; sQ[(lg * 8 + 7) * 64 + lt] = q1.w;
        sK[(lg * 8 + 0) * 64 + lt] = kk0.x; sK[(lg * 8 + 1) * 64 + lt] = kk0.y;
        sK[(lg * 8 + 2) * 64 + lt] = kk0.z; sK[(lg * 8 + 3) * 64 + lt] = kk0.w;
        sK[(lg * 8 + 4) * 64 + lt] = kk1.x; sK[(lg * 8 + 5) * 64 + lt] = kk1.y;
        sK[(lg * 8 + 6) * 64 + lt] = kk1.z; sK[(lg * 8 + 7) * 64 + lt] = kk1.w;
        __syncthreads();
#pragma unroll
        for (int dd = 0; dd < 32; dd++) {
            float4 a4 = *reinterpret_cast<const float4*>(&sQ[dd * 64 + ty * 4]);
            float4 b4 = *reinterpret_cast<const float4*>(&sK[dd * 64 + tx * 4]);
            const float ar[4] = {a4.x, a4.y, a4.z, a4.w};
            const float br[4] = {b4.x, b4.y, b4.z, b4.w};
#pragma unroll
            for (int i = 0; i < 4; i++)
#pragma unroll
                for (int j = 0; j < 4; j++)
                    acc[i][j] = fmaf(ar[i], br[j], acc[i][j]);
        }
        __syncthreads();
    }

#pragma unroll
    for (int i = 0; i < 4; i++)
#pragma unroll
        for (int j = 0; j < 4; j++) {
            const int t = ty * 4 + i, s = tx * 4 + j;
            sA[t * 65 + s] = (s <= t) ? acc[i][j] : 0.f;
        }
    __syncthreads();

    // stage 2: this CTA's 128-col half only
    const int t2r = tid >> 4;
    const int t2c = tid & 15;
    for (int i = tid; i < 2048; i += 256) {
        const int s = i >> 5, c4 = (i & 31) * 4;
        *reinterpret_cast<float4*>(&sV[s * 132 + c4]) =
            *reinterpret_cast<const float4*>(v + vbase + (size_t)s * VDIM + vhalf * 128 + c4);
    }
    __syncthreads();

    float a2[4][8];
#pragma unroll
    for (int i = 0; i < 4; i++)
#pragma unroll
        for (int j = 0; j < 8; j++) a2[i][j] = 0.f;

#pragma unroll 4
    for (int s = 0; s < CHUNK; s++) {
        float ar[4];
#pragma unroll
        for (int i = 0; i < 4; i++) ar[i] = sA[(t2r * 4 + i) * 65 + s];
        float4 b0 = *reinterpret_cast<const float4*>(&sV[s * 132 + t2c * 8]);
        float4 b1 = *reinterpret_cast<const float4*>(&sV[s * 132 + t2c * 8 + 4]);
        const float br[8] = {b0.x, b0.y, b0.z, b0.w, b1.x, b1.y, b1.z, b1.w};
#pragma unroll
        for (int i = 0; i < 4; i++)
#pragma unroll
            for (int j = 0; j < 8; j++)
                a2[i][j] = fmaf(ar[i], br[j], a2[i][j]);
    }

#pragma unroll
    for (int i = 0; i < 4; i++) {
        float* op = o + vbase + (size_t)(t2r * 4 + i) * VDIM + vhalf * 128 + t2c * 8;
        *reinterpret_cast<float4*>(op) =
            make_float4(a2[i][0], a2[i][1], a2[i][2], a2[i][3]);
        *reinterpret_cast<float4*>(op + 4) =
            make_float4(a2[i][4], a2[i][5], a2[i][6], a2[i][7]);
    }
}

// ---------------------------------------------------------------------------
// Per-chunk state contribution: U = (Khat * D)^T @ V
// ---------------------------------------------------------------------------
__global__ __launch_bounds__(256) void u_gemm_kernel(
    const float* __restrict__ kh, const float* __restrict__ v,
    const float* __restrict__ D, float* __restrict__ U)
{
    __shared__ float As[8][128];
    __shared__ float Bs[8][128];
    __shared__ float sD[128];

    const int bx = blockIdx.x, by = blockIdx.y;
    const int bh = by >> 4, c = by & 15;
    const int b = bh >> 2, h = bh & 3;
    const int tid = threadIdx.x;
    if (tid < 128) sD[tid] = D[by * DK + tid];

    const size_t kbase = ((size_t)(b * NN + c * CHUNK)) * KDIM + h * DK;
    const size_t vbase = ((size_t)(b * NN + c * CHUNK)) * VDIM + h * DV + bx * 128;
    const int trow = tid >> 4, tcol = tid & 15;
    const int ls = tid >> 5, lc = (tid & 31) * 4;

    float acc[8][8];
#pragma unroll
    for (int i = 0; i < 8; i++)
#pragma unroll
        for (int j = 0; j < 8; j++) acc[i][j] = 0.f;
    __syncthreads();

    for (int s0 = 0; s0 < CHUNK; s0 += 8) {
        float4 a4 = *reinterpret_cast<const float4*>(kh + kbase + (size_t)(s0 + ls) * KDIM + lc);
        float4 b4 = *reinterpret_cast<const float4*>(v + vbase + (size_t)(s0 + ls) * VDIM + lc);
        a4.x *= sD[lc]; a4.y *= sD[lc + 1]; a4.z *= sD[lc + 2]; a4.w *= sD[lc + 3];
        *reinterpret_cast<float4*>(&As[ls][lc]) = a4;
        *reinterpret_cast<float4*>(&Bs[ls][lc]) = b4;
        __syncthreads();
#pragma unroll
        for (int kk = 0; kk < 8; kk++) {
            float ar[8], br[8];
            *reinterpret_cast<float4*>(ar)     = *reinterpret_cast<const float4*>(&As[kk][trow * 8]);
            *reinterpret_cast<float4*>(ar + 4) = *reinterpret_cast<const float4*>(&As[kk][trow * 8 + 4]);
            *reinterpret_cast<float4*>(br)     = *reinterpret_cast<const float4*>(&Bs[kk][tcol * 8]);
            *reinterpret_cast<float4*>(br + 4) = *reinterpret_cast<const float4*>(&Bs[kk][tcol * 8 + 4]);
#pragma unroll
            for (int i = 0; i < 8; i++)
#pragma unroll
                for (int j = 0; j < 8; j++)
                    acc[i][j] = fmaf(ar[i], br[j], acc[i][j]);
        }
        __syncthreads();
    }

    float* Ub = U + ((size_t)by * DK) * DV + bx * 128;
#pragma unroll
    for (int i = 0; i < 8; i++) {
        float* urow = Ub + (size_t)(trow * 8 + i) * DV + tcol * 8;
        *reinterpret_cast<float4*>(urow)     = make_float4(acc[i][0], acc[i][1], acc[i][2], acc[i][3]);
        *reinterpret_cast<float4*>(urow + 4) = make_float4(acc[i][4], acc[i][5], acc[i][6], acc[i][7]);
    }
}

// ---------------------------------------------------------------------------
// Elementwise chunk-state scan
// ---------------------------------------------------------------------------
__global__ __launch_bounds__(256) void state_scan_kernel(
    const float* __restrict__ U, const float* __restrict__ D, float* __restrict__ S)
{
    const int bh = blockIdx.y;
    const int e = blockIdx.x * 256 + threadIdx.x;
    const int d = e >> 6;
    const int vq = (e & 63) * 4;

    float4 s = make_float4(0.f, 0.f, 0.f, 0.f);
#pragma unroll
    for (int c = 0; c < NCHUNK; c++) {
        const size_t base = ((size_t)((bh * NCHUNK + c) * DK) + d) * DV + vq;
        if (c > 0)
            *reinterpret_cast<float4*>(S + base) = s;
        const float dc = D[(bh * NCHUNK + c) * DK + d];
        const float4 u = *reinterpret_cast<const float4*>(U + base);
        s.x = fmaf(s.x, dc, u.x);
        s.y = fmaf(s.y, dc, u.y);
        s.z = fmaf(s.z, dc, u.z);
        s.w = fmaf(s.w, dc, u.w);
    }
}

// ---------------------------------------------------------------------------
// Inter-chunk output: O_c += Qhat_c @ Sstart_c
// ---------------------------------------------------------------------------
__global__ __launch_bounds__(256) void inter2_kernel(
    const float* __restrict__ qh, const float* __restrict__ S, float* __restrict__ o)
{
    __shared__ float sQ[16 * 68];
    __shared__ float sS[16 * 132];

    const int vhalf = blockIdx.x;
    const int j = blockIdx.y;
    const int bh = j / 15;
    const int c = j % 15 + 1;
    const int b = bh >> 2, h = bh & 3;
    const int tid = threadIdx.x;

    const size_t qbase = ((size_t)(b * NN + c * CHUNK)) * KDIM + h * DK;
    const size_t Sbase = ((size_t)((bh * NCHUNK + c) * DK)) * DV + vhalf * 128;
    const size_t obase = ((size_t)(b * NN + c * CHUNK)) * VDIM + h * DV + vhalf * 128;

    const int trow = tid >> 4, tcol = tid & 15;
    const int qt = tid >> 2;
    const int qk = (tid & 3) * 4;
    const int sr = tid >> 5;
    const int sc = (tid & 31) * 4;

    float acc[4][8];
#pragma unroll
    for (int i = 0; i < 4; i++)
#pragma unroll
        for (int j2 = 0; j2 < 8; j2++) acc[i][j2] = 0.f;

    for (int k0 = 0; k0 < DK; k0 += 16) {
        float4 qv = *reinterpret_cast<const float4*>(qh + qbase + (size_t)qt * KDIM + k0 + qk);
        sQ[(qk + 0) * 68 + qt] = qv.x;
        sQ[(qk + 1) * 68 + qt] = qv.y;
        sQ[(qk + 2) * 68 + qt] = qv.z;
        sQ[(qk + 3) * 68 + qt] = qv.w;
        *reinterpret_cast<float4*>(&sS[sr * 132 + sc]) =
            *reinterpret_cast<const float4*>(S + Sbase + (size_t)(k0 + sr) * DV + sc);
        *reinterpret_cast<float4*>(&sS[(sr + 8) * 132 + sc]) =
            *reinterpret_cast<const float4*>(S + Sbase + (size_t)(k0 + sr + 8) * DV + sc);
        __syncthreads();

#pragma unroll
        for (int kk = 0; kk < 16; kk++) {
            float4 a4 = *reinterpret_cast<const float4*>(&sQ[kk * 68 + trow * 4]);
            float4 b0 = *reinterpret_cast<const float4*>(&sS[kk * 132 + tcol * 8]);
            float4 b1 = *reinterpret_cast<const float4*>(&sS[kk * 132 + tcol * 8 + 4]);
            const float ar[4] = {a4.x, a4.y, a4.z, a4.w};
            const float br[8] = {b0.x, b0.y, b0.z, b0.w, b1.x, b1.y, b1.z, b1.w};
#pragma unroll
            for (int i = 0; i < 4; i++)
#pragma unroll
                for (int j2 = 0; j2 < 8; j2++)
                    acc[i][j2] = fmaf(ar[i], br[j2], acc[i][j2]);
        }
        __syncthreads();
    }

#pragma unroll
    for (int i = 0; i < 4; i++) {
        float* op = o + obase + (size_t)(trow * 4 + i) * VDIM + tcol * 8;
        float4 c0 = *reinterpret_cast<const float4*>(op);
        float4 c1 = *reinterpret_cast<const float4*>(op + 4);
        c0.x += acc[i][0]; c0.y += acc[i][1]; c0.z += acc[i][2]; c0.w += acc[i][3];
        c1.x += acc[i][4]; c1.y += acc[i][5]; c1.z += acc[i][6]; c1.w += acc[i][7];
        *reinterpret_cast<float4*>(op)     = c0;
        *reinterpret_cast<float4*>(op + 4) = c1;
    }
}

// ---------------------------------------------------------------------------
// RMSNorm + SiLU gating
// ---------------------------------------------------------------------------
__global__ __launch_bounds__(256) void norm_gate_kernel(
    const float* __restrict__ o, const float* __restrict__ gaux,
    const float* __restrict__ rms_w, float* __restrict__ y)
{
    const int row = blockIdx.x;
    const int tid = threadIdx.x;
    const size_t base = (size_t)row * VDIM + tid * 4;

    const float4 ov = *reinterpret_cast<const float4*>(o + base);
    float ss = ov.x * ov.x + ov.y * ov.y + ov.z * ov.z + ov.w * ov.w;
#pragma unroll
    for (int off = 16; off; off >>= 1)
        ss += __shfl_xor_sync(0xffffffffu, ss, off);

    __shared__ float ws[8];
    const int warp = tid >> 5, lane = tid & 31;
    if (lane == 0) ws[warp] = ss;
    __syncthreads();

    const int hw = (tid >> 6) << 1;
    const float tot = ws[hw] + ws[hw + 1];
    const float scale = rsqrtf(tot * (1.f / 256.f) + 1e-5f);

    const float4 gv = *reinterpret_cast<const float4*>(gaux + base);
    const int dv = (tid * 4) & 255;
    const float w0 = rms_w[dv + 0], w1 = rms_w[dv + 1], w2 = rms_w[dv + 2], w3 = rms_w[dv + 3];

    float4 r;
    r.x = ov.x * scale * w0 * (gv.x / (1.f + expf(-gv.x)));
    r.y = ov.y * scale * w1 * (gv.y / (1.f + expf(-gv.y)));
    r.z = ov.z * scale * w2 * (gv.z / (1.f + expf(-gv.z)));
    r.w = ov.w * scale * w3 * (gv.w / (1.f + expf(-gv.w)));
    *reinterpret_cast<float4*>(y + base) = r;
}

// ---------------------------------------------------------------------------
extern "C" void kernel_launch(void* const* d_in, const int* in_sizes, int n_in,
                              void* d_out, int out_size)
{
    const float* x    = (const float*)d_in[0];
    const float* Wq   = (const float*)d_in[1];
    const float* Wk   = (const float*)d_in[2];
    const float* Wv   = (const float*)d_in[3];
    const float* Wg   = (const float*)d_in[4];
    const float* Wgk1 = (const float*)d_in[5];
    const float* Wgk2 = (const float*)d_in[6];
    const float* bgk2 = (const float*)d_in[7];
    const float* Wout = (const float*)d_in[8];
    const float* rmsw = (const float*)d_in[9];
    float* out = (float*)d_out;

    float* scratch = nullptr;
    cudaGetSymbolAddress((void**)&scratch, g_scratch);
    float* Ag   = scratch + OFF_AG;
    float* v    = scratch + OFF_V;
    float* ga   = scratch + OFF_GA;
    float* t16  = scratch + OFF_T16;
    float* o    = scratch + OFF_O;
    float* y    = scratch + OFF_Y;
    float* qhb  = scratch + OFF_QH;
    float* khb  = scratch + OFF_KH;
    float* Ub   = scratch + OFF_U;
    float* Db   = scratch + OFF_D;
    float* Sb   = scratch + OFF_S;

    // gate path (x only)
    proj_lr_kernel<<<MROWS, 128>>>(x, Wgk1, t16);
    gate_cum_kernel<<<dim3(NCHUNK, BB * HH), 256>>>(t16, Wgk2, bgk2, Ag, Db);

    // fused projections with gate scaling in epilogue (q->qh, k->kh)
    proj_gemm_kernel<<<dim3(VDIM / 128, MROWS / 128, 4), 256>>>(
        x, Wq, Wk, Wv, Wg, qhb, khb, v, ga, Ag);

    // chunked GLA
    intra_kernel<<<TOTCHUNK * 2, 256>>>(qhb, khb, v, o);
    u_gemm_kernel<<<dim3(2, TOTCHUNK), 256>>>(khb, v, Db, Ub);
    state_scan_kernel<<<dim3(32, BB * HH), 256>>>(Ub, Db, Sb);
    inter2_kernel<<<dim3(2, BB * HH * (NCHUNK - 1)), 256>>>(qhb, Sb, o);

    // epilogue
    norm_gate_kernel<<<MROWS, 256>>>(o, ga, rmsw, y);
    out_gemm_kernel<<<dim3(VDIM / 128, MROWS / 128), 256>>>(y, Wout, out);
}

// round 7
// speedup vs baseline: 4.2469x; 1.0025x over previous
#include <cuda_runtime.h>
#include <cstdint>
#include <cstddef>

// Problem constants
#define BB 2
#define NN 1024
#define DD 1024
#define HH 4
#define KDIM 512
#define VDIM 1024
#define DK 128
#define DV 256
#define MROWS (BB*NN)
#define CHUNK 64
#define NCHUNK (NN/CHUNK)          // 16
#define TOTCHUNK (BB*HH*NCHUNK)    // 128

// Scratch layout (floats)
#define OFF_AG  0
#define OFF_V   2097152
#define OFF_GA  4194304
#define OFF_T16 6291456
#define OFF_O   6324224
#define OFF_Y   8421376
#define OFF_QH  10518528
#define OFF_KH  11567104
#define OFF_U   12615680
#define OFF_D   16809984
#define OFF_S   16826368
#define SCRATCH_TOTAL 21020672

__device__ float g_scratch[SCRATCH_TOTAL];

// ---------------------------------------------------------------------------
// TF32 helpers
// ---------------------------------------------------------------------------
__device__ __forceinline__ uint32_t f2tf32(float x) {
    uint32_t r;
    asm("cvt.rna.tf32.f32 %0, %1;" : "=r"(r) : "f"(x));
    return r;
}

__device__ __forceinline__ void mma_tf32(
    float* c, uint32_t a0, uint32_t a1, uint32_t a2, uint32_t a3,
    uint32_t b0, uint32_t b1)
{
    asm volatile(
        "mma.sync.aligned.m16n8k8.row.col.f32.tf32.tf32.f32 "
        "{%0,%1,%2,%3}, {%4,%5,%6,%7}, {%8,%9}, {%0,%1,%2,%3};"
        : "+f"(c[0]), "+f"(c[1]), "+f"(c[2]), "+f"(c[3])
        : "r"(a0), "r"(a1), "r"(a2), "r"(a3), "r"(b0), "r"(b1));
}

// ---------------------------------------------------------------------------
// TF32 tensor-core GEMM body: C = A[MxK] @ B[KxN], 128x128x16 tiles,
// 256 threads = 8 warps (2M x 4N). Optional gate: C *= exp(sgn * gA[r][c]).
// ---------------------------------------------------------------------------
__device__ __forceinline__ void tf32_gemm_body(
    int N, int K,
    const float* __restrict__ A, const float* __restrict__ B, float* __restrict__ C,
    int bx, int by, const float* __restrict__ gA, float sgn)
{
    constexpr int BM = 128, BN = 128, BK = 16, LDA = 132;
    __shared__ uint32_t As[2][BK][LDA];
    __shared__ uint32_t Bs[2][BK][LDA];

    const int tid = threadIdx.x;
    const int lane = tid & 31, wid = tid >> 5;
    const int warpM = wid >> 2, warpN = wid & 3;
    const int lg = lane >> 2, lt = lane & 3;

    const float* Ab = A + (size_t)by * BM * K;
    const float* Bb = B + (size_t)bx * BN;

    const int ar = tid >> 2, ac = (tid & 3) * 4;
    const int br = tid >> 5, bc = (tid & 31) * 4;

    float acc[4][4][4];
#pragma unroll
    for (int mt = 0; mt < 4; mt++)
#pragma unroll
        for (int nt = 0; nt < 4; nt++)
#pragma unroll
            for (int i = 0; i < 4; i++) acc[mt][nt][i] = 0.f;

    float4 a40, a41, b40, b41;
    a40 = *reinterpret_cast<const float4*>(Ab + (size_t)ar * K + ac);
    a41 = *reinterpret_cast<const float4*>(Ab + (size_t)(ar + 64) * K + ac);
    b40 = *reinterpret_cast<const float4*>(Bb + (size_t)br * N + bc);
    b41 = *reinterpret_cast<const float4*>(Bb + (size_t)(br + 8) * N + bc);

    {
        As[0][ac + 0][ar] = f2tf32(a40.x); As[0][ac + 1][ar] = f2tf32(a40.y);
        As[0][ac + 2][ar] = f2tf32(a40.z); As[0][ac + 3][ar] = f2tf32(a40.w);
        As[0][ac + 0][ar + 64] = f2tf32(a41.x); As[0][ac + 1][ar + 64] = f2tf32(a41.y);
        As[0][ac + 2][ar + 64] = f2tf32(a41.z); As[0][ac + 3][ar + 64] = f2tf32(a41.w);
        uint4 u0 = make_uint4(f2tf32(b40.x), f2tf32(b40.y), f2tf32(b40.z), f2tf32(b40.w));
        uint4 u1 = make_uint4(f2tf32(b41.x), f2tf32(b41.y), f2tf32(b41.z), f2tf32(b41.w));
        *reinterpret_cast<uint4*>(&Bs[0][br][bc]) = u0;
        *reinterpret_cast<uint4*>(&Bs[0][br + 8][bc]) = u1;
    }
    __syncthreads();

    int buf = 0;
    for (int k0 = BK; k0 < K; k0 += BK) {
        a40 = *reinterpret_cast<const float4*>(Ab + (size_t)ar * K + k0 + ac);
        a41 = *reinterpret_cast<const float4*>(Ab + (size_t)(ar + 64) * K + k0 + ac);
        b40 = *reinterpret_cast<const float4*>(Bb + (size_t)(k0 + br) * N + bc);
        b41 = *reinterpret_cast<const float4*>(Bb + (size_t)(k0 + br + 8) * N + bc);

#pragma unroll
        for (int ks = 0; ks < 2; ks++) {
            const int kk = ks * 8;
            uint32_t bf[4][2];
#pragma unroll
            for (int nt = 0; nt < 4; nt++) {
                const int n0 = warpN * 32 + nt * 8 + lg;
                bf[nt][0] = Bs[buf][kk + lt][n0];
                bf[nt][1] = Bs[buf][kk + lt + 4][n0];
            }
#pragma unroll
            for (int mt = 0; mt < 4; mt++) {
                const int m0 = warpM * 64 + mt * 16 + lg;
                const uint32_t A0 = As[buf][kk + lt][m0];
                const uint32_t A1 = As[buf][kk + lt][m0 + 8];
                const uint32_t A2 = As[buf][kk + lt + 4][m0];
                const uint32_t A3 = As[buf][kk + lt + 4][m0 + 8];
#pragma unroll
                for (int nt = 0; nt < 4; nt++)
                    mma_tf32(acc[mt][nt], A0, A1, A2, A3, bf[nt][0], bf[nt][1]);
            }
        }

        const int nb = buf ^ 1;
        As[nb][ac + 0][ar] = f2tf32(a40.x); As[nb][ac + 1][ar] = f2tf32(a40.y);
        As[nb][ac + 2][ar] = f2tf32(a40.z); As[nb][ac + 3][ar] = f2tf32(a40.w);
        As[nb][ac + 0][ar + 64] = f2tf32(a41.x); As[nb][ac + 1][ar + 64] = f2tf32(a41.y);
        As[nb][ac + 2][ar + 64] = f2tf32(a41.z); As[nb][ac + 3][ar + 64] = f2tf32(a41.w);
        uint4 u0 = make_uint4(f2tf32(b40.x), f2tf32(b40.y), f2tf32(b40.z), f2tf32(b40.w));
        uint4 u1 = make_uint4(f2tf32(b41.x), f2tf32(b41.y), f2tf32(b41.z), f2tf32(b41.w));
        *reinterpret_cast<uint4*>(&Bs[nb][br][bc]) = u0;
        *reinterpret_cast<uint4*>(&Bs[nb][br + 8][bc]) = u1;
        __syncthreads();
        buf = nb;
    }

#pragma unroll
    for (int ks = 0; ks < 2; ks++) {
        const int kk = ks * 8;
        uint32_t bf[4][2];
#pragma unroll
        for (int nt = 0; nt < 4; nt++) {
            const int n0 = warpN * 32 + nt * 8 + lg;
            bf[nt][0] = Bs[buf][kk + lt][n0];
            bf[nt][1] = Bs[buf][kk + lt + 4][n0];
        }
#pragma unroll
        for (int mt = 0; mt < 4; mt++) {
            const int m0 = warpM * 64 + mt * 16 + lg;
            const uint32_t A0 = As[buf][kk + lt][m0];
            const uint32_t A1 = As[buf][kk + lt][m0 + 8];
            const uint32_t A2 = As[buf][kk + lt + 4][m0];
            const uint32_t A3 = As[buf][kk + lt + 4][m0 + 8];
#pragma unroll
            for (int nt = 0; nt < 4; nt++)
                mma_tf32(acc[mt][nt], A0, A1, A2, A3, bf[nt][0], bf[nt][1]);
        }
    }

    float* Cb = C + (size_t)by * BM * N + (size_t)bx * BN;
    if (gA) {
        const float* gb = gA + (size_t)by * BM * N + (size_t)bx * BN;
#pragma unroll
        for (int mt = 0; mt < 4; mt++) {
            const int r = warpM * 64 + mt * 16 + lg;
#pragma unroll
            for (int nt = 0; nt < 4; nt++) {
                const int c = warpN * 32 + nt * 8 + 2 * lt;
                float2 e0 = *reinterpret_cast<const float2*>(gb + (size_t)r * N + c);
                float2 e1 = *reinterpret_cast<const float2*>(gb + (size_t)(r + 8) * N + c);
                *reinterpret_cast<float2*>(Cb + (size_t)r * N + c) =
                    make_float2(acc[mt][nt][0] * __expf(sgn * e0.x),
                                acc[mt][nt][1] * __expf(sgn * e0.y));
                *reinterpret_cast<float2*>(Cb + (size_t)(r + 8) * N + c) =
                    make_float2(acc[mt][nt][2] * __expf(sgn * e1.x),
                                acc[mt][nt][3] * __expf(sgn * e1.y));
            }
        }
    } else {
#pragma unroll
        for (int mt = 0; mt < 4; mt++) {
            const int r = warpM * 64 + mt * 16 + lg;
#pragma unroll
            for (int nt = 0; nt < 4; nt++) {
                const int c = warpN * 32 + nt * 8 + 2 * lt;
                *reinterpret_cast<float2*>(Cb + (size_t)r * N + c) =
                    make_float2(acc[mt][nt][0], acc[mt][nt][1]);
                *reinterpret_cast<float2*>(Cb + (size_t)(r + 8) * N + c) =
                    make_float2(acc[mt][nt][2], acc[mt][nt][3]);
            }
        }
    }
}

// Fused projections: z=0 -> qh (gate e^{+A}), z=1 -> kh (gate e^{-A}),
// z=2 -> v, z=3 -> gaux.
__global__ __launch_bounds__(256) void proj_gemm_kernel(
    const float* __restrict__ x,
    const float* __restrict__ Bq, const float* __restrict__ Bk,
    const float* __restrict__ Bv, const float* __restrict__ Bg,
    float* __restrict__ Cq, float* __restrict__ Ck,
    float* __restrict__ Cv, float* __restrict__ Cg,
    const float* __restrict__ Ag)
{
    const int z = blockIdx.z;
    const int N = (z < 2) ? KDIM : VDIM;
    if ((int)blockIdx.x * 128 >= N) return;
    const float* B = (z == 0) ? Bq : (z == 1) ? Bk : (z == 2) ? Bv : Bg;
    float*       C = (z == 0) ? Cq : (z == 1) ? Ck : (z == 2) ? Cv : Cg;
    const float* gA = (z < 2) ? Ag : nullptr;
    const float sgn = (z == 0) ? 1.f : -1.f;
    tf32_gemm_body(N, DD, x, B, C, blockIdx.x, blockIdx.y, gA, sgn);
}

__global__ __launch_bounds__(256) void out_gemm_kernel(
    const float* __restrict__ A, const float* __restrict__ B, float* __restrict__ C)
{
    tf32_gemm_body(DD, VDIM, A, B, C, blockIdx.x, blockIdx.y, nullptr, 0.f);
}

// ---------------------------------------------------------------------------
// Low-rank projection t16 = x @ Wgk1
// ---------------------------------------------------------------------------
__global__ __launch_bounds__(128) void proj_lr_kernel(
    const float* __restrict__ x, const float* __restrict__ Wgk1, float* __restrict__ t16)
{
    __shared__ float sx[1024];
    __shared__ float part[8][16];
    const int row = blockIdx.x;
    const int tid = threadIdx.x;
    for (int i = tid; i < 1024; i += 128) sx[i] = x[(size_t)row * 1024 + i];
    __syncthreads();
    const int col = tid & 15;
    const int seg = tid >> 4;
    float p = 0.f;
#pragma unroll 8
    for (int j = 0; j < 128; j++) {
        int kidx = seg * 128 + j;
        p = fmaf(sx[kidx], Wgk1[(size_t)kidx * 16 + col], p);
    }
    part[seg][col] = p;
    __syncthreads();
    if (tid < 16) {
        float s = 0.f;
#pragma unroll
        for (int s8 = 0; s8 < 8; s8++) s += part[s8][tid];
        t16[(size_t)row * 16 + tid] = s;
    }
}

// ---------------------------------------------------------------------------
// Gate cumsum: A = cumsum_t(max(logsig(t16@Wgk2+b)/16,-3)) per chunk;
// D = exp(A at t=63). Grid (16 chunks, 8 bh) x 256 threads.
// ---------------------------------------------------------------------------
__global__ __launch_bounds__(256) void gate_cum_kernel(
    const float* __restrict__ t16, const float* __restrict__ Wgk2,
    const float* __restrict__ bgk2,
    float* __restrict__ Ag, float* __restrict__ D)
{
    __shared__ float st[64][16];
    __shared__ float sg[64 * 128];

    const int c = blockIdx.x, bh = blockIdx.y;
    const int b = bh >> 2, h = bh & 3;
    const int tid = threadIdx.x;

    {
        const float* tp = t16 + (size_t)(b * NN + c * CHUNK) * 16;
        for (int i = tid; i < 1024; i += 256)
            (&st[0][0])[i] = tp[i];
    }
    __syncthreads();

    for (int i = tid; i < CHUNK * DK; i += 256) {
        const int t = i >> 7, d = i & 127;
        float z = bgk2[h * DK + d];
#pragma unroll
        for (int r = 0; r < 16; r++)
            z = fmaf(st[t][r], Wgk2[(size_t)r * KDIM + h * DK + d], z);
        // log-sigmoid(z) = min(z,0) - log(1 + exp(-|z|))
        float ls = fminf(z, 0.f) - __logf(1.f + __expf(-fabsf(z)));
        sg[i] = fmaxf(ls * 0.0625f, -3.f);
    }
    __syncthreads();

    // two-level cumsum: halves of 32 per d, then offset fix
    {
        const int d = tid & 127, hl = tid >> 7;
        const int t0 = hl * 32;
#pragma unroll 4
        for (int t = t0 + 1; t < t0 + 32; t++)
            sg[t * 128 + d] += sg[(t - 1) * 128 + d];
    }
    __syncthreads();
    {
        const int d = tid & 127, hl = tid >> 7;
        if (hl == 1) {
            const float off = sg[31 * 128 + d];
#pragma unroll 4
            for (int t = 32; t < 64; t++)
                sg[t * 128 + d] += off;
        }
    }
    __syncthreads();

    const size_t gbase = ((size_t)(b * NN + c * CHUNK)) * KDIM + h * DK;
    for (int i = tid; i < CHUNK * DK; i += 256) {
        const int t = i >> 7, d = i & 127;
        Ag[gbase + (size_t)t * KDIM + d] = sg[i];
    }
    if (tid < 128)
        D[(bh * NCHUNK + c) * DK + tid] = __expf(sg[63 * 128 + tid]);
}

// ---------------------------------------------------------------------------
// Fused intra-chunk + U: per (chunk-instance, vhalf):
//   A = tril(Qhat Khat^T); O_half = A @ V_half; U_half = (Khat*D)^T @ V_half.
// Grid 256 CTAs x 256 threads.
// ---------------------------------------------------------------------------
__global__ __launch_bounds__(256) void intra_u_kernel(
    const float* __restrict__ qh, const float* __restrict__ kh,
    const float* __restrict__ v, const float* __restrict__ D,
    float* __restrict__ o, float* __restrict__ U)
{
    __shared__ float sm[4160 + 64 * 132 + 64 * 68 + 128];
    float* sQ  = sm;            // [32][64] stage 1
    float* sK  = sm + 2048;     // [32][64]
    float* sA  = sm;            // [64][65] stage 2 (overlay)
    float* sV  = sm + 4160;     // [64][132]
    float* sKU = sm + 4160 + 8448;        // [64][68]
    float* sD  = sm + 4160 + 8448 + 4352; // [128]

    const int vhalf = blockIdx.x & 1;
    const int cta = blockIdx.x >> 1;
    const int bh = cta >> 4, c = cta & 15;
    const int b = bh >> 2, h = bh & 3;
    const int tid = threadIdx.x;
    const size_t rbase = ((size_t)(b * NN + c * CHUNK)) * KDIM + h * DK;
    const size_t vbase = ((size_t)(b * NN + c * CHUNK)) * VDIM + h * DV;

    if (tid < 128) sD[tid] = D[(bh * NCHUNK + c) * DK + tid];

    const int ty = tid >> 4, tx = tid & 15;
    const int lt = tid & 63, lg = tid >> 6;

    float acc[4][4];
#pragma unroll
    for (int i = 0; i < 4; i++)
#pragma unroll
        for (int j = 0; j < 4; j++) acc[i][j] = 0.f;

    for (int k0 = 0; k0 < DK; k0 += 32) {
        const float* qp = qh + rbase + (size_t)lt * KDIM + k0 + lg * 8;
        const float* kp = kh + rbase + (size_t)lt * KDIM + k0 + lg * 8;
        float4 q0 = *reinterpret_cast<const float4*>(qp);
        float4 q1 = *reinterpret_cast<const float4*>(qp + 4);
        float4 kk0 = *reinterpret_cast<const float4*>(kp);
        float4 kk1 = *reinterpret_cast<const float4*>(kp + 4);
        sQ[(lg * 8 + 0) * 64 + lt] = q0.x; sQ[(lg * 8 + 1) * 64 + lt] = q0.y;
        sQ[(lg * 8 + 2) * 64 + lt] = q0.z; sQ[(lg * 8 + 3) * 64 + lt] = q0.w;
        sQ[(lg * 8 + 4) * 64 + lt] = q1.x; sQ[(lg * 8 + 5) * 64 + lt] = q1.y;
        sQ[(lg * 8 + 6) * 64 + lt] = q1.z; sQ[(lg * 8 + 7) * 64 + lt] = q1.w;
        sK[(lg * 8 + 0) * 64 + lt] = kk0.x; sK[(lg * 8 + 1) * 64 + lt] = kk0.y;
        sK[(lg * 8 + 2) * 64 + lt] = kk0.z; sK[(lg * 8 + 3) * 64 + lt] = kk0.w;
        sK[(lg * 8 + 4) * 64 + lt] = kk1.x; sK[(lg * 8 + 5) * 64 + lt] = kk1.y;
        sK[(lg * 8 + 6) * 64 + lt] = kk1.z; sK[(lg * 8 + 7) * 64 + lt] = kk1.w;
        __syncthreads();
#pragma unroll
        for (int dd = 0; dd < 32; dd++) {
            float4 a4 = *reinterpret_cast<const float4*>(&sQ[dd * 64 + ty * 4]);
            float4 b4 = *reinterpret_cast<const float4*>(&sK[dd * 64 + tx * 4]);
            const float ar[4] = {a4.x, a4.y, a4.z, a4.w};
            const float br[4] = {b4.x, b4.y, b4.z, b4.w};
#pragma unroll
            for (int i = 0; i < 4; i++)
#pragma unroll
                for (int j = 0; j < 4; j++)
                    acc[i][j] = fmaf(ar[i], br[j], acc[i][j]);
        }
        __syncthreads();
    }

#pragma unroll
    for (int i = 0; i < 4; i++)
#pragma unroll
        for (int j = 0; j < 4; j++) {
            const int t = ty * 4 + i, s = tx * 4 + j;
            sA[t * 65 + s] = (s <= t) ? acc[i][j] : 0.f;
        }

    // load V half (can't overlap sA region)
    for (int i = tid; i < 2048; i += 256) {
        const int s = i >> 5, c4 = (i & 31) * 4;
        *reinterpret_cast<float4*>(&sV[s * 132 + c4]) =
            *reinterpret_cast<const float4*>(v + vbase + (size_t)s * VDIM + vhalf * 128 + c4);
    }
    __syncthreads();

    // stage 2: O = A @ Vhalf
    const int t2r = tid >> 4;
    const int t2c = tid & 15;
    {
        float a2[4][8];
#pragma unroll
        for (int i = 0; i < 4; i++)
#pragma unroll
            for (int j = 0; j < 8; j++) a2[i][j] = 0.f;

#pragma unroll 4
        for (int s = 0; s < CHUNK; s++) {
            float ar[4];
#pragma unroll
            for (int i = 0; i < 4; i++) ar[i] = sA[(t2r * 4 + i) * 65 + s];
            float4 b0 = *reinterpret_cast<const float4*>(&sV[s * 132 + t2c * 8]);
            float4 b1 = *reinterpret_cast<const float4*>(&sV[s * 132 + t2c * 8 + 4]);
            const float br[8] = {b0.x, b0.y, b0.z, b0.w, b1.x, b1.y, b1.z, b1.w};
#pragma unroll
            for (int i = 0; i < 4; i++)
#pragma unroll
                for (int j = 0; j < 8; j++)
                    a2[i][j] = fmaf(ar[i], br[j], a2[i][j]);
        }

#pragma unroll
        for (int i = 0; i < 4; i++) {
            float* op = o + vbase + (size_t)(t2r * 4 + i) * VDIM + vhalf * 128 + t2c * 8;
            *reinterpret_cast<float4*>(op) =
                make_float4(a2[i][0], a2[i][1], a2[i][2], a2[i][3]);
            *reinterpret_cast<float4*>(op + 4) =
                make_float4(a2[i][4], a2[i][5], a2[i][6], a2[i][7]);
        }
    }

    // U phase: U[d, vhalf*128 + j] = sum_t kh[t][d]*D[d]*v[t][j], d in 2 slices
    float* Ub = U + ((size_t)(bh * NCHUNK + c) * DK) * DV + vhalf * 128;
    const int ut = tid >> 2;            // 0..63 (row t)
    const int ud = (tid & 3) * 16;      // 0,16,32,48 (d' group)
#pragma unroll
    for (int ks = 0; ks < 2; ks++) {
        __syncthreads();   // protect sKU from previous iteration's readers
        {
            const float* kp = kh + rbase + (size_t)ut * KDIM + ks * 64 + ud;
#pragma unroll
            for (int m = 0; m < 16; m += 4) {
                float4 kv = *reinterpret_cast<const float4*>(kp + m);
                kv.x *= sD[ks * 64 + ud + m + 0];
                kv.y *= sD[ks * 64 + ud + m + 1];
                kv.z *= sD[ks * 64 + ud + m + 2];
                kv.w *= sD[ks * 64 + ud + m + 3];
                *reinterpret_cast<float4*>(&sKU[ut * 68 + ud + m]) = kv;
            }
        }
        __syncthreads();

        float ua[4][8];
#pragma unroll
        for (int i = 0; i < 4; i++)
#pragma unroll
            for (int j = 0; j < 8; j++) ua[i][j] = 0.f;

#pragma unroll 4
        for (int s = 0; s < CHUNK; s++) {
            float4 a4 = *reinterpret_cast<const float4*>(&sKU[s * 68 + t2r * 4]);
            float4 b0 = *reinterpret_cast<const float4*>(&sV[s * 132 + t2c * 8]);
            float4 b1 = *reinterpret_cast<const float4*>(&sV[s * 132 + t2c * 8 + 4]);
            const float ar[4] = {a4.x, a4.y, a4.z, a4.w};
            const float br[8] = {b0.x, b0.y, b0.z, b0.w, b1.x, b1.y, b1.z, b1.w};
#pragma unroll
            for (int i = 0; i < 4; i++)
#pragma unroll
                for (int j = 0; j < 8; j++)
                    ua[i][j] = fmaf(ar[i], br[j], ua[i][j]);
        }

#pragma unroll
        for (int i = 0; i < 4; i++) {
            float* up = Ub + (size_t)(ks * 64 + t2r * 4 + i) * DV + t2c * 8;
            *reinterpret_cast<float4*>(up) =
                make_float4(ua[i][0], ua[i][1], ua[i][2], ua[i][3]);
            *reinterpret_cast<float4*>(up + 4) =
                make_float4(ua[i][4], ua[i][5], ua[i][6], ua[i][7]);
        }
    }
}

// ---------------------------------------------------------------------------
// Elementwise chunk-state scan
// ---------------------------------------------------------------------------
__global__ __launch_bounds__(256) void state_scan_kernel(
    const float* __restrict__ U, const float* __restrict__ D, float* __restrict__ S)
{
    const int bh = blockIdx.y;
    const int e = blockIdx.x * 256 + threadIdx.x;
    const int d = e >> 6;
    const int vq = (e & 63) * 4;

    float4 s = make_float4(0.f, 0.f, 0.f, 0.f);
#pragma unroll
    for (int c = 0; c < NCHUNK; c++) {
        const size_t base = ((size_t)((bh * NCHUNK + c) * DK) + d) * DV + vq;
        if (c > 0)
            *reinterpret_cast<float4*>(S + base) = s;
        const float dc = D[(bh * NCHUNK + c) * DK + d];
        const float4 u = *reinterpret_cast<const float4*>(U + base);
        s.x = fmaf(s.x, dc, u.x);
        s.y = fmaf(s.y, dc, u.y);
        s.z = fmaf(s.z, dc, u.z);
        s.w = fmaf(s.w, dc, u.w);
    }
}

// ---------------------------------------------------------------------------
// Inter-chunk output: O_c += Qhat_c @ Sstart_c
// ---------------------------------------------------------------------------
__global__ __launch_bounds__(256) void inter2_kernel(
    const float* __restrict__ qh, const float* __restrict__ S, float* __restrict__ o)
{
    __shared__ float sQ[16 * 68];
    __shared__ float sS[16 * 132];

    const int vhalf = blockIdx.x;
    const int j = blockIdx.y;
    const int bh = j / 15;
    const int c = j % 15 + 1;
    const int b = bh >> 2, h = bh & 3;
    const int tid = threadIdx.x;

    const size_t qbase = ((size_t)(b * NN + c * CHUNK)) * KDIM + h * DK;
    const size_t Sbase = ((size_t)((bh * NCHUNK + c) * DK)) * DV + vhalf * 128;
    const size_t obase = ((size_t)(b * NN + c * CHUNK)) * VDIM + h * DV + vhalf * 128;

    const int trow = tid >> 4, tcol = tid & 15;
    const int qt = tid >> 2;
    const int qk = (tid & 3) * 4;
    const int sr = tid >> 5;
    const int sc = (tid & 31) * 4;

    float acc[4][8];
#pragma unroll
    for (int i = 0; i < 4; i++)
#pragma unroll
        for (int j2 = 0; j2 < 8; j2++) acc[i][j2] = 0.f;

    for (int k0 = 0; k0 < DK; k0 += 16) {
        float4 qv = *reinterpret_cast<const float4*>(qh + qbase + (size_t)qt * KDIM + k0 + qk);
        sQ[(qk + 0) * 68 + qt] = qv.x;
        sQ[(qk + 1) * 68 + qt] = qv.y;
        sQ[(qk + 2) * 68 + qt] = qv.z;
        sQ[(qk + 3) * 68 + qt] = qv.w;
        *reinterpret_cast<float4*>(&sS[sr * 132 + sc]) =
            *reinterpret_cast<const float4*>(S + Sbase + (size_t)(k0 + sr) * DV + sc);
        *reinterpret_cast<float4*>(&sS[(sr + 8) * 132 + sc]) =
            *reinterpret_cast<const float4*>(S + Sbase + (size_t)(k0 + sr + 8) * DV + sc);
        __syncthreads();

#pragma unroll
        for (int kk = 0; kk < 16; kk++) {
            float4 a4 = *reinterpret_cast<const float4*>(&sQ[kk * 68 + trow * 4]);
            float4 b0 = *reinterpret_cast<const float4*>(&sS[kk * 132 + tcol * 8]);
            float4 b1 = *reinterpret_cast<const float4*>(&sS[kk * 132 + tcol * 8 + 4]);
            const float ar[4] = {a4.x, a4.y, a4.z, a4.w};
            const float br[8] = {b0.x, b0.y, b0.z, b0.w, b1.x, b1.y, b1.z, b1.w};
#pragma unroll
            for (int i = 0; i < 4; i++)
#pragma unroll
                for (int j2 = 0; j2 < 8; j2++)
                    acc[i][j2] = fmaf(ar[i], br[j2], acc[i][j2]);
        }
        __syncthreads();
    }

#pragma unroll
    for (int i = 0; i < 4; i++) {
        float* op = o + obase + (size_t)(trow * 4 + i) * VDIM + tcol * 8;
        float4 c0 = *reinterpret_cast<const float4*>(op);
        float4 c1 = *reinterpret_cast<const float4*>(op + 4);
        c0.x += acc[i][0]; c0.y += acc[i][1]; c0.z += acc[i][2]; c0.w += acc[i][3];
        c1.x += acc[i][4]; c1.y += acc[i][5]; c1.z += acc[i][6]; c1.w += acc[i][7];
        *reinterpret_cast<float4*>(op)     = c0;
        *reinterpret_cast<float4*>(op + 4) = c1;
    }
}

// ---------------------------------------------------------------------------
// RMSNorm + SiLU gating
// ---------------------------------------------------------------------------
__global__ __launch_bounds__(256) void norm_gate_kernel(
    const float* __restrict__ o, const float* __restrict__ gaux,
    const float* __restrict__ rms_w, float* __restrict__ y)
{
    const int row = blockIdx.x;
    const int tid = threadIdx.x;
    const size_t base = (size_t)row * VDIM + tid * 4;

    const float4 ov = *reinterpret_cast<const float4*>(o + base);
    float ss = ov.x * ov.x + ov.y * ov.y + ov.z * ov.z + ov.w * ov.w;
#pragma unroll
    for (int off = 16; off; off >>= 1)
        ss += __shfl_xor_sync(0xffffffffu, ss, off);

    __shared__ float ws[8];
    const int warp = tid >> 5, lane = tid & 31;
    if (lane == 0) ws[warp] = ss;
    __syncthreads();

    const int hw = (tid >> 6) << 1;
    const float tot = ws[hw] + ws[hw + 1];
    const float scale = rsqrtf(tot * (1.f / 256.f) + 1e-5f);

    const float4 gv = *reinterpret_cast<const float4*>(gaux + base);
    const int dv = (tid * 4) & 255;
    const float w0 = rms_w[dv + 0], w1 = rms_w[dv + 1], w2 = rms_w[dv + 2], w3 = rms_w[dv + 3];

    float4 r;
    r.x = ov.x * scale * w0 * (gv.x / (1.f + __expf(-gv.x)));
    r.y = ov.y * scale * w1 * (gv.y / (1.f + __expf(-gv.y)));
    r.z = ov.z * scale * w2 * (gv.z / (1.f + __expf(-gv.z)));
    r.w = ov.w * scale * w3 * (gv.w / (1.f + __expf(-gv.w)));
    *reinterpret_cast<float4*>(y + base) = r;
}

// ---------------------------------------------------------------------------
extern "C" void kernel_launch(void* const* d_in, const int* in_sizes, int n_in,
                              void* d_out, int out_size)
{
    const float* x    = (const float*)d_in[0];
    const float* Wq   = (const float*)d_in[1];
    const float* Wk   = (const float*)d_in[2];
    const float* Wv   = (const float*)d_in[3];
    const float* Wg   = (const float*)d_in[4];
    const float* Wgk1 = (const float*)d_in[5];
    const float* Wgk2 = (const float*)d_in[6];
    const float* bgk2 = (const float*)d_in[7];
    const float* Wout = (const float*)d_in[8];
    const float* rmsw = (const float*)d_in[9];
    float* out = (float*)d_out;

    float* scratch = nullptr;
    cudaGetSymbolAddress((void**)&scratch, g_scratch);
    float* Ag   = scratch + OFF_AG;
    float* v    = scratch + OFF_V;
    float* ga   = scratch + OFF_GA;
    float* t16  = scratch + OFF_T16;
    float* o    = scratch + OFF_O;
    float* y    = scratch + OFF_Y;
    float* qhb  = scratch + OFF_QH;
    float* khb  = scratch + OFF_KH;
    float* Ub   = scratch + OFF_U;
    float* Db   = scratch + OFF_D;
    float* Sb   = scratch + OFF_S;

    // gate path (x only)
    proj_lr_kernel<<<MROWS, 128>>>(x, Wgk1, t16);
    gate_cum_kernel<<<dim3(NCHUNK, BB * HH), 256>>>(t16, Wgk2, bgk2, Ag, Db);

    // fused projections with gate scaling in epilogue (q->qh, k->kh)
    proj_gemm_kernel<<<dim3(VDIM / 128, MROWS / 128, 4), 256>>>(
        x, Wq, Wk, Wv, Wg, qhb, khb, v, ga, Ag);

    // chunked GLA: fused intra + U, then scan, then inter
    intra_u_kernel<<<TOTCHUNK * 2, 256>>>(qhb, khb, v, Db, o, Ub);
    state_scan_kernel<<<dim3(32, BB * HH), 256>>>(Ub, Db, Sb);
    inter2_kernel<<<dim3(2, BB * HH * (NCHUNK - 1)), 256>>>(qhb, Sb, o);

    // epilogue
    norm_gate_kernel<<<MROWS, 256>>>(o, ga, rmsw, y);
    out_gemm_kernel<<<dim3(VDIM / 128, MROWS / 128), 256>>>(y, Wout, out);
}

// round 8
// speedup vs baseline: 4.4934x; 1.0580x over previous
#include <cuda_runtime.h>
#include <cstdint>
#include <cstddef>

// Problem constants
#define BB 2
#define NN 1024
#define DD 1024
#define HH 4
#define KDIM 512
#define VDIM 1024
#define DK 128
#define DV 256
#define MROWS (BB*NN)
#define CHUNK 64
#define NCHUNK (NN/CHUNK)          // 16
#define TOTCHUNK (BB*HH*NCHUNK)    // 128

// Scratch layout (floats)
#define OFF_AG  0
#define OFF_V   2097152
#define OFF_GA  4194304
#define OFF_T16 6291456
#define OFF_O   6324224
#define OFF_Y   8421376
#define OFF_QH  10518528
#define OFF_KH  11567104
#define OFF_U   12615680
#define OFF_D   16809984
#define OFF_S   16826368
#define SCRATCH_TOTAL 21020672

__device__ float g_scratch[SCRATCH_TOTAL];

// ---------------------------------------------------------------------------
// TF32 helpers
// ---------------------------------------------------------------------------
__device__ __forceinline__ uint32_t f2tf32(float x) {
    uint32_t r;
    asm("cvt.rna.tf32.f32 %0, %1;" : "=r"(r) : "f"(x));
    return r;
}

__device__ __forceinline__ void mma_tf32(
    float* c, uint32_t a0, uint32_t a1, uint32_t a2, uint32_t a3,
    uint32_t b0, uint32_t b1)
{
    asm volatile(
        "mma.sync.aligned.m16n8k8.row.col.f32.tf32.tf32.f32 "
        "{%0,%1,%2,%3}, {%4,%5,%6,%7}, {%8,%9}, {%0,%1,%2,%3};"
        : "+f"(c[0]), "+f"(c[1]), "+f"(c[2]), "+f"(c[3])
        : "r"(a0), "r"(a1), "r"(a2), "r"(a3), "r"(b0), "r"(b1));
}

// Dekker-style fp32 -> tf32 hi/lo split (hi + lo ~ fp32 accurate)
__device__ __forceinline__ void split2(float x, uint32_t& hi, uint32_t& lo) {
    hi = f2tf32(x);
    lo = f2tf32(x - __uint_as_float(hi));
}

// 3-term split mma: acc += Ahi*Bhi + Ahi*Blo + Alo*Bhi
__device__ __forceinline__ void mma3(
    float* c, const uint32_t* Ah, const uint32_t* Al,
    uint32_t bh0, uint32_t bh1, uint32_t bl0, uint32_t bl1)
{
    mma_tf32(c, Ah[0], Ah[1], Ah[2], Ah[3], bh0, bh1);
    mma_tf32(c, Ah[0], Ah[1], Ah[2], Ah[3], bl0, bl1);
    mma_tf32(c, Al[0], Al[1], Al[2], Al[3], bh0, bh1);
}

// ---------------------------------------------------------------------------
// TF32 tensor-core GEMM body: C = A[MxK] @ B[KxN], 128x128x16 tiles,
// 256 threads = 8 warps (2M x 4N). Optional gate: C *= exp(sgn * gA[r][c]).
// ---------------------------------------------------------------------------
__device__ __forceinline__ void tf32_gemm_body(
    int N, int K,
    const float* __restrict__ A, const float* __restrict__ B, float* __restrict__ C,
    int bx, int by, const float* __restrict__ gA, float sgn)
{
    constexpr int BM = 128, BN = 128, BK = 16, LDA = 132;
    __shared__ uint32_t As[2][BK][LDA];
    __shared__ uint32_t Bs[2][BK][LDA];

    const int tid = threadIdx.x;
    const int lane = tid & 31, wid = tid >> 5;
    const int warpM = wid >> 2, warpN = wid & 3;
    const int lg = lane >> 2, lt = lane & 3;

    const float* Ab = A + (size_t)by * BM * K;
    const float* Bb = B + (size_t)bx * BN;

    const int ar = tid >> 2, ac = (tid & 3) * 4;
    const int br = tid >> 5, bc = (tid & 31) * 4;

    float acc[4][4][4];
#pragma unroll
    for (int mt = 0; mt < 4; mt++)
#pragma unroll
        for (int nt = 0; nt < 4; nt++)
#pragma unroll
            for (int i = 0; i < 4; i++) acc[mt][nt][i] = 0.f;

    float4 a40, a41, b40, b41;
    a40 = *reinterpret_cast<const float4*>(Ab + (size_t)ar * K + ac);
    a41 = *reinterpret_cast<const float4*>(Ab + (size_t)(ar + 64) * K + ac);
    b40 = *reinterpret_cast<const float4*>(Bb + (size_t)br * N + bc);
    b41 = *reinterpret_cast<const float4*>(Bb + (size_t)(br + 8) * N + bc);

    {
        As[0][ac + 0][ar] = f2tf32(a40.x); As[0][ac + 1][ar] = f2tf32(a40.y);
        As[0][ac + 2][ar] = f2tf32(a40.z); As[0][ac + 3][ar] = f2tf32(a40.w);
        As[0][ac + 0][ar + 64] = f2tf32(a41.x); As[0][ac + 1][ar + 64] = f2tf32(a41.y);
        As[0][ac + 2][ar + 64] = f2tf32(a41.z); As[0][ac + 3][ar + 64] = f2tf32(a41.w);
        uint4 u0 = make_uint4(f2tf32(b40.x), f2tf32(b40.y), f2tf32(b40.z), f2tf32(b40.w));
        uint4 u1 = make_uint4(f2tf32(b41.x), f2tf32(b41.y), f2tf32(b41.z), f2tf32(b41.w));
        *reinterpret_cast<uint4*>(&Bs[0][br][bc]) = u0;
        *reinterpret_cast<uint4*>(&Bs[0][br + 8][bc]) = u1;
    }
    __syncthreads();

    int buf = 0;
    for (int k0 = BK; k0 < K; k0 += BK) {
        a40 = *reinterpret_cast<const float4*>(Ab + (size_t)ar * K + k0 + ac);
        a41 = *reinterpret_cast<const float4*>(Ab + (size_t)(ar + 64) * K + k0 + ac);
        b40 = *reinterpret_cast<const float4*>(Bb + (size_t)(k0 + br) * N + bc);
        b41 = *reinterpret_cast<const float4*>(Bb + (size_t)(k0 + br + 8) * N + bc);

#pragma unroll
        for (int ks = 0; ks < 2; ks++) {
            const int kk = ks * 8;
            uint32_t bf[4][2];
#pragma unroll
            for (int nt = 0; nt < 4; nt++) {
                const int n0 = warpN * 32 + nt * 8 + lg;
                bf[nt][0] = Bs[buf][kk + lt][n0];
                bf[nt][1] = Bs[buf][kk + lt + 4][n0];
            }
#pragma unroll
            for (int mt = 0; mt < 4; mt++) {
                const int m0 = warpM * 64 + mt * 16 + lg;
                const uint32_t A0 = As[buf][kk + lt][m0];
                const uint32_t A1 = As[buf][kk + lt][m0 + 8];
                const uint32_t A2 = As[buf][kk + lt + 4][m0];
                const uint32_t A3 = As[buf][kk + lt + 4][m0 + 8];
#pragma unroll
                for (int nt = 0; nt < 4; nt++)
                    mma_tf32(acc[mt][nt], A0, A1, A2, A3, bf[nt][0], bf[nt][1]);
            }
        }

        const int nb = buf ^ 1;
        As[nb][ac + 0][ar] = f2tf32(a40.x); As[nb][ac + 1][ar] = f2tf32(a40.y);
        As[nb][ac + 2][ar] = f2tf32(a40.z); As[nb][ac + 3][ar] = f2tf32(a40.w);
        As[nb][ac + 0][ar + 64] = f2tf32(a41.x); As[nb][ac + 1][ar + 64] = f2tf32(a41.y);
        As[nb][ac + 2][ar + 64] = f2tf32(a41.z); As[nb][ac + 3][ar + 64] = f2tf32(a41.w);
        uint4 u0 = make_uint4(f2tf32(b40.x), f2tf32(b40.y), f2tf32(b40.z), f2tf32(b40.w));
        uint4 u1 = make_uint4(f2tf32(b41.x), f2tf32(b41.y), f2tf32(b41.z), f2tf32(b41.w));
        *reinterpret_cast<uint4*>(&Bs[nb][br][bc]) = u0;
        *reinterpret_cast<uint4*>(&Bs[nb][br + 8][bc]) = u1;
        __syncthreads();
        buf = nb;
    }

#pragma unroll
    for (int ks = 0; ks < 2; ks++) {
        const int kk = ks * 8;
        uint32_t bf[4][2];
#pragma unroll
        for (int nt = 0; nt < 4; nt++) {
            const int n0 = warpN * 32 + nt * 8 + lg;
            bf[nt][0] = Bs[buf][kk + lt][n0];
            bf[nt][1] = Bs[buf][kk + lt + 4][n0];
        }
#pragma unroll
        for (int mt = 0; mt < 4; mt++) {
            const int m0 = warpM * 64 + mt * 16 + lg;
            const uint32_t A0 = As[buf][kk + lt][m0];
            const uint32_t A1 = As[buf][kk + lt][m0 + 8];
            const uint32_t A2 = As[buf][kk + lt + 4][m0];
            const uint32_t A3 = As[buf][kk + lt + 4][m0 + 8];
#pragma unroll
            for (int nt = 0; nt < 4; nt++)
                mma_tf32(acc[mt][nt], A0, A1, A2, A3, bf[nt][0], bf[nt][1]);
        }
    }

    float* Cb = C + (size_t)by * BM * N + (size_t)bx * BN;
    if (gA) {
        const float* gb = gA + (size_t)by * BM * N + (size_t)bx * BN;
#pragma unroll
        for (int mt = 0; mt < 4; mt++) {
            const int r = warpM * 64 + mt * 16 + lg;
#pragma unroll
            for (int nt = 0; nt < 4; nt++) {
                const int c = warpN * 32 + nt * 8 + 2 * lt;
                float2 e0 = *reinterpret_cast<const float2*>(gb + (size_t)r * N + c);
                float2 e1 = *reinterpret_cast<const float2*>(gb + (size_t)(r + 8) * N + c);
                *reinterpret_cast<float2*>(Cb + (size_t)r * N + c) =
                    make_float2(acc[mt][nt][0] * __expf(sgn * e0.x),
                                acc[mt][nt][1] * __expf(sgn * e0.y));
                *reinterpret_cast<float2*>(Cb + (size_t)(r + 8) * N + c) =
                    make_float2(acc[mt][nt][2] * __expf(sgn * e1.x),
                                acc[mt][nt][3] * __expf(sgn * e1.y));
            }
        }
    } else {
#pragma unroll
        for (int mt = 0; mt < 4; mt++) {
            const int r = warpM * 64 + mt * 16 + lg;
#pragma unroll
            for (int nt = 0; nt < 4; nt++) {
                const int c = warpN * 32 + nt * 8 + 2 * lt;
                *reinterpret_cast<float2*>(Cb + (size_t)r * N + c) =
                    make_float2(acc[mt][nt][0], acc[mt][nt][1]);
                *reinterpret_cast<float2*>(Cb + (size_t)(r + 8) * N + c) =
                    make_float2(acc[mt][nt][2], acc[mt][nt][3]);
            }
        }
    }
}

// Fused projections: z=0 -> qh (gate e^{+A}), z=1 -> kh (gate e^{-A}),
// z=2 -> v, z=3 -> gaux.
__global__ __launch_bounds__(256) void proj_gemm_kernel(
    const float* __restrict__ x,
    const float* __restrict__ Bq, const float* __restrict__ Bk,
    const float* __restrict__ Bv, const float* __restrict__ Bg,
    float* __restrict__ Cq, float* __restrict__ Ck,
    float* __restrict__ Cv, float* __restrict__ Cg,
    const float* __restrict__ Ag)
{
    const int z = blockIdx.z;
    const int N = (z < 2) ? KDIM : VDIM;
    if ((int)blockIdx.x * 128 >= N) return;
    const float* B = (z == 0) ? Bq : (z == 1) ? Bk : (z == 2) ? Bv : Bg;
    float*       C = (z == 0) ? Cq : (z == 1) ? Ck : (z == 2) ? Cv : Cg;
    const float* gA = (z < 2) ? Ag : nullptr;
    const float sgn = (z == 0) ? 1.f : -1.f;
    tf32_gemm_body(N, DD, x, B, C, blockIdx.x, blockIdx.y, gA, sgn);
}

__global__ __launch_bounds__(256) void out_gemm_kernel(
    const float* __restrict__ A, const float* __restrict__ B, float* __restrict__ C)
{
    tf32_gemm_body(DD, VDIM, A, B, C, blockIdx.x, blockIdx.y, nullptr, 0.f);
}

// ---------------------------------------------------------------------------
// Low-rank projection t16 = x @ Wgk1
// ---------------------------------------------------------------------------
__global__ __launch_bounds__(128) void proj_lr_kernel(
    const float* __restrict__ x, const float* __restrict__ Wgk1, float* __restrict__ t16)
{
    __shared__ float sx[1024];
    __shared__ float part[8][16];
    const int row = blockIdx.x;
    const int tid = threadIdx.x;
    for (int i = tid; i < 1024; i += 128) sx[i] = x[(size_t)row * 1024 + i];
    __syncthreads();
    const int col = tid & 15;
    const int seg = tid >> 4;
    float p = 0.f;
#pragma unroll 8
    for (int j = 0; j < 128; j++) {
        int kidx = seg * 128 + j;
        p = fmaf(sx[kidx], Wgk1[(size_t)kidx * 16 + col], p);
    }
    part[seg][col] = p;
    __syncthreads();
    if (tid < 16) {
        float s = 0.f;
#pragma unroll
        for (int s8 = 0; s8 < 8; s8++) s += part[s8][tid];
        t16[(size_t)row * 16 + tid] = s;
    }
}

// ---------------------------------------------------------------------------
// Gate cumsum: A = cumsum_t(max(logsig(t16@Wgk2+b)/16,-3)) per chunk;
// D = exp(A at t=63). Grid (16 chunks, 8 bh) x 256 threads.
// ---------------------------------------------------------------------------
__global__ __launch_bounds__(256) void gate_cum_kernel(
    const float* __restrict__ t16, const float* __restrict__ Wgk2,
    const float* __restrict__ bgk2,
    float* __restrict__ Ag, float* __restrict__ D)
{
    __shared__ float st[64][16];
    __shared__ float sg[64 * 128];

    const int c = blockIdx.x, bh = blockIdx.y;
    const int b = bh >> 2, h = bh & 3;
    const int tid = threadIdx.x;

    {
        const float* tp = t16 + (size_t)(b * NN + c * CHUNK) * 16;
        for (int i = tid; i < 1024; i += 256)
            (&st[0][0])[i] = tp[i];
    }
    __syncthreads();

    for (int i = tid; i < CHUNK * DK; i += 256) {
        const int t = i >> 7, d = i & 127;
        float z = bgk2[h * DK + d];
#pragma unroll
        for (int r = 0; r < 16; r++)
            z = fmaf(st[t][r], Wgk2[(size_t)r * KDIM + h * DK + d], z);
        float ls = fminf(z, 0.f) - __logf(1.f + __expf(-fabsf(z)));
        sg[i] = fmaxf(ls * 0.0625f, -3.f);
    }
    __syncthreads();

    {
        const int d = tid & 127, hl = tid >> 7;
        const int t0 = hl * 32;
#pragma unroll 4
        for (int t = t0 + 1; t < t0 + 32; t++)
            sg[t * 128 + d] += sg[(t - 1) * 128 + d];
    }
    __syncthreads();
    {
        const int d = tid & 127, hl = tid >> 7;
        if (hl == 1) {
            const float off = sg[31 * 128 + d];
#pragma unroll 4
            for (int t = 32; t < 64; t++)
                sg[t * 128 + d] += off;
        }
    }
    __syncthreads();

    const size_t gbase = ((size_t)(b * NN + c * CHUNK)) * KDIM + h * DK;
    for (int i = tid; i < CHUNK * DK; i += 256) {
        const int t = i >> 7, d = i & 127;
        Ag[gbase + (size_t)t * KDIM + d] = sg[i];
    }
    if (tid < 128)
        D[(bh * NCHUNK + c) * DK + tid] = __expf(sg[63 * 128 + tid]);
}

// ---------------------------------------------------------------------------
// Fused intra-chunk + U via 3xTF32 split mma (fp32-accurate).
// Per CTA (chunk-instance, vhalf):
//   S = Qh Kh^T (64x64, k=128)  -> causal mask in regs -> sA
//   O = sA @ Vhalf (64x128, k=64)
//   U = (Kh*D)^T @ Vhalf (128x128, k=64)
// Grid 256 CTAs x 256 threads (8 warps).
// ---------------------------------------------------------------------------
__global__ __launch_bounds__(256) void intra_u_kernel(
    const float* __restrict__ qh, const float* __restrict__ kh,
    const float* __restrict__ v, const float* __restrict__ D,
    float* __restrict__ o, float* __restrict__ U)
{
    __shared__ float sQ[128 * 72];   // [d][t]; overlaid by sA [s][t] (64*72)
    __shared__ float sK[128 * 72];   // [d][s]; overlaid by sKU [s][d] (64*136)
    __shared__ float sV[64 * 136];   // [s][v] fp32
    __shared__ float sD[128];

    const int vhalf = blockIdx.x & 1;
    const int cta = blockIdx.x >> 1;
    const int bh = cta >> 4, c = cta & 15;
    const int b = bh >> 2, h = bh & 3;
    const int tid = threadIdx.x;
    const int lane = tid & 31, w = tid >> 5;
    const int lg = lane >> 2, lt = lane & 3;
    const int wm = w >> 1, wn = w & 1;

    const size_t rbase = ((size_t)(b * NN + c * CHUNK)) * KDIM + h * DK;
    const size_t vbase = ((size_t)(b * NN + c * CHUNK)) * VDIM + h * DV;

    if (tid < 128) sD[tid] = D[(bh * NCHUNK + c) * DK + tid];

    // load V half: [s][v] fp32
    for (int i = tid; i < 2048; i += 256) {
        const int s = i >> 5, c4 = (i & 31) * 4;
        *reinterpret_cast<float4*>(&sV[s * 136 + c4]) =
            *reinterpret_cast<const float4*>(v + vbase + (size_t)s * VDIM + vhalf * 128 + c4);
    }
    // load Qh, Kh into [d][t] / [d][s]
    {
        const int t = tid >> 2;
        const int d0 = (tid & 3) * 4;
        const float* qp = qh + rbase + (size_t)t * KDIM;
        const float* kp = kh + rbase + (size_t)t * KDIM;
#pragma unroll
        for (int dd = 0; dd < 8; dd++) {
            const int d = d0 + dd * 16;
            float4 qv = *reinterpret_cast<const float4*>(qp + d);
            float4 kv = *reinterpret_cast<const float4*>(kp + d);
            sQ[(d + 0) * 72 + t] = qv.x; sQ[(d + 1) * 72 + t] = qv.y;
            sQ[(d + 2) * 72 + t] = qv.z; sQ[(d + 3) * 72 + t] = qv.w;
            sK[(d + 0) * 72 + t] = kv.x; sK[(d + 1) * 72 + t] = kv.y;
            sK[(d + 2) * 72 + t] = kv.z; sK[(d + 3) * 72 + t] = kv.w;
        }
    }
    __syncthreads();

    // ---- Stage 1: S = Qh Kh^T (m=64,n=64,k=128); warp = (wm 4) x (wn 2) ----
    float acc1[4][4];
#pragma unroll
    for (int nt = 0; nt < 4; nt++)
#pragma unroll
        for (int i = 0; i < 4; i++) acc1[nt][i] = 0.f;

    for (int k0 = 0; k0 < DK; k0 += 8) {
        uint32_t Ah[4], Al[4];
        split2(sQ[(k0 + lt) * 72 + wm * 16 + lg],         Ah[0], Al[0]);
        split2(sQ[(k0 + lt) * 72 + wm * 16 + lg + 8],     Ah[1], Al[1]);
        split2(sQ[(k0 + lt + 4) * 72 + wm * 16 + lg],     Ah[2], Al[2]);
        split2(sQ[(k0 + lt + 4) * 72 + wm * 16 + lg + 8], Ah[3], Al[3]);
#pragma unroll
        for (int nt = 0; nt < 4; nt++) {
            const int n0 = wn * 32 + nt * 8 + lg;
            uint32_t bh0, bl0, bh1, bl1;
            split2(sK[(k0 + lt) * 72 + n0],     bh0, bl0);
            split2(sK[(k0 + lt + 4) * 72 + n0], bh1, bl1);
            mma3(acc1[nt], Ah, Al, bh0, bh1, bl0, bl1);
        }
    }
    __syncthreads();   // all stage-1 reads of sQ/sK done

    // masked A -> sA[s][t] (overlay sQ); sKU[s][d] = kh*D (overlay sK)
    float* sA  = sQ;
    float* sKU = sK;
    {
        const int r0 = wm * 16 + lg, r1 = r0 + 8;
#pragma unroll
        for (int nt = 0; nt < 4; nt++) {
            const int c0 = wn * 32 + nt * 8 + 2 * lt, c1 = c0 + 1;
            sA[c0 * 72 + r0] = (c0 <= r0) ? acc1[nt][0] : 0.f;
            sA[c1 * 72 + r0] = (c1 <= r0) ? acc1[nt][1] : 0.f;
            sA[c0 * 72 + r1] = (c0 <= r1) ? acc1[nt][2] : 0.f;
            sA[c1 * 72 + r1] = (c1 <= r1) ? acc1[nt][3] : 0.f;
        }
    }
    {
        const int s = tid >> 2;
        const int d0 = (tid & 3) * 4;
        const float* kp = kh + rbase + (size_t)s * KDIM;
#pragma unroll
        for (int dd = 0; dd < 8; dd++) {
            const int d = d0 + dd * 16;
            float4 kv = *reinterpret_cast<const float4*>(kp + d);
            kv.x *= sD[d + 0]; kv.y *= sD[d + 1];
            kv.z *= sD[d + 2]; kv.w *= sD[d + 3];
            sKU[s * 136 + d + 0] = kv.x; sKU[s * 136 + d + 1] = kv.y;
            sKU[s * 136 + d + 2] = kv.z; sKU[s * 136 + d + 3] = kv.w;
        }
    }
    __syncthreads();

    // ---- Stage 2: O = sA @ Vhalf (m=64,n=128,k=64); warp wm x (wn 64 cols) ----
    {
        float acc2[8][4];
#pragma unroll
        for (int nt = 0; nt < 8; nt++)
#pragma unroll
            for (int i = 0; i < 4; i++) acc2[nt][i] = 0.f;

        for (int k0 = 0; k0 < CHUNK; k0 += 8) {
            uint32_t Ah[4], Al[4];
            split2(sA[(k0 + lt) * 72 + wm * 16 + lg],         Ah[0], Al[0]);
            split2(sA[(k0 + lt) * 72 + wm * 16 + lg + 8],     Ah[1], Al[1]);
            split2(sA[(k0 + lt + 4) * 72 + wm * 16 + lg],     Ah[2], Al[2]);
            split2(sA[(k0 + lt + 4) * 72 + wm * 16 + lg + 8], Ah[3], Al[3]);
#pragma unroll
            for (int nt = 0; nt < 8; nt++) {
                const int n0 = wn * 64 + nt * 8 + lg;
                uint32_t bh0, bl0, bh1, bl1;
                split2(sV[(k0 + lt) * 136 + n0],     bh0, bl0);
                split2(sV[(k0 + lt + 4) * 136 + n0], bh1, bl1);
                mma3(acc2[nt], Ah, Al, bh0, bh1, bl0, bl1);
            }
        }

        const int r0 = wm * 16 + lg, r1 = r0 + 8;
#pragma unroll
        for (int nt = 0; nt < 8; nt++) {
            const int c0 = wn * 64 + nt * 8 + 2 * lt;
            *reinterpret_cast<float2*>(o + vbase + (size_t)r0 * VDIM + vhalf * 128 + c0) =
                make_float2(acc2[nt][0], acc2[nt][1]);
            *reinterpret_cast<float2*>(o + vbase + (size_t)r1 * VDIM + vhalf * 128 + c0) =
                make_float2(acc2[nt][2], acc2[nt][3]);
        }
    }

    // ---- U phase: U = sKU^T-view @ Vhalf (m=128 d, n=128 v, k=64 s) ----
    {
        float acc3[16][4];
#pragma unroll
        for (int nt = 0; nt < 16; nt++)
#pragma unroll
            for (int i = 0; i < 4; i++) acc3[nt][i] = 0.f;

        for (int k0 = 0; k0 < CHUNK; k0 += 8) {
            uint32_t Ah[4], Al[4];
            split2(sKU[(k0 + lt) * 136 + w * 16 + lg],         Ah[0], Al[0]);
            split2(sKU[(k0 + lt) * 136 + w * 16 + lg + 8],     Ah[1], Al[1]);
            split2(sKU[(k0 + lt + 4) * 136 + w * 16 + lg],     Ah[2], Al[2]);
            split2(sKU[(k0 + lt + 4) * 136 + w * 16 + lg + 8], Ah[3], Al[3]);
#pragma unroll
            for (int nt = 0; nt < 16; nt++) {
                const int n0 = nt * 8 + lg;
                uint32_t bh0, bl0, bh1, bl1;
                split2(sV[(k0 + lt) * 136 + n0],     bh0, bl0);
                split2(sV[(k0 + lt + 4) * 136 + n0], bh1, bl1);
                mma3(acc3[nt], Ah, Al, bh0, bh1, bl0, bl1);
            }
        }

        float* Ub = U + ((size_t)(bh * NCHUNK + c) * DK) * DV + vhalf * 128;
        const int d0 = w * 16 + lg, d1 = d0 + 8;
#pragma unroll
        for (int nt = 0; nt < 16; nt++) {
            const int c0 = nt * 8 + 2 * lt;
            *reinterpret_cast<float2*>(Ub + (size_t)d0 * DV + c0) =
                make_float2(acc3[nt][0], acc3[nt][1]);
            *reinterpret_cast<float2*>(Ub + (size_t)d1 * DV + c0) =
                make_float2(acc3[nt][2], acc3[nt][3]);
        }
    }
}

// ---------------------------------------------------------------------------
// Elementwise chunk-state scan
// ---------------------------------------------------------------------------
__global__ __launch_bounds__(256) void state_scan_kernel(
    const float* __restrict__ U, const float* __restrict__ D, float* __restrict__ S)
{
    const int bh = blockIdx.y;
    const int e = blockIdx.x * 256 + threadIdx.x;
    const int d = e >> 6;
    const int vq = (e & 63) * 4;

    float4 s = make_float4(0.f, 0.f, 0.f, 0.f);
#pragma unroll
    for (int c = 0; c < NCHUNK; c++) {
        const size_t base = ((size_t)((bh * NCHUNK + c) * DK) + d) * DV + vq;
        if (c > 0)
            *reinterpret_cast<float4*>(S + base) = s;
        const float dc = D[(bh * NCHUNK + c) * DK + d];
        const float4 u = *reinterpret_cast<const float4*>(U + base);
        s.x = fmaf(s.x, dc, u.x);
        s.y = fmaf(s.y, dc, u.y);
        s.z = fmaf(s.z, dc, u.z);
        s.w = fmaf(s.w, dc, u.w);
    }
}

// ---------------------------------------------------------------------------
// Inter-chunk output: O_c += Qhat_c @ Sstart_c
// ---------------------------------------------------------------------------
__global__ __launch_bounds__(256) void inter2_kernel(
    const float* __restrict__ qh, const float* __restrict__ S, float* __restrict__ o)
{
    __shared__ float sQ[16 * 68];
    __shared__ float sS[16 * 132];

    const int vhalf = blockIdx.x;
    const int j = blockIdx.y;
    const int bh = j / 15;
    const int c = j % 15 + 1;
    const int b = bh >> 2, h = bh & 3;
    const int tid = threadIdx.x;

    const size_t qbase = ((size_t)(b * NN + c * CHUNK)) * KDIM + h * DK;
    const size_t Sbase = ((size_t)((bh * NCHUNK + c) * DK)) * DV + vhalf * 128;
    const size_t obase = ((size_t)(b * NN + c * CHUNK)) * VDIM + h * DV + vhalf * 128;

    const int trow = tid >> 4, tcol = tid & 15;
    const int qt = tid >> 2;
    const int qk = (tid & 3) * 4;
    const int sr = tid >> 5;
    const int sc = (tid & 31) * 4;

    float acc[4][8];
#pragma unroll
    for (int i = 0; i < 4; i++)
#pragma unroll
        for (int j2 = 0; j2 < 8; j2++) acc[i][j2] = 0.f;

    for (int k0 = 0; k0 < DK; k0 += 16) {
        float4 qv = *reinterpret_cast<const float4*>(qh + qbase + (size_t)qt * KDIM + k0 + qk);
        sQ[(qk + 0) * 68 + qt] = qv.x;
        sQ[(qk + 1) * 68 + qt] = qv.y;
        sQ[(qk + 2) * 68 + qt] = qv.z;
        sQ[(qk + 3) * 68 + qt] = qv.w;
        *reinterpret_cast<float4*>(&sS[sr * 132 + sc]) =
            *reinterpret_cast<const float4*>(S + Sbase + (size_t)(k0 + sr) * DV + sc);
        *reinterpret_cast<float4*>(&sS[(sr + 8) * 132 + sc]) =
            *reinterpret_cast<const float4*>(S + Sbase + (size_t)(k0 + sr + 8) * DV + sc);
        __syncthreads();

#pragma unroll
        for (int kk = 0; kk < 16; kk++) {
            float4 a4 = *reinterpret_cast<const float4*>(&sQ[kk * 68 + trow * 4]);
            float4 b0 = *reinterpret_cast<const float4*>(&sS[kk * 132 + tcol * 8]);
            float4 b1 = *reinterpret_cast<const float4*>(&sS[kk * 132 + tcol * 8 + 4]);
            const float ar[4] = {a4.x, a4.y, a4.z, a4.w};
            const float br[8] = {b0.x, b0.y, b0.z, b0.w, b1.x, b1.y, b1.z, b1.w};
#pragma unroll
            for (int i = 0; i < 4; i++)
#pragma unroll
                for (int j2 = 0; j2 < 8; j2++)
                    acc[i][j2] = fmaf(ar[i], br[j2], acc[i][j2]);
        }
        __syncthreads();
    }

#pragma unroll
    for (int i = 0; i < 4; i++) {
        float* op = o + obase + (size_t)(trow * 4 + i) * VDIM + tcol * 8;
        float4 c0 = *reinterpret_cast<const float4*>(op);
        float4 c1 = *reinterpret_cast<const float4*>(op + 4);
        c0.x += acc[i][0]; c0.y += acc[i][1]; c0.z += acc[i][2]; c0.w += acc[i][3];
        c1.x += acc[i][4]; c1.y += acc[i][5]; c1.z += acc[i][6]; c1.w += acc[i][7];
        *reinterpret_cast<float4*>(op)     = c0;
        *reinterpret_cast<float4*>(op + 4) = c1;
    }
}

// ---------------------------------------------------------------------------
// RMSNorm + SiLU gating
// ---------------------------------------------------------------------------
__global__ __launch_bounds__(256) void norm_gate_kernel(
    const float* __restrict__ o, const float* __restrict__ gaux,
    const float* __restrict__ rms_w, float* __restrict__ y)
{
    const int row = blockIdx.x;
    const int tid = threadIdx.x;
    const size_t base = (size_t)row * VDIM + tid * 4;

    const float4 ov = *reinterpret_cast<const float4*>(o + base);
    float ss = ov.x * ov.x + ov.y * ov.y + ov.z * ov.z + ov.w * ov.w;
#pragma unroll
    for (int off = 16; off; off >>= 1)
        ss += __shfl_xor_sync(0xffffffffu, ss, off);

    __shared__ float ws[8];
    const int warp = tid >> 5, lane = tid & 31;
    if (lane == 0) ws[warp] = ss;
    __syncthreads();

    const int hw = (tid >> 6) << 1;
    const float tot = ws[hw] + ws[hw + 1];
    const float scale = rsqrtf(tot * (1.f / 256.f) + 1e-5f);

    const float4 gv = *reinterpret_cast<const float4*>(gaux + base);
    const int dv = (tid * 4) & 255;
    const float w0 = rms_w[dv + 0], w1 = rms_w[dv + 1], w2 = rms_w[dv + 2], w3 = rms_w[dv + 3];

    float4 r;
    r.x = ov.x * scale * w0 * (gv.x / (1.f + __expf(-gv.x)));
    r.y = ov.y * scale * w1 * (gv.y / (1.f + __expf(-gv.y)));
    r.z = ov.z * scale * w2 * (gv.z / (1.f + __expf(-gv.z)));
    r.w = ov.w * scale * w3 * (gv.w / (1.f + __expf(-gv.w)));
    *reinterpret_cast<float4*>(y + base) = r;
}

// ---------------------------------------------------------------------------
extern "C" void kernel_launch(void* const* d_in, const int* in_sizes, int n_in,
                              void* d_out, int out_size)
{
    const float* x    = (const float*)d_in[0];
    const float* Wq   = (const float*)d_in[1];
    const float* Wk   = (const float*)d_in[2];
    const float* Wv   = (const float*)d_in[3];
    const float* Wg   = (const float*)d_in[4];
    const float* Wgk1 = (const float*)d_in[5];
    const float* Wgk2 = (const float*)d_in[6];
    const float* bgk2 = (const float*)d_in[7];
    const float* Wout = (const float*)d_in[8];
    const float* rmsw = (const float*)d_in[9];
    float* out = (float*)d_out;

    float* scratch = nullptr;
    cudaGetSymbolAddress((void**)&scratch, g_scratch);
    float* Ag   = scratch + OFF_AG;
    float* v    = scratch + OFF_V;
    float* ga   = scratch + OFF_GA;
    float* t16  = scratch + OFF_T16;
    float* o    = scratch + OFF_O;
    float* y    = scratch + OFF_Y;
    float* qhb  = scratch + OFF_QH;
    float* khb  = scratch + OFF_KH;
    float* Ub   = scratch + OFF_U;
    float* Db   = scratch + OFF_D;
    float* Sb   = scratch + OFF_S;

    // gate path (x only)
    proj_lr_kernel<<<MROWS, 128>>>(x, Wgk1, t16);
    gate_cum_kernel<<<dim3(NCHUNK, BB * HH), 256>>>(t16, Wgk2, bgk2, Ag, Db);

    // fused projections with gate scaling in epilogue (q->qh, k->kh)
    proj_gemm_kernel<<<dim3(VDIM / 128, MROWS / 128, 4), 256>>>(
        x, Wq, Wk, Wv, Wg, qhb, khb, v, ga, Ag);

    // chunked GLA: tensor-core intra+U, then scan, then inter
    intra_u_kernel<<<TOTCHUNK * 2, 256>>>(qhb, khb, v, Db, o, Ub);
    state_scan_kernel<<<dim3(32, BB * HH), 256>>>(Ub, Db, Sb);
    inter2_kernel<<<dim3(2, BB * HH * (NCHUNK - 1)), 256>>>(qhb, Sb, o);

    // epilogue
    norm_gate_kernel<<<MROWS, 256>>>(o, ga, rmsw, y);
    out_gemm_kernel<<<dim3(VDIM / 128, MROWS / 128), 256>>>(y, Wout, out);
}